// round 1
// baseline (speedup 1.0000x reference)
#include <cuda_runtime.h>
#include <cstdint>
#include <math.h>

#define NN   20000
#define EE   320000
#define DD   128
#define HH   2

// ---------------- scratch (device globals; no allocation allowed) -------------
__device__ float g_feat0[(size_t)NN * 512];   // relation-0 transformed features
__device__ float g_feat1[(size_t)NN * 512];   // relation-1 transformed features
__device__ float g_acc  [(size_t)NN * 512];   // accumulated GAT output (both relations)
__device__ float g_h1   [(size_t)NN * 256];   // layer-1 output (post mean+relu)
__device__ float g_el0[NN * HH], g_er0[NN * HH];
__device__ float g_el1[NN * HH], g_er1[NN * HH];
__device__ float g_m0[NN * HH], g_s0[NN * HH];
__device__ float g_m1[NN * HH], g_s1[NN * HH];
__device__ float g_e0[(size_t)EE * HH];       // per-edge logits -> exp values, rel 0
__device__ float g_e1[(size_t)EE * HH];       // per-edge logits -> exp values, rel 1

// ---------------- init ---------------------------------------------------------
__global__ void init_k(float* acc, int accN, float* m0, float* m1,
                       float* s0, float* s1, int nm) {
    int i = blockIdx.x * blockDim.x + threadIdx.x;
    int stride = gridDim.x * blockDim.x;
    for (int j = i; j < accN; j += stride) acc[j] = 0.f;
    for (int j = i; j < nm; j += stride) {
        m0[j] = -INFINITY; m1[j] = -INFINITY;
        s0[j] = 0.f;       s1[j] = 0.f;
    }
}

// ---------------- GEMM: C[M,Nd] = A[M,Kd] * B[Kd,Nd] --------------------------
// 64x64 block tile, BK=16, 256 threads, 4x4 per thread.
__global__ void gemm_k(const float* __restrict__ A, const float* __restrict__ B,
                       float* __restrict__ C, int M, int Kd, int Nd) {
    __shared__ float As[16][64];
    __shared__ float Bs[16][64];
    int tid = threadIdx.x;
    int tx = tid & 15, ty = tid >> 4;
    int rowBase = blockIdx.y * 64;
    int colBase = blockIdx.x * 64;
    float acc[4][4] = {};
    for (int k0 = 0; k0 < Kd; k0 += 16) {
        #pragma unroll
        for (int i = 0; i < 4; i++) {
            int e = tid + i * 256;
            int r = e >> 4, c = e & 15;
            int row = rowBase + r;
            As[c][r] = (row < M) ? A[(size_t)row * Kd + k0 + c] : 0.f;
        }
        #pragma unroll
        for (int i = 0; i < 4; i++) {
            int e = tid + i * 256;
            int r = e >> 6, c = e & 63;
            Bs[r][c] = B[(size_t)(k0 + r) * Nd + colBase + c];
        }
        __syncthreads();
        #pragma unroll
        for (int kk = 0; kk < 16; kk++) {
            float4 av = *reinterpret_cast<const float4*>(&As[kk][ty * 4]);
            float4 bv = *reinterpret_cast<const float4*>(&Bs[kk][tx * 4]);
            float a[4] = {av.x, av.y, av.z, av.w};
            float b[4] = {bv.x, bv.y, bv.z, bv.w};
            #pragma unroll
            for (int i = 0; i < 4; i++)
                #pragma unroll
                for (int j = 0; j < 4; j++)
                    acc[i][j] += a[i] * b[j];
        }
        __syncthreads();
    }
    #pragma unroll
    for (int i = 0; i < 4; i++) {
        int row = rowBase + ty * 4 + i;
        if (row < M) {
            float4 v = make_float4(acc[i][0], acc[i][1], acc[i][2], acc[i][3]);
            *reinterpret_cast<float4*>(&C[(size_t)row * Nd + colBase + tx * 4]) = v;
        }
    }
}

// ---------------- attention scores: el/er per (node, head) --------------------
// One warp per (node, head). blockDim = 64 (H warps).
__global__ void attn_k(const float* __restrict__ feat, const float* __restrict__ al,
                       const float* __restrict__ ar, float* __restrict__ el,
                       float* __restrict__ er, int O) {
    int n = blockIdx.x;
    int h = threadIdx.x >> 5;
    int lane = threadIdx.x & 31;
    const float* f = feat + (size_t)n * (HH * O) + h * O;
    const float* a = al + h * O;
    const float* r = ar + h * O;
    float sl = 0.f, sr = 0.f;
    for (int j = lane; j < O; j += 32) {
        float v = f[j];
        sl += v * a[j];
        sr += v * r[j];
    }
    #pragma unroll
    for (int off = 16; off; off >>= 1) {
        sl += __shfl_down_sync(0xffffffffu, sl, off);
        sr += __shfl_down_sync(0xffffffffu, sr, off);
    }
    if (lane == 0) { el[n * HH + h] = sl; er[n * HH + h] = sr; }
}

// ---------------- edge pass A: logits + segment max ---------------------------
__global__ void edgeA_k(const int* __restrict__ src, const int* __restrict__ dst,
                        const float* __restrict__ el, const float* __restrict__ er,
                        float* __restrict__ e, float* __restrict__ m) {
    int idx = blockIdx.x * blockDim.x + threadIdx.x;
    if (idx >= EE * HH) return;
    int eid = idx >> 1, h = idx & 1;
    int s = src[eid], d = dst[eid];
    float v = el[s * HH + h] + er[d * HH + h];
    v = v > 0.f ? v : 0.2f * v;                 // leaky relu, slope 0.2
    e[idx] = v;
    float* addr = &m[d * HH + h];
    if (v >= 0.f) atomicMax((int*)addr, __float_as_int(v));
    else          atomicMin((unsigned int*)addr, __float_as_uint(v));
}

// ---------------- edge pass B: exp + segment sum -------------------------------
__global__ void edgeB_k(const int* __restrict__ dst, float* __restrict__ e,
                        const float* __restrict__ m, float* __restrict__ s) {
    int idx = blockIdx.x * blockDim.x + threadIdx.x;
    if (idx >= EE * HH) return;
    int eid = idx >> 1, h = idx & 1;
    int d = dst[eid];
    float v = __expf(e[idx] - m[d * HH + h]);
    e[idx] = v;
    atomicAdd(&s[d * HH + h], v);
}

// ---------------- edge pass C: weighted scatter-add ----------------------------
// One warp per edge; width = H*O floats per node; vectorized red.add.v4.f32.
__global__ void edgeC_k(const int* __restrict__ src, const int* __restrict__ dst,
                        const float* __restrict__ ee, const float* __restrict__ ssum,
                        const float* __restrict__ feat, float* __restrict__ acc,
                        int width, int O) {
    int warp = (blockIdx.x * blockDim.x + threadIdx.x) >> 5;
    int lane = threadIdx.x & 31;
    if (warp >= EE) return;
    int s = src[warp], d = dst[warp];
    float alpha = 0.f;
    if (lane < HH) {
        float den = ssum[d * HH + lane];
        alpha = ee[warp * HH + lane] / fmaxf(den, 1e-9f);
    }
    float a0 = __shfl_sync(0xffffffffu, alpha, 0);
    float a1 = __shfl_sync(0xffffffffu, alpha, 1);
    const float4* fin = reinterpret_cast<const float4*>(feat + (size_t)s * width);
    float* base = acc + (size_t)d * width;
    int nchunk = width >> 7;   // 128 floats / chunk
    for (int c = 0; c < nchunk; c++) {
        float a = ((c * 128) < O) ? a0 : a1;   // chunk lies entirely in one head
        float4 v = fin[c * 32 + lane];
        float* p = base + c * 128 + lane * 4;
        asm volatile("red.global.add.v4.f32 [%0], {%1, %2, %3, %4};"
                     :: "l"(p), "f"(v.x * a), "f"(v.y * a), "f"(v.z * a), "f"(v.w * a)
                     : "memory");
    }
}

// ---------------- finalize layer 1: mean over heads + bias + relu -------------
__global__ void fin1_k(const float* __restrict__ acc, const float* __restrict__ b0,
                       const float* __restrict__ b1, float* __restrict__ h1) {
    const int O = 256;
    int idx = blockIdx.x * blockDim.x + threadIdx.x;
    if (idx >= NN * O) return;
    int n = idx / O, j = idx % O;
    float v = acc[(size_t)n * 2 * O + j] + acc[(size_t)n * 2 * O + O + j]
            + b0[j] + b0[O + j] + b1[j] + b1[O + j];
    h1[idx] = fmaxf(0.5f * v, 0.f);
}

// ---------------- finalize layer 2: mean over heads + bias --------------------
__global__ void fin2_k(const float* __restrict__ acc, const float* __restrict__ b0,
                       const float* __restrict__ b1, float* __restrict__ out) {
    const int O = 128;
    int idx = blockIdx.x * blockDim.x + threadIdx.x;
    if (idx >= NN * O) return;
    int n = idx / O, j = idx % O;
    float v = acc[(size_t)n * 2 * O + j] + acc[(size_t)n * 2 * O + O + j]
            + b0[j] + b0[O + j] + b1[j] + b1[O + j];
    out[idx] = 0.5f * v;
}

// ---------------- host launch ---------------------------------------------------
static float* symf(const void* s) {
    void* p = nullptr;
    cudaGetSymbolAddress(&p, s);
    return (float*)p;
}

extern "C" void kernel_launch(void* const* d_in, const int* in_sizes, int n_in,
                              void* d_out, int out_size) {
    const float* x     = (const float*)d_in[0];
    const int*   src0  = (const int*)d_in[1];
    const int*   dst0  = (const int*)d_in[2];
    const int*   src1  = (const int*)d_in[3];
    const int*   dst1  = (const int*)d_in[4];
    const float* W1_0  = (const float*)d_in[5];
    const float* al1_0 = (const float*)d_in[6];
    const float* ar1_0 = (const float*)d_in[7];
    const float* b1_0  = (const float*)d_in[8];
    const float* W1_1  = (const float*)d_in[9];
    const float* al1_1 = (const float*)d_in[10];
    const float* ar1_1 = (const float*)d_in[11];
    const float* b1_1  = (const float*)d_in[12];
    const float* W2_0  = (const float*)d_in[13];
    const float* al2_0 = (const float*)d_in[14];
    const float* ar2_0 = (const float*)d_in[15];
    const float* b2_0  = (const float*)d_in[16];
    const float* W2_1  = (const float*)d_in[17];
    const float* al2_1 = (const float*)d_in[18];
    const float* ar2_1 = (const float*)d_in[19];
    const float* b2_1  = (const float*)d_in[20];
    float* out = (float*)d_out;

    float* feat0 = symf(g_feat0);
    float* feat1 = symf(g_feat1);
    float* acc   = symf(g_acc);
    float* h1    = symf(g_h1);
    float* el0 = symf(g_el0); float* er0 = symf(g_er0);
    float* el1 = symf(g_el1); float* er1 = symf(g_er1);
    float* m0 = symf(g_m0); float* s0 = symf(g_s0);
    float* m1 = symf(g_m1); float* s1 = symf(g_s1);
    float* e0 = symf(g_e0); float* e1 = symf(g_e1);

    const int eThreads = EE * HH;
    const int eBlocks  = (eThreads + 255) / 256;
    const int cBlocks  = EE / 8;           // 8 warps per 256-thread block

    // ================= layer 1: in=128, O=256, width=512 =================
    init_k<<<1024, 256>>>(acc, NN * 512, m0, m1, s0, s1, NN * HH);

    { dim3 g(512 / 64, (NN + 63) / 64);
      gemm_k<<<g, 256>>>(x, W1_0, feat0, NN, DD, 512);
      gemm_k<<<g, 256>>>(x, W1_1, feat1, NN, DD, 512); }

    attn_k<<<NN, 64>>>(feat0, al1_0, ar1_0, el0, er0, 256);
    attn_k<<<NN, 64>>>(feat1, al1_1, ar1_1, el1, er1, 256);

    edgeA_k<<<eBlocks, 256>>>(src0, dst0, el0, er0, e0, m0);
    edgeA_k<<<eBlocks, 256>>>(src1, dst1, el1, er1, e1, m1);
    edgeB_k<<<eBlocks, 256>>>(dst0, e0, m0, s0);
    edgeB_k<<<eBlocks, 256>>>(dst1, e1, m1, s1);
    edgeC_k<<<cBlocks, 256>>>(src0, dst0, e0, s0, feat0, acc, 512, 256);
    edgeC_k<<<cBlocks, 256>>>(src1, dst1, e1, s1, feat1, acc, 512, 256);

    fin1_k<<<(NN * 256 + 255) / 256, 256>>>(acc, b1_0, b1_1, h1);

    // ================= layer 2: in=256, O=128, width=256 =================
    init_k<<<1024, 256>>>(acc, NN * 256, m0, m1, s0, s1, NN * HH);

    { dim3 g(256 / 64, (NN + 63) / 64);
      gemm_k<<<g, 256>>>(h1, W2_0, feat0, NN, 256, 256);
      gemm_k<<<g, 256>>>(h1, W2_1, feat1, NN, 256, 256); }

    attn_k<<<NN, 64>>>(feat0, al2_0, ar2_0, el0, er0, 128);
    attn_k<<<NN, 64>>>(feat1, al2_1, ar2_1, el1, er1, 128);

    edgeA_k<<<eBlocks, 256>>>(src0, dst0, el0, er0, e0, m0);
    edgeA_k<<<eBlocks, 256>>>(src1, dst1, el1, er1, e1, m1);
    edgeB_k<<<eBlocks, 256>>>(dst0, e0, m0, s0);
    edgeB_k<<<eBlocks, 256>>>(dst1, e1, m1, s1);
    edgeC_k<<<cBlocks, 256>>>(src0, dst0, e0, s0, feat0, acc, 256, 128);
    edgeC_k<<<cBlocks, 256>>>(src1, dst1, e1, s1, feat1, acc, 256, 128);

    fin2_k<<<(NN * 128 + 255) / 256, 256>>>(acc, b2_0, b2_1, out);
}

// round 2
// speedup vs baseline: 1.2754x; 1.2754x over previous
#include <cuda_runtime.h>
#include <cstdint>
#include <math.h>

#define NN   20000
#define EE   320000
#define DD   128
#define HH   2

// ---------------- scratch (device globals) ------------------------------------
__device__ float g_feat0[(size_t)NN * 512];
__device__ float g_feat1[(size_t)NN * 512];
__device__ float g_h1   [(size_t)NN * 256];
__device__ float g_el0[NN * 2], g_er0[NN * 2];
__device__ float g_el1[NN * 2], g_er1[NN * 2];
__device__ int   g_deg0[NN], g_deg1[NN];
__device__ int   g_off0[NN + 1], g_off1[NN + 1];
__device__ int   g_pos0[NN], g_pos1[NN];
__device__ int   g_csr0[EE], g_csr1[EE];

// ---------------- CSR build -----------------------------------------------------
__global__ void zero_k(int* a, int* b, int n) {
    int i = blockIdx.x * blockDim.x + threadIdx.x;
    if (i < n) { a[i] = 0; b[i] = 0; }
}

__global__ void hist_k(const int* __restrict__ dst0, const int* __restrict__ dst1,
                       int* deg0, int* deg1) {
    int i = blockIdx.x * blockDim.x + threadIdx.x;
    if (i < EE) {
        atomicAdd(&deg0[dst0[i]], 1);
        atomicAdd(&deg1[dst1[i]], 1);
    }
}

// single-block exclusive scan over NN degrees -> offsets (off[NN] = total)
__global__ void scan_k(const int* __restrict__ deg, int* __restrict__ off) {
    __shared__ int tmp[1024];
    __shared__ int carry;
    int tid = threadIdx.x;
    if (tid == 0) carry = 0;
    __syncthreads();
    for (int base = 0; base < NN; base += 1024) {
        int v = (base + tid < NN) ? deg[base + tid] : 0;
        tmp[tid] = v;
        __syncthreads();
        for (int o = 1; o < 1024; o <<= 1) {
            int t = (tid >= o) ? tmp[tid - o] : 0;
            __syncthreads();
            tmp[tid] += t;
            __syncthreads();
        }
        if (base + tid < NN) off[base + tid] = carry + tmp[tid] - v;
        __syncthreads();
        if (tid == 0) carry += tmp[1023];
        __syncthreads();
    }
    if (tid == 0) off[NN] = carry;
}

__global__ void copyoff_k(const int* __restrict__ o0, const int* __restrict__ o1,
                          int* p0, int* p1) {
    int i = blockIdx.x * blockDim.x + threadIdx.x;
    if (i < NN) { p0[i] = o0[i]; p1[i] = o1[i]; }
}

__global__ void scat_k(const int* __restrict__ src0, const int* __restrict__ dst0,
                       const int* __restrict__ src1, const int* __restrict__ dst1,
                       int* pos0, int* pos1, int* csr0, int* csr1) {
    int i = blockIdx.x * blockDim.x + threadIdx.x;
    if (i < EE) {
        csr0[atomicAdd(&pos0[dst0[i]], 1)] = src0[i];
        csr1[atomicAdd(&pos1[dst1[i]], 1)] = src1[i];
    }
}

// ---------------- GEMM: C[M,Nd] = A[M,Kd]*B[Kd,Nd], 128x128 tile, BK=8 --------
__global__ void __launch_bounds__(256) gemm_k(
        const float* __restrict__ A, const float* __restrict__ B,
        float* __restrict__ C, int M, int Kd, int Nd) {
    __shared__ float As[8][128];
    __shared__ float Bs[8][128];
    int tid = threadIdx.x;
    int rowBase = blockIdx.y * 128;
    int colBase = blockIdx.x * 128;
    // A load: row ar (0..127), col chunk ac in {0,4}
    int ar = tid >> 1, ac = (tid & 1) * 4;
    // B load: row br (0..7), col bc (0..124 step 4)
    int br = tid >> 5, bc = (tid & 31) * 4;
    int rowT = tid >> 4, colT = tid & 15;
    float acc[8][8] = {};
    for (int k0 = 0; k0 < Kd; k0 += 8) {
        float4 av = make_float4(0.f, 0.f, 0.f, 0.f);
        if (rowBase + ar < M)
            av = *reinterpret_cast<const float4*>(&A[(size_t)(rowBase + ar) * Kd + k0 + ac]);
        As[ac + 0][ar] = av.x;
        As[ac + 1][ar] = av.y;
        As[ac + 2][ar] = av.z;
        As[ac + 3][ar] = av.w;
        float4 bv = *reinterpret_cast<const float4*>(&B[(size_t)(k0 + br) * Nd + colBase + bc]);
        *reinterpret_cast<float4*>(&Bs[br][bc]) = bv;
        __syncthreads();
        #pragma unroll
        for (int kk = 0; kk < 8; kk++) {
            float a[8], b[8];
            *reinterpret_cast<float4*>(a)     = *reinterpret_cast<const float4*>(&As[kk][rowT * 8]);
            *reinterpret_cast<float4*>(a + 4) = *reinterpret_cast<const float4*>(&As[kk][rowT * 8 + 4]);
            *reinterpret_cast<float4*>(b)     = *reinterpret_cast<const float4*>(&Bs[kk][colT * 8]);
            *reinterpret_cast<float4*>(b + 4) = *reinterpret_cast<const float4*>(&Bs[kk][colT * 8 + 4]);
            #pragma unroll
            for (int i = 0; i < 8; i++)
                #pragma unroll
                for (int j = 0; j < 8; j++)
                    acc[i][j] += a[i] * b[j];
        }
        __syncthreads();
    }
    #pragma unroll
    for (int i = 0; i < 8; i++) {
        int row = rowBase + rowT * 8 + i;
        if (row < M) {
            float* cp = &C[(size_t)row * Nd + colBase + colT * 8];
            *reinterpret_cast<float4*>(cp)     = make_float4(acc[i][0], acc[i][1], acc[i][2], acc[i][3]);
            *reinterpret_cast<float4*>(cp + 4) = make_float4(acc[i][4], acc[i][5], acc[i][6], acc[i][7]);
        }
    }
}

// ---------------- attention scores: el/er per (node, head) --------------------
__global__ void attn_k(const float* __restrict__ feat, const float* __restrict__ al,
                       const float* __restrict__ ar, float* __restrict__ el,
                       float* __restrict__ er, int O) {
    int n = blockIdx.x;
    int h = threadIdx.x >> 5;
    int lane = threadIdx.x & 31;
    const float* f = feat + (size_t)n * (HH * O) + h * O;
    const float* a = al + h * O;
    const float* r = ar + h * O;
    float sl = 0.f, sr = 0.f;
    for (int j = lane * 4; j < O; j += 128) {
        float4 v = *reinterpret_cast<const float4*>(&f[j]);
        float4 av = *reinterpret_cast<const float4*>(&a[j]);
        float4 rv = *reinterpret_cast<const float4*>(&r[j]);
        sl += v.x * av.x + v.y * av.y + v.z * av.z + v.w * av.w;
        sr += v.x * rv.x + v.y * rv.y + v.z * rv.z + v.w * rv.w;
    }
    #pragma unroll
    for (int off = 16; off; off >>= 1) {
        sl += __shfl_down_sync(0xffffffffu, sl, off);
        sr += __shfl_down_sync(0xffffffffu, sr, off);
    }
    if (lane == 0) { el[n * HH + h] = sl; er[n * HH + h] = sr; }
}

// ---------------- fused per-dst-node softmax + aggregation + epilogue ---------
// One block (128 threads) per dst node. WIDTH = 2*O floats per node.
template<int O>
__global__ void __launch_bounds__(128) agg_k(
        const int* __restrict__ off0, const int* __restrict__ csr0,
        const int* __restrict__ off1, const int* __restrict__ csr1,
        const float* __restrict__ el0, const float* __restrict__ er0,
        const float* __restrict__ el1, const float* __restrict__ er1,
        const float* __restrict__ feat0, const float* __restrict__ feat1,
        const float* __restrict__ b0, const float* __restrict__ b1,
        float* __restrict__ out, int do_relu) {
    constexpr int WIDTH = 2 * O;
    constexpr int NV = WIDTH / 128;     // floats per thread (4 or 2)
    constexpr int CAP = 512;            // cached exp values per relation
    __shared__ float2 s_exp[CAP];
    __shared__ float2 s_red[128];
    __shared__ float  s_out[WIDTH];
    int n = blockIdx.x;
    int tid = threadIdx.x;
    int head = tid >> 6;                // thread's columns lie in one head
    float acc[NV];
    #pragma unroll
    for (int j = 0; j < NV; j++) acc[j] = 0.f;

    #pragma unroll
    for (int rel = 0; rel < 2; rel++) {
        const int* off = rel ? off1 : off0;
        const int* csr = rel ? csr1 : csr0;
        const float* el = rel ? el1 : el0;
        const float* er = rel ? er1 : er0;
        const float* feat = rel ? feat1 : feat0;
        int beg = off[n];
        int deg = off[n + 1] - beg;
        float ern0 = er[n * 2 + 0], ern1 = er[n * 2 + 1];
        __syncthreads();                 // protect s_exp reuse across relations
        // phase 1: exp(leakyrelu(el[s]+er[n])), cache + partial denominators
        float d0 = 0.f, d1 = 0.f;
        for (int i = tid; i < deg; i += 128) {
            int s = csr[beg + i];
            float v0 = el[s * 2 + 0] + ern0;
            float v1 = el[s * 2 + 1] + ern1;
            v0 = v0 > 0.f ? v0 : 0.2f * v0;
            v1 = v1 > 0.f ? v1 : 0.2f * v1;
            v0 = __expf(v0);
            v1 = __expf(v1);
            if (i < CAP) s_exp[i] = make_float2(v0, v1);
            d0 += v0; d1 += v1;
        }
        s_red[tid] = make_float2(d0, d1);
        __syncthreads();
        #pragma unroll
        for (int o = 64; o; o >>= 1) {
            if (tid < o) {
                s_red[tid].x += s_red[tid + o].x;
                s_red[tid].y += s_red[tid + o].y;
            }
            __syncthreads();
        }
        float inv0 = 1.f / fmaxf(s_red[0].x, 1e-9f);
        float inv1 = 1.f / fmaxf(s_red[0].y, 1e-9f);
        float inv = head ? inv1 : inv0;
        // phase 2: weighted gather-accumulate; all threads walk all edges
        #pragma unroll 4
        for (int i = 0; i < deg; i++) {
            int s = csr[beg + i];
            float a;
            if (i < CAP) {
                float2 ev = s_exp[i];
                a = (head ? ev.y : ev.x) * inv;
            } else {
                float v = el[s * 2 + head] + (head ? ern1 : ern0);
                v = v > 0.f ? v : 0.2f * v;
                a = __expf(v) * inv;
            }
            const float* fp = feat + (size_t)s * WIDTH + tid * NV;
            if (NV == 4) {
                float4 v = *reinterpret_cast<const float4*>(fp);
                acc[0] += a * v.x; acc[1] += a * v.y;
                acc[2] += a * v.z; acc[3] += a * v.w;
            } else {
                float2 v = *reinterpret_cast<const float2*>(fp);
                acc[0] += a * v.x; acc[1] += a * v.y;
            }
        }
    }
    // epilogue: mean over heads + bias (+relu), single write
    #pragma unroll
    for (int j = 0; j < NV; j++) s_out[tid * NV + j] = acc[j];
    __syncthreads();
    for (int j = tid; j < O; j += 128) {
        float v = s_out[j] + s_out[j + O]
                + b0[j] + b0[j + O] + b1[j] + b1[j + O];
        v *= 0.5f;
        if (do_relu) v = fmaxf(v, 0.f);
        out[(size_t)n * O + j] = v;
    }
}

// ---------------- host launch ---------------------------------------------------
static float* symf(const void* s) {
    void* p = nullptr;
    cudaGetSymbolAddress(&p, s);
    return (float*)p;
}
static int* symi(const void* s) {
    void* p = nullptr;
    cudaGetSymbolAddress(&p, s);
    return (int*)p;
}

extern "C" void kernel_launch(void* const* d_in, const int* in_sizes, int n_in,
                              void* d_out, int out_size) {
    const float* x     = (const float*)d_in[0];
    const int*   src0  = (const int*)d_in[1];
    const int*   dst0  = (const int*)d_in[2];
    const int*   src1  = (const int*)d_in[3];
    const int*   dst1  = (const int*)d_in[4];
    const float* W1_0  = (const float*)d_in[5];
    const float* al1_0 = (const float*)d_in[6];
    const float* ar1_0 = (const float*)d_in[7];
    const float* b1_0  = (const float*)d_in[8];
    const float* W1_1  = (const float*)d_in[9];
    const float* al1_1 = (const float*)d_in[10];
    const float* ar1_1 = (const float*)d_in[11];
    const float* b1_1  = (const float*)d_in[12];
    const float* W2_0  = (const float*)d_in[13];
    const float* al2_0 = (const float*)d_in[14];
    const float* ar2_0 = (const float*)d_in[15];
    const float* b2_0  = (const float*)d_in[16];
    const float* W2_1  = (const float*)d_in[17];
    const float* al2_1 = (const float*)d_in[18];
    const float* ar2_1 = (const float*)d_in[19];
    const float* b2_1  = (const float*)d_in[20];
    float* out = (float*)d_out;

    float* feat0 = symf(g_feat0);
    float* feat1 = symf(g_feat1);
    float* h1    = symf(g_h1);
    float* el0 = symf(g_el0); float* er0 = symf(g_er0);
    float* el1 = symf(g_el1); float* er1 = symf(g_er1);
    int* deg0 = symi(g_deg0); int* deg1 = symi(g_deg1);
    int* off0 = symi(g_off0); int* off1 = symi(g_off1);
    int* pos0 = symi(g_pos0); int* pos1 = symi(g_pos1);
    int* csr0 = symi(g_csr0); int* csr1 = symi(g_csr1);

    // ---- build CSR (shared by both layers) ----
    zero_k<<<(NN + 255) / 256, 256>>>(deg0, deg1, NN);
    hist_k<<<(EE + 255) / 256, 256>>>(dst0, dst1, deg0, deg1);
    scan_k<<<1, 1024>>>(deg0, off0);
    scan_k<<<1, 1024>>>(deg1, off1);
    copyoff_k<<<(NN + 255) / 256, 256>>>(off0, off1, pos0, pos1);
    scat_k<<<(EE + 255) / 256, 256>>>(src0, dst0, src1, dst1, pos0, pos1, csr0, csr1);

    // ================= layer 1: in=128, O=256, width=512 =================
    { dim3 g(512 / 128, (NN + 127) / 128);
      gemm_k<<<g, 256>>>(x, W1_0, feat0, NN, DD, 512);
      gemm_k<<<g, 256>>>(x, W1_1, feat1, NN, DD, 512); }
    attn_k<<<NN, 64>>>(feat0, al1_0, ar1_0, el0, er0, 256);
    attn_k<<<NN, 64>>>(feat1, al1_1, ar1_1, el1, er1, 256);
    agg_k<256><<<NN, 128>>>(off0, csr0, off1, csr1, el0, er0, el1, er1,
                            feat0, feat1, b1_0, b1_1, h1, 1);

    // ================= layer 2: in=256, O=128, width=256 =================
    { dim3 g(256 / 128, (NN + 127) / 128);
      gemm_k<<<g, 256>>>(h1, W2_0, feat0, NN, 256, 256);
      gemm_k<<<g, 256>>>(h1, W2_1, feat1, NN, 256, 256); }
    attn_k<<<NN, 64>>>(feat0, al2_0, ar2_0, el0, er0, 128);
    attn_k<<<NN, 64>>>(feat1, al2_1, ar2_1, el1, er1, 128);
    agg_k<128><<<NN, 128>>>(off0, csr0, off1, csr1, el0, er0, el1, er1,
                            feat0, feat1, b2_0, b2_1, out, 0);
}

// round 3
// speedup vs baseline: 1.7737x; 1.3907x over previous
#include <cuda_runtime.h>
#include <cstdint>
#include <math.h>

#define NN   20000
#define EE   320000
#define DD   128
#define HH   2
#define NB   ((NN + 1023) / 1024)   // 20 scan blocks

// ---------------- scratch (device globals) ------------------------------------
__device__ float g_feat0[(size_t)NN * 512];
__device__ float g_feat1[(size_t)NN * 512];
__device__ float g_h1   [(size_t)NN * 256];
__device__ float g_el0[NN * 2], g_er0[NN * 2];
__device__ float g_el1[NN * 2], g_er1[NN * 2];
__device__ int   g_deg0[NN], g_deg1[NN];
__device__ int   g_off0[NN + 1], g_off1[NN + 1];
__device__ int   g_pos0[NN], g_pos1[NN];
__device__ int   g_csr0[EE], g_csr1[EE];
__device__ int   g_bsum[64];

// ---------------- CSR build -----------------------------------------------------
__global__ void zero_k(int* a, int* b, int n) {
    int i = blockIdx.x * blockDim.x + threadIdx.x;
    if (i < n) { a[i] = 0; b[i] = 0; }
}

__global__ void hist_k(const int* __restrict__ dst0, const int* __restrict__ dst1,
                       int* deg0, int* deg1) {
    int i = blockIdx.x * blockDim.x + threadIdx.x;
    if (i < EE) {
        atomicAdd(&deg0[dst0[i]], 1);
        atomicAdd(&deg1[dst1[i]], 1);
    }
}

// phase A: per-block exclusive scan (warp-shuffle), block totals to bsum
__global__ void scanA_k(const int* __restrict__ deg0, const int* __restrict__ deg1,
                        int* off0, int* off1, int* bsum) {
    const int* deg = blockIdx.y ? deg1 : deg0;
    int* off = blockIdx.y ? off1 : off0;
    int i = blockIdx.x * 1024 + threadIdx.x;
    int lane = threadIdx.x & 31, wid = threadIdx.x >> 5;
    int v = (i < NN) ? deg[i] : 0;
    int x = v;
    #pragma unroll
    for (int o = 1; o < 32; o <<= 1) {
        int t = __shfl_up_sync(0xffffffffu, x, o);
        if (lane >= o) x += t;
    }
    __shared__ int wsum[32];
    if (lane == 31) wsum[wid] = x;
    __syncthreads();
    if (wid == 0) {
        int w = wsum[lane];
        #pragma unroll
        for (int o = 1; o < 32; o <<= 1) {
            int t = __shfl_up_sync(0xffffffffu, w, o);
            if (lane >= o) w += t;
        }
        wsum[lane] = w;
    }
    __syncthreads();
    int inc = x + (wid ? wsum[wid - 1] : 0);
    if (i < NN) off[i] = inc - v;                       // exclusive within block
    if (threadIdx.x == 1023) bsum[blockIdx.y * 32 + blockIdx.x] = inc;
}

// phase B: one warp per relation scans the NB block sums
__global__ void scanB_k(int* bsum, int* off0, int* off1) {
    int y = threadIdx.x >> 5, lane = threadIdx.x & 31;
    int v = (lane < NB) ? bsum[y * 32 + lane] : 0;
    int x = v;
    #pragma unroll
    for (int o = 1; o < 32; o <<= 1) {
        int t = __shfl_up_sync(0xffffffffu, x, o);
        if (lane >= o) x += t;
    }
    if (lane < NB) bsum[y * 32 + lane] = x - v;          // exclusive block prefix
    if (lane == NB - 1) { int* off = y ? off1 : off0; off[NN] = x; }
}

// phase C: add block prefix, fused pos copy
__global__ void scanC_k(const int* __restrict__ bsum, int* off0, int* off1,
                        int* pos0, int* pos1) {
    int i = blockIdx.x * 1024 + threadIdx.x;
    if (i >= NN) return;
    int y = blockIdx.y;
    int* off = y ? off1 : off0;
    int* pos = y ? pos1 : pos0;
    int val = off[i] + bsum[y * 32 + blockIdx.x];
    off[i] = val; pos[i] = val;
}

__global__ void scat_k(const int* __restrict__ src0, const int* __restrict__ dst0,
                       const int* __restrict__ src1, const int* __restrict__ dst1,
                       int* pos0, int* pos1, int* csr0, int* csr1) {
    int i = blockIdx.x * blockDim.x + threadIdx.x;
    if (i < EE) {
        csr0[atomicAdd(&pos0[dst0[i]], 1)] = src0[i];
        csr1[atomicAdd(&pos1[dst1[i]], 1)] = src1[i];
    }
}

// ---------------- GEMM: 128x128 tile, BK=16, double-buffered ------------------
__global__ void __launch_bounds__(256) gemm_k(
        const float* __restrict__ A, const float* __restrict__ B,
        float* __restrict__ C, int M, int Kd, int Nd) {
    __shared__ float As[2][16][128];
    __shared__ float Bs[2][16][128];
    int tid = threadIdx.x;
    int rowBase = blockIdx.y * 128;
    int colBase = blockIdx.x * 128;
    int ar = tid >> 1, ac = (tid & 1) * 8;       // A: row 0..127, col 0/8
    int br = tid >> 4, bc = (tid & 15) * 8;      // B: row 0..15, col 0..120
    int rowT = tid >> 4, colT = tid & 15;
    bool aval = (rowBase + ar) < M;
    const float* Aptr = A + (size_t)(rowBase + ar) * Kd + ac;
    const float* Bptr = B + (size_t)br * Nd + colBase + bc;

    float4 av0 = make_float4(0.f, 0.f, 0.f, 0.f), av1 = av0;
    if (aval) { av0 = *(const float4*)Aptr; av1 = *(const float4*)(Aptr + 4); }
    float4 bv0 = *(const float4*)Bptr, bv1 = *(const float4*)(Bptr + 4);

    As[0][ac + 0][ar] = av0.x; As[0][ac + 1][ar] = av0.y;
    As[0][ac + 2][ar] = av0.z; As[0][ac + 3][ar] = av0.w;
    As[0][ac + 4][ar] = av1.x; As[0][ac + 5][ar] = av1.y;
    As[0][ac + 6][ar] = av1.z; As[0][ac + 7][ar] = av1.w;
    *(float4*)&Bs[0][br][bc] = bv0;
    *(float4*)&Bs[0][br][bc + 4] = bv1;
    __syncthreads();

    float acc[8][8] = {};
    int nk = Kd >> 4;
    int buf = 0;
    for (int kt = 0; kt < nk; kt++) {
        bool more = (kt + 1) < nk;
        if (more) {                              // prefetch next tile into regs
            const float* ap = Aptr + (kt + 1) * 16;
            if (aval) { av0 = *(const float4*)ap; av1 = *(const float4*)(ap + 4); }
            const float* bp = Bptr + (size_t)(kt + 1) * 16 * Nd;
            bv0 = *(const float4*)bp; bv1 = *(const float4*)(bp + 4);
        }
        #pragma unroll
        for (int kk = 0; kk < 16; kk++) {
            float a[8], b[8];
            *(float4*)(a)     = *(const float4*)&As[buf][kk][rowT * 8];
            *(float4*)(a + 4) = *(const float4*)&As[buf][kk][rowT * 8 + 4];
            *(float4*)(b)     = *(const float4*)&Bs[buf][kk][colT * 8];
            *(float4*)(b + 4) = *(const float4*)&Bs[buf][kk][colT * 8 + 4];
            #pragma unroll
            for (int i = 0; i < 8; i++)
                #pragma unroll
                for (int j = 0; j < 8; j++)
                    acc[i][j] += a[i] * b[j];
        }
        if (more) {
            int nb = buf ^ 1;
            As[nb][ac + 0][ar] = av0.x; As[nb][ac + 1][ar] = av0.y;
            As[nb][ac + 2][ar] = av0.z; As[nb][ac + 3][ar] = av0.w;
            As[nb][ac + 4][ar] = av1.x; As[nb][ac + 5][ar] = av1.y;
            As[nb][ac + 6][ar] = av1.z; As[nb][ac + 7][ar] = av1.w;
            *(float4*)&Bs[nb][br][bc] = bv0;
            *(float4*)&Bs[nb][br][bc + 4] = bv1;
            __syncthreads();
            buf = nb;
        }
    }
    #pragma unroll
    for (int i = 0; i < 8; i++) {
        int row = rowBase + rowT * 8 + i;
        if (row < M) {
            float* cp = &C[(size_t)row * Nd + colBase + colT * 8];
            *(float4*)cp       = make_float4(acc[i][0], acc[i][1], acc[i][2], acc[i][3]);
            *(float4*)(cp + 4) = make_float4(acc[i][4], acc[i][5], acc[i][6], acc[i][7]);
        }
    }
}

// ---------------- attention scores ---------------------------------------------
__global__ void attn_k(const float* __restrict__ feat, const float* __restrict__ al,
                       const float* __restrict__ ar, float* __restrict__ el,
                       float* __restrict__ er, int O) {
    int n = blockIdx.x;
    int h = threadIdx.x >> 5;
    int lane = threadIdx.x & 31;
    const float* f = feat + (size_t)n * (HH * O) + h * O;
    const float* a = al + h * O;
    const float* r = ar + h * O;
    float sl = 0.f, sr = 0.f;
    for (int j = lane * 4; j < O; j += 128) {
        float4 v = *(const float4*)&f[j];
        float4 av = *(const float4*)&a[j];
        float4 rv = *(const float4*)&r[j];
        sl += v.x * av.x + v.y * av.y + v.z * av.z + v.w * av.w;
        sr += v.x * rv.x + v.y * rv.y + v.z * rv.z + v.w * rv.w;
    }
    #pragma unroll
    for (int off = 16; off; off >>= 1) {
        sl += __shfl_down_sync(0xffffffffu, sl, off);
        sr += __shfl_down_sync(0xffffffffu, sr, off);
    }
    if (lane == 0) { el[n * HH + h] = sl; er[n * HH + h] = sr; }
}

// ---------------- fused softmax + aggregation + epilogue ----------------------
template<int O>
__global__ void __launch_bounds__(128) agg_k(
        const int* __restrict__ off0, const int* __restrict__ csr0,
        const int* __restrict__ off1, const int* __restrict__ csr1,
        const float* __restrict__ el0, const float* __restrict__ er0,
        const float* __restrict__ el1, const float* __restrict__ er1,
        const float* __restrict__ feat0, const float* __restrict__ feat1,
        const float* __restrict__ b0, const float* __restrict__ b1,
        float* __restrict__ out, int do_relu) {
    constexpr int WIDTH = 2 * O;
    constexpr int NV = WIDTH / 128;
    constexpr int CAP = 512;
    __shared__ float2 s_exp[CAP];
    __shared__ float2 s_red[128];
    __shared__ float  s_out[WIDTH];
    int n = blockIdx.x;
    int tid = threadIdx.x;
    int head = tid >> 6;
    float acc[NV];
    #pragma unroll
    for (int j = 0; j < NV; j++) acc[j] = 0.f;

    #pragma unroll
    for (int rel = 0; rel < 2; rel++) {
        const int* off = rel ? off1 : off0;
        const int* csr = rel ? csr1 : csr0;
        const float* el = rel ? el1 : el0;
        const float* er = rel ? er1 : er0;
        const float* feat = rel ? feat1 : feat0;
        int beg = off[n];
        int deg = off[n + 1] - beg;
        float ern0 = er[n * 2 + 0], ern1 = er[n * 2 + 1];
        __syncthreads();
        float d0 = 0.f, d1 = 0.f;
        for (int i = tid; i < deg; i += 128) {
            int s = csr[beg + i];
            float v0 = el[s * 2 + 0] + ern0;
            float v1 = el[s * 2 + 1] + ern1;
            v0 = v0 > 0.f ? v0 : 0.2f * v0;
            v1 = v1 > 0.f ? v1 : 0.2f * v1;
            v0 = __expf(v0);
            v1 = __expf(v1);
            if (i < CAP) s_exp[i] = make_float2(v0, v1);
            d0 += v0; d1 += v1;
        }
        s_red[tid] = make_float2(d0, d1);
        __syncthreads();
        #pragma unroll
        for (int o = 64; o; o >>= 1) {
            if (tid < o) {
                s_red[tid].x += s_red[tid + o].x;
                s_red[tid].y += s_red[tid + o].y;
            }
            __syncthreads();
        }
        float inv0 = 1.f / fmaxf(s_red[0].x, 1e-9f);
        float inv1 = 1.f / fmaxf(s_red[0].y, 1e-9f);
        float inv = head ? inv1 : inv0;
        #pragma unroll 4
        for (int i = 0; i < deg; i++) {
            int s = csr[beg + i];
            float a;
            if (i < CAP) {
                float2 ev = s_exp[i];
                a = (head ? ev.y : ev.x) * inv;
            } else {
                float v = el[s * 2 + head] + (head ? ern1 : ern0);
                v = v > 0.f ? v : 0.2f * v;
                a = __expf(v) * inv;
            }
            const float* fp = feat + (size_t)s * WIDTH + tid * NV;
            if (NV == 4) {
                float4 v = *(const float4*)fp;
                acc[0] += a * v.x; acc[1] += a * v.y;
                acc[2] += a * v.z; acc[3] += a * v.w;
            } else {
                float2 v = *(const float2*)fp;
                acc[0] += a * v.x; acc[1] += a * v.y;
            }
        }
    }
    #pragma unroll
    for (int j = 0; j < NV; j++) s_out[tid * NV + j] = acc[j];
    __syncthreads();
    for (int j = tid; j < O; j += 128) {
        float v = s_out[j] + s_out[j + O]
                + b0[j] + b0[j + O] + b1[j] + b1[j + O];
        v *= 0.5f;
        if (do_relu) v = fmaxf(v, 0.f);
        out[(size_t)n * O + j] = v;
    }
}

// ---------------- host launch ---------------------------------------------------
static float* symf(const void* s) { void* p = nullptr; cudaGetSymbolAddress(&p, s); return (float*)p; }
static int*   symi(const void* s) { void* p = nullptr; cudaGetSymbolAddress(&p, s); return (int*)p; }

struct Ctx {
    cudaStream_t s1, s2;
    cudaEvent_t fork1, join1a, join1b, fork2, join2;
    Ctx() {
        cudaStreamCreateWithFlags(&s1, cudaStreamNonBlocking);
        cudaStreamCreateWithFlags(&s2, cudaStreamNonBlocking);
        cudaEventCreateWithFlags(&fork1,  cudaEventDisableTiming);
        cudaEventCreateWithFlags(&join1a, cudaEventDisableTiming);
        cudaEventCreateWithFlags(&join1b, cudaEventDisableTiming);
        cudaEventCreateWithFlags(&fork2,  cudaEventDisableTiming);
        cudaEventCreateWithFlags(&join2,  cudaEventDisableTiming);
    }
};

extern "C" void kernel_launch(void* const* d_in, const int* in_sizes, int n_in,
                              void* d_out, int out_size) {
    static Ctx ctx;   // host-side resources only; created once, no device alloc
    const float* x     = (const float*)d_in[0];
    const int*   src0  = (const int*)d_in[1];
    const int*   dst0  = (const int*)d_in[2];
    const int*   src1  = (const int*)d_in[3];
    const int*   dst1  = (const int*)d_in[4];
    const float* W1_0  = (const float*)d_in[5];
    const float* al1_0 = (const float*)d_in[6];
    const float* ar1_0 = (const float*)d_in[7];
    const float* b1_0  = (const float*)d_in[8];
    const float* W1_1  = (const float*)d_in[9];
    const float* al1_1 = (const float*)d_in[10];
    const float* ar1_1 = (const float*)d_in[11];
    const float* b1_1  = (const float*)d_in[12];
    const float* W2_0  = (const float*)d_in[13];
    const float* al2_0 = (const float*)d_in[14];
    const float* ar2_0 = (const float*)d_in[15];
    const float* b2_0  = (const float*)d_in[16];
    const float* W2_1  = (const float*)d_in[17];
    const float* al2_1 = (const float*)d_in[18];
    const float* ar2_1 = (const float*)d_in[19];
    const float* b2_1  = (const float*)d_in[20];
    float* out = (float*)d_out;

    float* feat0 = symf(g_feat0);
    float* feat1 = symf(g_feat1);
    float* h1    = symf(g_h1);
    float* el0 = symf(g_el0); float* er0 = symf(g_er0);
    float* el1 = symf(g_el1); float* er1 = symf(g_er1);
    int* deg0 = symi(g_deg0); int* deg1 = symi(g_deg1);
    int* off0 = symi(g_off0); int* off1 = symi(g_off1);
    int* pos0 = symi(g_pos0); int* pos1 = symi(g_pos1);
    int* csr0 = symi(g_csr0); int* csr1 = symi(g_csr1);
    int* bsum = symi(g_bsum);

    cudaStream_t s1 = ctx.s1, s2 = ctx.s2;

    // ---- fork: CSR build on s1, rel-1 pipeline on s2, rel-0 on default ----
    cudaEventRecord(ctx.fork1, 0);
    cudaStreamWaitEvent(s1, ctx.fork1, 0);
    cudaStreamWaitEvent(s2, ctx.fork1, 0);

    // CSR build (s1)
    zero_k<<<(NN + 255) / 256, 256, 0, s1>>>(deg0, deg1, NN);
    hist_k<<<(EE + 255) / 256, 256, 0, s1>>>(dst0, dst1, deg0, deg1);
    { dim3 g(NB, 2); scanA_k<<<g, 1024, 0, s1>>>(deg0, deg1, off0, off1, bsum); }
    scanB_k<<<1, 64, 0, s1>>>(bsum, off0, off1);
    { dim3 g(NB, 2); scanC_k<<<g, 1024, 0, s1>>>(bsum, off0, off1, pos0, pos1); }
    scat_k<<<(EE + 255) / 256, 256, 0, s1>>>(src0, dst0, src1, dst1, pos0, pos1, csr0, csr1);

    // layer-1 GEMMs + attn (default: rel 0, s2: rel 1)
    { dim3 g(512 / 128, (NN + 127) / 128);
      gemm_k<<<g, 256>>>(x, W1_0, feat0, NN, DD, 512);
      gemm_k<<<g, 256, 0, s2>>>(x, W1_1, feat1, NN, DD, 512); }
    attn_k<<<NN, 64>>>(feat0, al1_0, ar1_0, el0, er0, 256);
    attn_k<<<NN, 64, 0, s2>>>(feat1, al1_1, ar1_1, el1, er1, 256);

    // join
    cudaEventRecord(ctx.join1a, s1);
    cudaEventRecord(ctx.join1b, s2);
    cudaStreamWaitEvent(0, ctx.join1a, 0);
    cudaStreamWaitEvent(0, ctx.join1b, 0);

    agg_k<256><<<NN, 128>>>(off0, csr0, off1, csr1, el0, er0, el1, er1,
                            feat0, feat1, b1_0, b1_1, h1, 1);

    // ---- layer 2 ----
    cudaEventRecord(ctx.fork2, 0);
    cudaStreamWaitEvent(s2, ctx.fork2, 0);
    { dim3 g(256 / 128, (NN + 127) / 128);
      gemm_k<<<g, 256>>>(h1, W2_0, feat0, NN, 256, 256);
      gemm_k<<<g, 256, 0, s2>>>(h1, W2_1, feat1, NN, 256, 256); }
    attn_k<<<NN, 64>>>(feat0, al2_0, ar2_0, el0, er0, 128);
    attn_k<<<NN, 64, 0, s2>>>(feat1, al2_1, ar2_1, el1, er1, 128);
    cudaEventRecord(ctx.join2, s2);
    cudaStreamWaitEvent(0, ctx.join2, 0);

    agg_k<128><<<NN, 128>>>(off0, csr0, off1, csr1, el0, er0, el1, er1,
                            feat0, feat1, b2_0, b2_1, out, 0);
}

// round 5
// speedup vs baseline: 2.3631x; 1.3322x over previous
#include <cuda_runtime.h>
#include <cuda_bf16.h>
#include <cstdint>
#include <math.h>

#define NN   20000
#define EE   320000
#define DD   128
#define HH   2
#define NB   ((NN + 1023) / 1024)

// ---------------- scratch (device globals) ------------------------------------
__device__ float g_feat0[(size_t)NN * 512];
__device__ float g_feat1[(size_t)NN * 512];
__device__ float g_el0[NN * 2], g_er0[NN * 2];
__device__ float g_el1[NN * 2], g_er1[NN * 2];
__device__ int   g_deg0[NN], g_deg1[NN];
__device__ int   g_off0[NN + 1], g_off1[NN + 1];
__device__ int   g_pos0[NN], g_pos1[NN];
__device__ int   g_csr0[EE], g_csr1[EE];
__device__ int   g_bsum[64];
// split-bf16 operands
__device__ __align__(16) __nv_bfloat16 g_xhi[(size_t)NN * DD],  g_xlo[(size_t)NN * DD];
__device__ __align__(16) __nv_bfloat16 g_h1hi[(size_t)NN * 256], g_h1lo[(size_t)NN * 256];
__device__ __align__(16) __nv_bfloat16 g_w1hi0[512 * 128], g_w1lo0[512 * 128];
__device__ __align__(16) __nv_bfloat16 g_w1hi1[512 * 128], g_w1lo1[512 * 128];
__device__ __align__(16) __nv_bfloat16 g_w2hi0[256 * 256], g_w2lo0[256 * 256];
__device__ __align__(16) __nv_bfloat16 g_w2hi1[256 * 256], g_w2lo1[256 * 256];

// ---------------- CSR build -----------------------------------------------------
__global__ void zero_k(int* a, int* b, int n) {
    int i = blockIdx.x * blockDim.x + threadIdx.x;
    if (i < n) { a[i] = 0; b[i] = 0; }
}
__global__ void hist_k(const int* __restrict__ dst0, const int* __restrict__ dst1,
                       int* deg0, int* deg1) {
    int i = blockIdx.x * blockDim.x + threadIdx.x;
    if (i < EE) {
        atomicAdd(&deg0[dst0[i]], 1);
        atomicAdd(&deg1[dst1[i]], 1);
    }
}
__global__ void scanA_k(const int* __restrict__ deg0, const int* __restrict__ deg1,
                        int* off0, int* off1, int* bsum) {
    const int* deg = blockIdx.y ? deg1 : deg0;
    int* off = blockIdx.y ? off1 : off0;
    int i = blockIdx.x * 1024 + threadIdx.x;
    int lane = threadIdx.x & 31, wid = threadIdx.x >> 5;
    int v = (i < NN) ? deg[i] : 0;
    int x = v;
    #pragma unroll
    for (int o = 1; o < 32; o <<= 1) {
        int t = __shfl_up_sync(0xffffffffu, x, o);
        if (lane >= o) x += t;
    }
    __shared__ int wsum[32];
    if (lane == 31) wsum[wid] = x;
    __syncthreads();
    if (wid == 0) {
        int w = wsum[lane];
        #pragma unroll
        for (int o = 1; o < 32; o <<= 1) {
            int t = __shfl_up_sync(0xffffffffu, w, o);
            if (lane >= o) w += t;
        }
        wsum[lane] = w;
    }
    __syncthreads();
    int inc = x + (wid ? wsum[wid - 1] : 0);
    if (i < NN) off[i] = inc - v;
    if (threadIdx.x == 1023) bsum[blockIdx.y * 32 + blockIdx.x] = inc;
}
__global__ void scanB_k(int* bsum, int* off0, int* off1) {
    int y = threadIdx.x >> 5, lane = threadIdx.x & 31;
    int v = (lane < NB) ? bsum[y * 32 + lane] : 0;
    int x = v;
    #pragma unroll
    for (int o = 1; o < 32; o <<= 1) {
        int t = __shfl_up_sync(0xffffffffu, x, o);
        if (lane >= o) x += t;
    }
    if (lane < NB) bsum[y * 32 + lane] = x - v;
    if (lane == NB - 1) { int* off = y ? off1 : off0; off[NN] = x; }
}
__global__ void scanC_k(const int* __restrict__ bsum, int* off0, int* off1,
                        int* pos0, int* pos1) {
    int i = blockIdx.x * 1024 + threadIdx.x;
    if (i >= NN) return;
    int y = blockIdx.y;
    int* off = y ? off1 : off0;
    int* pos = y ? pos1 : pos0;
    int val = off[i] + bsum[y * 32 + blockIdx.x];
    off[i] = val; pos[i] = val;
}
__global__ void scat_k(const int* __restrict__ src0, const int* __restrict__ dst0,
                       const int* __restrict__ src1, const int* __restrict__ dst1,
                       int* pos0, int* pos1, int* csr0, int* csr1) {
    int i = blockIdx.x * blockDim.x + threadIdx.x;
    if (i < EE) {
        csr0[atomicAdd(&pos0[dst0[i]], 1)] = src0[i];
        csr1[atomicAdd(&pos1[dst1[i]], 1)] = src1[i];
    }
}

// ---------------- split-bf16 conversion kernels --------------------------------
__global__ void convX_k(const float* __restrict__ x, __nv_bfloat16* hi,
                        __nv_bfloat16* lo, int n) {
    int i = blockIdx.x * blockDim.x + threadIdx.x;
    if (i < n) {
        float v = x[i];
        __nv_bfloat16 h = __float2bfloat16(v);
        hi[i] = h;
        lo[i] = __float2bfloat16(v - __bfloat162float(h));
    }
}
// transpose W[K][Nd] -> Wt[Nd][K] with hi/lo split
__global__ void convW_k(const float* __restrict__ W, __nv_bfloat16* hi,
                        __nv_bfloat16* lo, int K, int Nd) {
    int i = blockIdx.x * blockDim.x + threadIdx.x;
    if (i >= K * Nd) return;
    int n = i / K, k = i % K;
    float v = W[(size_t)k * Nd + n];
    __nv_bfloat16 h = __float2bfloat16(v);
    hi[i] = h;
    lo[i] = __float2bfloat16(v - __bfloat162float(h));
}

// ---------------- mma.sync helpers ---------------------------------------------
__device__ __forceinline__ uint32_t smem_u32(const void* p) {
    uint32_t a;
    asm("{ .reg .u64 t; cvta.to.shared.u64 t, %1; cvt.u32.u64 %0, t; }" : "=r"(a) : "l"(p));
    return a;
}
__device__ __forceinline__ void ldsm_x4(uint32_t* r, uint32_t addr) {
    asm volatile("ldmatrix.sync.aligned.m8n8.x4.shared.b16 {%0,%1,%2,%3}, [%4];"
                 : "=r"(r[0]), "=r"(r[1]), "=r"(r[2]), "=r"(r[3]) : "r"(addr));
}
__device__ __forceinline__ void ldsm_x2(uint32_t* r, uint32_t addr) {
    asm volatile("ldmatrix.sync.aligned.m8n8.x2.shared.b16 {%0,%1}, [%2];"
                 : "=r"(r[0]), "=r"(r[1]) : "r"(addr));
}
__device__ __forceinline__ void mma_bf16(float* d, const uint32_t* a, const uint32_t* b) {
    asm volatile(
        "mma.sync.aligned.m16n8k16.row.col.f32.bf16.bf16.f32 "
        "{%0,%1,%2,%3}, {%4,%5,%6,%7}, {%8,%9}, {%0,%1,%2,%3};"
        : "+f"(d[0]), "+f"(d[1]), "+f"(d[2]), "+f"(d[3])
        : "r"(a[0]), "r"(a[1]), "r"(a[2]), "r"(a[3]), "r"(b[0]), "r"(b[1]));
}

// ---------------- tensor-core split-bf16 GEMM ----------------------------------
// C[M,Nd] = A[M,KTOT] * B[Nd,KTOT]^T; 3-term compensation (hihi+hilo+lohi).
// Block 128x128, 8 warps (2x4 of 64x32), BK=32, smem stride 40 bf16.
#define SSTR 40
__device__ __forceinline__ void load_chunk(const __nv_bfloat16* __restrict__ g,
        int ld, int rbase, int kofs, __nv_bfloat16* s, int rlim, int tid) {
    #pragma unroll
    for (int i = 0; i < 2; i++) {
        int id = tid + i * 256;
        int r = id >> 2;
        int c = (id & 3) * 8;
        uint4 v = make_uint4(0u, 0u, 0u, 0u);
        int gr = rbase + r;
        if (gr < rlim)
            v = *(const uint4*)(g + (size_t)gr * ld + kofs + c);
        *(uint4*)(s + r * SSTR + c) = v;
    }
}

template<int KTOT>
__global__ void __launch_bounds__(256) gemm_mma_k(
        const __nv_bfloat16* __restrict__ Ahi, const __nv_bfloat16* __restrict__ Alo,
        const __nv_bfloat16* __restrict__ Bhi, const __nv_bfloat16* __restrict__ Blo,
        float* __restrict__ C, int M, int Nd) {
    __shared__ __align__(16) __nv_bfloat16 sAhi[128 * SSTR];
    __shared__ __align__(16) __nv_bfloat16 sAlo[128 * SSTR];
    __shared__ __align__(16) __nv_bfloat16 sBhi[128 * SSTR];
    __shared__ __align__(16) __nv_bfloat16 sBlo[128 * SSTR];
    const int tid = threadIdx.x;
    const int w = tid >> 5;
    const int lane = tid & 31;
    const int rowBase = blockIdx.y * 128;
    const int colBase = blockIdx.x * 128;
    const int wRow = w >> 2;          // 0..1 -> 64 rows
    const int wCol = w & 3;           // 0..3 -> 32 cols

    uint32_t aBaseHi = smem_u32(sAhi), aBaseLo = smem_u32(sAlo);
    uint32_t bBaseHi = smem_u32(sBhi), bBaseLo = smem_u32(sBlo);

    float d[4][4][4];
    #pragma unroll
    for (int i = 0; i < 4; i++)
        #pragma unroll
        for (int j = 0; j < 4; j++)
            #pragma unroll
            for (int q = 0; q < 4; q++) d[i][j][q] = 0.f;

    constexpr int NKC = KTOT / 32;
    for (int kc = 0; kc < NKC; kc++) {
        load_chunk(Ahi, KTOT, rowBase, kc * 32, sAhi, M, tid);
        load_chunk(Alo, KTOT, rowBase, kc * 32, sAlo, M, tid);
        load_chunk(Bhi, KTOT, colBase, kc * 32, sBhi, 1 << 30, tid);
        load_chunk(Blo, KTOT, colBase, kc * 32, sBlo, 1 << 30, tid);
        __syncthreads();
        #pragma unroll
        for (int ks = 0; ks < 32; ks += 16) {
            // B fragments (resident): n-tile nt covers cols wCol*32+nt*8
            uint32_t bhi[4][2], blo[4][2];
            {
                int brow = (lane & 7);
                int bcol = ks + ((lane >> 3) & 1) * 8;
                #pragma unroll
                for (int nt = 0; nt < 4; nt++) {
                    uint32_t off = (uint32_t)(((wCol * 32 + nt * 8 + brow) * SSTR + bcol) * 2);
                    ldsm_x2(bhi[nt], bBaseHi + off);
                    ldsm_x2(blo[nt], bBaseLo + off);
                }
            }
            int arow = (lane & 15);
            int acol = ks + (lane >> 4) * 8;
            #pragma unroll
            for (int mt = 0; mt < 4; mt++) {
                uint32_t ahi[4], alo[4];
                uint32_t off = (uint32_t)(((wRow * 64 + mt * 16 + arow) * SSTR + acol) * 2);
                ldsm_x4(ahi, aBaseHi + off);
                ldsm_x4(alo, aBaseLo + off);
                #pragma unroll
                for (int nt = 0; nt < 4; nt++) {
                    mma_bf16(d[mt][nt], ahi, bhi[nt]);
                    mma_bf16(d[mt][nt], ahi, blo[nt]);
                    mma_bf16(d[mt][nt], alo, bhi[nt]);
                }
            }
        }
        __syncthreads();
    }
    // epilogue
    int mlocal = lane >> 2;
    int nlocal = (lane & 3) * 2;
    #pragma unroll
    for (int mt = 0; mt < 4; mt++) {
        int row = rowBase + wRow * 64 + mt * 16 + mlocal;
        #pragma unroll
        for (int nt = 0; nt < 4; nt++) {
            int col = colBase + wCol * 32 + nt * 8 + nlocal;
            if (row < M)
                *(float2*)&C[(size_t)row * Nd + col] = make_float2(d[mt][nt][0], d[mt][nt][1]);
            if (row + 8 < M)
                *(float2*)&C[(size_t)(row + 8) * Nd + col] = make_float2(d[mt][nt][2], d[mt][nt][3]);
        }
    }
}

// ---------------- attention scores ---------------------------------------------
__global__ void attn_k(const float* __restrict__ feat, const float* __restrict__ al,
                       const float* __restrict__ ar, float* __restrict__ el,
                       float* __restrict__ er, int O) {
    int n = blockIdx.x;
    int h = threadIdx.x >> 5;
    int lane = threadIdx.x & 31;
    const float* f = feat + (size_t)n * (HH * O) + h * O;
    const float* a = al + h * O;
    const float* r = ar + h * O;
    float sl = 0.f, sr = 0.f;
    for (int j = lane * 4; j < O; j += 128) {
        float4 v = *(const float4*)&f[j];
        float4 av = *(const float4*)&a[j];
        float4 rv = *(const float4*)&r[j];
        sl += v.x * av.x + v.y * av.y + v.z * av.z + v.w * av.w;
        sr += v.x * rv.x + v.y * rv.y + v.z * rv.z + v.w * rv.w;
    }
    #pragma unroll
    for (int off = 16; off; off >>= 1) {
        sl += __shfl_down_sync(0xffffffffu, sl, off);
        sr += __shfl_down_sync(0xffffffffu, sr, off);
    }
    if (lane == 0) { el[n * HH + h] = sl; er[n * HH + h] = sr; }
}

// ---------------- fused softmax + aggregation + epilogue ----------------------
template<int O>
__global__ void __launch_bounds__(128) agg_k(
        const int* __restrict__ off0, const int* __restrict__ csr0,
        const int* __restrict__ off1, const int* __restrict__ csr1,
        const float* __restrict__ el0, const float* __restrict__ er0,
        const float* __restrict__ el1, const float* __restrict__ er1,
        const float* __restrict__ feat0, const float* __restrict__ feat1,
        const float* __restrict__ b0, const float* __restrict__ b1,
        float* __restrict__ out, __nv_bfloat16* __restrict__ outHi,
        __nv_bfloat16* __restrict__ outLo, int do_relu) {
    constexpr int WIDTH = 2 * O;
    constexpr int NV = WIDTH / 128;
    constexpr int CAP = 512;
    __shared__ float2 s_exp[CAP];
    __shared__ float2 s_red[128];
    __shared__ float  s_out[WIDTH];
    int n = blockIdx.x;
    int tid = threadIdx.x;
    int head = tid >> 6;
    float acc[NV];
    #pragma unroll
    for (int j = 0; j < NV; j++) acc[j] = 0.f;

    #pragma unroll
    for (int rel = 0; rel < 2; rel++) {
        const int* off = rel ? off1 : off0;
        const int* csr = rel ? csr1 : csr0;
        const float* el = rel ? el1 : el0;
        const float* er = rel ? er1 : er0;
        const float* feat = rel ? feat1 : feat0;
        int beg = off[n];
        int deg = off[n + 1] - beg;
        float ern0 = er[n * 2 + 0], ern1 = er[n * 2 + 1];
        __syncthreads();
        float d0 = 0.f, d1 = 0.f;
        for (int i = tid; i < deg; i += 128) {
            int s = csr[beg + i];
            float v0 = el[s * 2 + 0] + ern0;
            float v1 = el[s * 2 + 1] + ern1;
            v0 = v0 > 0.f ? v0 : 0.2f * v0;
            v1 = v1 > 0.f ? v1 : 0.2f * v1;
            v0 = __expf(v0);
            v1 = __expf(v1);
            if (i < CAP) s_exp[i] = make_float2(v0, v1);
            d0 += v0; d1 += v1;
        }
        s_red[tid] = make_float2(d0, d1);
        __syncthreads();
        #pragma unroll
        for (int o = 64; o; o >>= 1) {
            if (tid < o) {
                s_red[tid].x += s_red[tid + o].x;
                s_red[tid].y += s_red[tid + o].y;
            }
            __syncthreads();
        }
        float inv0 = 1.f / fmaxf(s_red[0].x, 1e-9f);
        float inv1 = 1.f / fmaxf(s_red[0].y, 1e-9f);
        float inv = head ? inv1 : inv0;
        #pragma unroll 4
        for (int i = 0; i < deg; i++) {
            int s = csr[beg + i];
            float a;
            if (i < CAP) {
                float2 ev = s_exp[i];
                a = (head ? ev.y : ev.x) * inv;
            } else {
                float v = el[s * 2 + head] + (head ? ern1 : ern0);
                v = v > 0.f ? v : 0.2f * v;
                a = __expf(v) * inv;
            }
            const float* fp = feat + (size_t)s * WIDTH + tid * NV;
            if (NV == 4) {
                float4 v = *(const float4*)fp;
                acc[0] += a * v.x; acc[1] += a * v.y;
                acc[2] += a * v.z; acc[3] += a * v.w;
            } else {
                float2 v = *(const float2*)fp;
                acc[0] += a * v.x; acc[1] += a * v.y;
            }
        }
    }
    #pragma unroll
    for (int j = 0; j < NV; j++) s_out[tid * NV + j] = acc[j];
    __syncthreads();
    for (int j = tid; j < O; j += 128) {
        float v = s_out[j] + s_out[j + O]
                + b0[j] + b0[j + O] + b1[j] + b1[j + O];
        v *= 0.5f;
        if (do_relu) v = fmaxf(v, 0.f);
        if (outHi) {
            __nv_bfloat16 h = __float2bfloat16(v);
            outHi[(size_t)n * O + j] = h;
            outLo[(size_t)n * O + j] = __float2bfloat16(v - __bfloat162float(h));
        } else {
            out[(size_t)n * O + j] = v;
        }
    }
}

// ---------------- host launch ---------------------------------------------------
static float* symf(const void* s) { void* p = nullptr; cudaGetSymbolAddress(&p, s); return (float*)p; }
static int*   symi(const void* s) { void* p = nullptr; cudaGetSymbolAddress(&p, s); return (int*)p; }
static __nv_bfloat16* symb(const void* s) { void* p = nullptr; cudaGetSymbolAddress(&p, s); return (__nv_bfloat16*)p; }

struct Ctx {
    cudaStream_t s1, s2;
    cudaEvent_t fork1, join1a, join1b, fork2, join2;
    Ctx() {
        cudaStreamCreateWithFlags(&s1, cudaStreamNonBlocking);
        cudaStreamCreateWithFlags(&s2, cudaStreamNonBlocking);
        cudaEventCreateWithFlags(&fork1,  cudaEventDisableTiming);
        cudaEventCreateWithFlags(&join1a, cudaEventDisableTiming);
        cudaEventCreateWithFlags(&join1b, cudaEventDisableTiming);
        cudaEventCreateWithFlags(&fork2,  cudaEventDisableTiming);
        cudaEventCreateWithFlags(&join2,  cudaEventDisableTiming);
    }
};

extern "C" void kernel_launch(void* const* d_in, const int* in_sizes, int n_in,
                              void* d_out, int out_size) {
    static Ctx ctx;
    const float* x     = (const float*)d_in[0];
    const int*   src0  = (const int*)d_in[1];
    const int*   dst0  = (const int*)d_in[2];
    const int*   src1  = (const int*)d_in[3];
    const int*   dst1  = (const int*)d_in[4];
    const float* W1_0  = (const float*)d_in[5];
    const float* al1_0 = (const float*)d_in[6];
    const float* ar1_0 = (const float*)d_in[7];
    const float* b1_0  = (const float*)d_in[8];
    const float* W1_1  = (const float*)d_in[9];
    const float* al1_1 = (const float*)d_in[10];
    const float* ar1_1 = (const float*)d_in[11];
    const float* b1_1  = (const float*)d_in[12];
    const float* W2_0  = (const float*)d_in[13];
    const float* al2_0 = (const float*)d_in[14];
    const float* ar2_0 = (const float*)d_in[15];
    const float* b2_0  = (const float*)d_in[16];
    const float* W2_1  = (const float*)d_in[17];
    const float* al2_1 = (const float*)d_in[18];
    const float* ar2_1 = (const float*)d_in[19];
    const float* b2_1  = (const float*)d_in[20];
    float* out = (float*)d_out;

    float* feat0 = symf(g_feat0);
    float* feat1 = symf(g_feat1);
    float* el0 = symf(g_el0); float* er0 = symf(g_er0);
    float* el1 = symf(g_el1); float* er1 = symf(g_er1);
    int* deg0 = symi(g_deg0); int* deg1 = symi(g_deg1);
    int* off0 = symi(g_off0); int* off1 = symi(g_off1);
    int* pos0 = symi(g_pos0); int* pos1 = symi(g_pos1);
    int* csr0 = symi(g_csr0); int* csr1 = symi(g_csr1);
    int* bsum = symi(g_bsum);
    __nv_bfloat16* xhi = symb(g_xhi);   __nv_bfloat16* xlo = symb(g_xlo);
    __nv_bfloat16* h1hi = symb(g_h1hi); __nv_bfloat16* h1lo = symb(g_h1lo);
    __nv_bfloat16* w1hi0 = symb(g_w1hi0); __nv_bfloat16* w1lo0 = symb(g_w1lo0);
    __nv_bfloat16* w1hi1 = symb(g_w1hi1); __nv_bfloat16* w1lo1 = symb(g_w1lo1);
    __nv_bfloat16* w2hi0 = symb(g_w2hi0); __nv_bfloat16* w2lo0 = symb(g_w2lo0);
    __nv_bfloat16* w2hi1 = symb(g_w2hi1); __nv_bfloat16* w2lo1 = symb(g_w2lo1);

    cudaStream_t s1 = ctx.s1, s2 = ctx.s2;

    // convert x (needed by both relations) before fork
    convX_k<<<(NN * DD + 255) / 256, 256>>>(x, xhi, xlo, NN * DD);

    cudaEventRecord(ctx.fork1, 0);
    cudaStreamWaitEvent(s1, ctx.fork1, 0);
    cudaStreamWaitEvent(s2, ctx.fork1, 0);

    // CSR build (s1)
    zero_k<<<(NN + 255) / 256, 256, 0, s1>>>(deg0, deg1, NN);
    hist_k<<<(EE + 255) / 256, 256, 0, s1>>>(dst0, dst1, deg0, deg1);
    { dim3 g(NB, 2); scanA_k<<<g, 1024, 0, s1>>>(deg0, deg1, off0, off1, bsum); }
    scanB_k<<<1, 64, 0, s1>>>(bsum, off0, off1);
    { dim3 g(NB, 2); scanC_k<<<g, 1024, 0, s1>>>(bsum, off0, off1, pos0, pos1); }
    scat_k<<<(EE + 255) / 256, 256, 0, s1>>>(src0, dst0, src1, dst1, pos0, pos1, csr0, csr1);

    // weight conversions + layer-1 GEMM + attn
    convW_k<<<(512 * 128 + 255) / 256, 256>>>(W1_0, w1hi0, w1lo0, 128, 512);
    convW_k<<<(256 * 256 + 255) / 256, 256>>>(W2_0, w2hi0, w2lo0, 256, 256);
    convW_k<<<(512 * 128 + 255) / 256, 256, 0, s2>>>(W1_1, w1hi1, w1lo1, 128, 512);
    convW_k<<<(256 * 256 + 255) / 256, 256, 0, s2>>>(W2_1, w2hi1, w2lo1, 256, 256);

    { dim3 g(4, (NN + 127) / 128);
      gemm_mma_k<128><<<g, 256>>>(xhi, xlo, w1hi0, w1lo0, feat0, NN, 512);
      gemm_mma_k<128><<<g, 256, 0, s2>>>(xhi, xlo, w1hi1, w1lo1, feat1, NN, 512); }
    attn_k<<<NN, 64>>>(feat0, al1_0, ar1_0, el0, er0, 256);
    attn_k<<<NN, 64, 0, s2>>>(feat1, al1_1, ar1_1, el1, er1, 256);

    cudaEventRecord(ctx.join1a, s1);
    cudaEventRecord(ctx.join1b, s2);
    cudaStreamWaitEvent(0, ctx.join1a, 0);
    cudaStreamWaitEvent(0, ctx.join1b, 0);

    agg_k<256><<<NN, 128>>>(off0, csr0, off1, csr1, el0, er0, el1, er1,
                            feat0, feat1, b1_0, b1_1, nullptr, h1hi, h1lo, 1);

    // ---- layer 2 ----
    cudaEventRecord(ctx.fork2, 0);
    cudaStreamWaitEvent(s2, ctx.fork2, 0);
    { dim3 g(2, (NN + 127) / 128);
      gemm_mma_k<256><<<g, 256>>>(h1hi, h1lo, w2hi0, w2lo0, feat0, NN, 256);
      gemm_mma_k<256><<<g, 256, 0, s2>>>(h1hi, h1lo, w2hi1, w2lo1, feat1, NN, 256); }
    attn_k<<<NN, 64>>>(feat0, al2_0, ar2_0, el0, er0, 128);
    attn_k<<<NN, 64, 0, s2>>>(feat1, al2_1, ar2_1, el1, er1, 128);
    cudaEventRecord(ctx.join2, s2);
    cudaStreamWaitEvent(0, ctx.join2, 0);

    agg_k<128><<<NN, 128>>>(off0, csr0, off1, csr1, el0, er0, el1, er1,
                            feat0, feat1, b2_0, b2_1, out, nullptr, nullptr, 0);
}

// round 6
// speedup vs baseline: 2.5745x; 1.0895x over previous
#include <cuda_runtime.h>
#include <cuda_bf16.h>
#include <cstdint>
#include <math.h>

#define NN   20000
#define EE   320000
#define DD   128
#define HH   2
#define NB   ((NN + 1023) / 1024)

// ---------------- scratch (device globals) ------------------------------------
__device__ float g_feat0[(size_t)NN * 512];
__device__ float g_feat1[(size_t)NN * 512];
__device__ float g_el0[NN * 2], g_er0[NN * 2];
__device__ float g_el1[NN * 2], g_er1[NN * 2];
__device__ int   g_deg0[NN], g_deg1[NN];
__device__ int   g_off0[NN + 1], g_off1[NN + 1];
__device__ int   g_pos0[NN], g_pos1[NN];
__device__ int   g_csr0[EE], g_csr1[EE];
__device__ int   g_bsum[64];
__device__ __align__(16) __nv_bfloat16 g_xhi[(size_t)NN * DD],  g_xlo[(size_t)NN * DD];
__device__ __align__(16) __nv_bfloat16 g_h1hi[(size_t)NN * 256], g_h1lo[(size_t)NN * 256];
__device__ __align__(16) __nv_bfloat16 g_w1hi0[512 * 128], g_w1lo0[512 * 128];
__device__ __align__(16) __nv_bfloat16 g_w1hi1[512 * 128], g_w1lo1[512 * 128];
__device__ __align__(16) __nv_bfloat16 g_w2hi0[256 * 256], g_w2lo0[256 * 256];
__device__ __align__(16) __nv_bfloat16 g_w2hi1[256 * 256], g_w2lo1[256 * 256];

// ---------------- CSR build -----------------------------------------------------
__global__ void zero_k(int* a, int* b, int n) {
    int i = blockIdx.x * blockDim.x + threadIdx.x;
    if (i < n) { a[i] = 0; b[i] = 0; }
}
__global__ void zeroEl_k(float* el0, float* er0, float* el1, float* er1, int n) {
    int i = blockIdx.x * blockDim.x + threadIdx.x;
    if (i < n) { el0[i] = 0.f; er0[i] = 0.f; el1[i] = 0.f; er1[i] = 0.f; }
}
__global__ void hist_k(const int* __restrict__ dst0, const int* __restrict__ dst1,
                       int* deg0, int* deg1) {
    int i = blockIdx.x * blockDim.x + threadIdx.x;
    if (i < EE) {
        atomicAdd(&deg0[dst0[i]], 1);
        atomicAdd(&deg1[dst1[i]], 1);
    }
}
__global__ void scanA_k(const int* __restrict__ deg0, const int* __restrict__ deg1,
                        int* off0, int* off1, int* bsum) {
    const int* deg = blockIdx.y ? deg1 : deg0;
    int* off = blockIdx.y ? off1 : off0;
    int i = blockIdx.x * 1024 + threadIdx.x;
    int lane = threadIdx.x & 31, wid = threadIdx.x >> 5;
    int v = (i < NN) ? deg[i] : 0;
    int x = v;
    #pragma unroll
    for (int o = 1; o < 32; o <<= 1) {
        int t = __shfl_up_sync(0xffffffffu, x, o);
        if (lane >= o) x += t;
    }
    __shared__ int wsum[32];
    if (lane == 31) wsum[wid] = x;
    __syncthreads();
    if (wid == 0) {
        int w = wsum[lane];
        #pragma unroll
        for (int o = 1; o < 32; o <<= 1) {
            int t = __shfl_up_sync(0xffffffffu, w, o);
            if (lane >= o) w += t;
        }
        wsum[lane] = w;
    }
    __syncthreads();
    int inc = x + (wid ? wsum[wid - 1] : 0);
    if (i < NN) off[i] = inc - v;
    if (threadIdx.x == 1023) bsum[blockIdx.y * 32 + blockIdx.x] = inc;
}
__global__ void scanB_k(int* bsum, int* off0, int* off1) {
    int y = threadIdx.x >> 5, lane = threadIdx.x & 31;
    int v = (lane < NB) ? bsum[y * 32 + lane] : 0;
    int x = v;
    #pragma unroll
    for (int o = 1; o < 32; o <<= 1) {
        int t = __shfl_up_sync(0xffffffffu, x, o);
        if (lane >= o) x += t;
    }
    if (lane < NB) bsum[y * 32 + lane] = x - v;
    if (lane == NB - 1) { int* off = y ? off1 : off0; off[NN] = x; }
}
__global__ void scanC_k(const int* __restrict__ bsum, int* off0, int* off1,
                        int* pos0, int* pos1) {
    int i = blockIdx.x * 1024 + threadIdx.x;
    if (i >= NN) return;
    int y = blockIdx.y;
    int* off = y ? off1 : off0;
    int* pos = y ? pos1 : pos0;
    int val = off[i] + bsum[y * 32 + blockIdx.x];
    off[i] = val; pos[i] = val;
}
__global__ void scat_k(const int* __restrict__ src0, const int* __restrict__ dst0,
                       const int* __restrict__ src1, const int* __restrict__ dst1,
                       int* pos0, int* pos1, int* csr0, int* csr1) {
    int i = blockIdx.x * blockDim.x + threadIdx.x;
    if (i < EE) {
        csr0[atomicAdd(&pos0[dst0[i]], 1)] = src0[i];
        csr1[atomicAdd(&pos1[dst1[i]], 1)] = src1[i];
    }
}

// ---------------- split-bf16 conversion kernels --------------------------------
__global__ void convX_k(const float* __restrict__ x, __nv_bfloat16* hi,
                        __nv_bfloat16* lo, int n) {
    int i = blockIdx.x * blockDim.x + threadIdx.x;
    if (i < n) {
        float v = x[i];
        __nv_bfloat16 h = __float2bfloat16(v);
        hi[i] = h;
        lo[i] = __float2bfloat16(v - __bfloat162float(h));
    }
}
__global__ void convW_k(const float* __restrict__ W, __nv_bfloat16* hi,
                        __nv_bfloat16* lo, int K, int Nd) {
    int i = blockIdx.x * blockDim.x + threadIdx.x;
    if (i >= K * Nd) return;
    int n = i / K, k = i % K;
    float v = W[(size_t)k * Nd + n];
    __nv_bfloat16 h = __float2bfloat16(v);
    hi[i] = h;
    lo[i] = __float2bfloat16(v - __bfloat162float(h));
}

// ---------------- mma.sync helpers ---------------------------------------------
__device__ __forceinline__ uint32_t smem_u32(const void* p) {
    uint32_t a;
    asm("{ .reg .u64 t; cvta.to.shared.u64 t, %1; cvt.u32.u64 %0, t; }" : "=r"(a) : "l"(p));
    return a;
}
__device__ __forceinline__ void ldsm_x4(uint32_t* r, uint32_t addr) {
    asm volatile("ldmatrix.sync.aligned.m8n8.x4.shared.b16 {%0,%1,%2,%3}, [%4];"
                 : "=r"(r[0]), "=r"(r[1]), "=r"(r[2]), "=r"(r[3]) : "r"(addr));
}
__device__ __forceinline__ void ldsm_x2(uint32_t* r, uint32_t addr) {
    asm volatile("ldmatrix.sync.aligned.m8n8.x2.shared.b16 {%0,%1}, [%2];"
                 : "=r"(r[0]), "=r"(r[1]) : "r"(addr));
}
__device__ __forceinline__ void mma_bf16(float* d, const uint32_t* a, const uint32_t* b) {
    asm volatile(
        "mma.sync.aligned.m16n8k16.row.col.f32.bf16.bf16.f32 "
        "{%0,%1,%2,%3}, {%4,%5,%6,%7}, {%8,%9}, {%0,%1,%2,%3};"
        : "+f"(d[0]), "+f"(d[1]), "+f"(d[2]), "+f"(d[3])
        : "r"(a[0]), "r"(a[1]), "r"(a[2]), "r"(a[3]), "r"(b[0]), "r"(b[1]));
}

// ---------------- tensor-core split-bf16 GEMM + fused attn epilogue ------------
// C[M,Nd] = A[M,KTOT] * B[Nd,KTOT]^T; 3-term compensation (hihi+hilo+lohi).
// Epilogue also accumulates el[row,h] += sum(feat*al), er likewise, via atomics.
#define SSTR 40
__device__ __forceinline__ void load_chunk(const __nv_bfloat16* __restrict__ g,
        int ld, int rbase, int kofs, __nv_bfloat16* s, int rlim, int tid) {
    #pragma unroll
    for (int i = 0; i < 2; i++) {
        int id = tid + i * 256;
        int r = id >> 2;
        int c = (id & 3) * 8;
        uint4 v = make_uint4(0u, 0u, 0u, 0u);
        int gr = rbase + r;
        if (gr < rlim)
            v = *(const uint4*)(g + (size_t)gr * ld + kofs + c);
        *(uint4*)(s + r * SSTR + c) = v;
    }
}

template<int KTOT, int O>
__global__ void __launch_bounds__(256) gemm_mma_k(
        const __nv_bfloat16* __restrict__ Ahi, const __nv_bfloat16* __restrict__ Alo,
        const __nv_bfloat16* __restrict__ Bhi, const __nv_bfloat16* __restrict__ Blo,
        float* __restrict__ C, int M, int Nd,
        const float* __restrict__ al, const float* __restrict__ ar,
        float* __restrict__ el, float* __restrict__ er) {
    __shared__ __align__(16) __nv_bfloat16 sAhi[128 * SSTR];
    __shared__ __align__(16) __nv_bfloat16 sAlo[128 * SSTR];
    __shared__ __align__(16) __nv_bfloat16 sBhi[128 * SSTR];
    __shared__ __align__(16) __nv_bfloat16 sBlo[128 * SSTR];
    const int tid = threadIdx.x;
    const int w = tid >> 5;
    const int lane = tid & 31;
    const int rowBase = blockIdx.y * 128;
    const int colBase = blockIdx.x * 128;
    const int wRow = w >> 2;
    const int wCol = w & 3;

    uint32_t aBaseHi = smem_u32(sAhi), aBaseLo = smem_u32(sAlo);
    uint32_t bBaseHi = smem_u32(sBhi), bBaseLo = smem_u32(sBlo);

    float d[4][4][4];
    #pragma unroll
    for (int i = 0; i < 4; i++)
        #pragma unroll
        for (int j = 0; j < 4; j++)
            #pragma unroll
            for (int q = 0; q < 4; q++) d[i][j][q] = 0.f;

    constexpr int NKC = KTOT / 32;
    for (int kc = 0; kc < NKC; kc++) {
        load_chunk(Ahi, KTOT, rowBase, kc * 32, sAhi, M, tid);
        load_chunk(Alo, KTOT, rowBase, kc * 32, sAlo, M, tid);
        load_chunk(Bhi, KTOT, colBase, kc * 32, sBhi, 1 << 30, tid);
        load_chunk(Blo, KTOT, colBase, kc * 32, sBlo, 1 << 30, tid);
        __syncthreads();
        #pragma unroll
        for (int ks = 0; ks < 32; ks += 16) {
            uint32_t bhi[4][2], blo[4][2];
            {
                int brow = (lane & 7);
                int bcol = ks + ((lane >> 3) & 1) * 8;
                #pragma unroll
                for (int nt = 0; nt < 4; nt++) {
                    uint32_t off = (uint32_t)(((wCol * 32 + nt * 8 + brow) * SSTR + bcol) * 2);
                    ldsm_x2(bhi[nt], bBaseHi + off);
                    ldsm_x2(blo[nt], bBaseLo + off);
                }
            }
            int arow = (lane & 15);
            int acol = ks + (lane >> 4) * 8;
            #pragma unroll
            for (int mt = 0; mt < 4; mt++) {
                uint32_t ahi[4], alo[4];
                uint32_t off = (uint32_t)(((wRow * 64 + mt * 16 + arow) * SSTR + acol) * 2);
                ldsm_x4(ahi, aBaseHi + off);
                ldsm_x4(alo, aBaseLo + off);
                #pragma unroll
                for (int nt = 0; nt < 4; nt++) {
                    mma_bf16(d[mt][nt], ahi, bhi[nt]);
                    mma_bf16(d[mt][nt], ahi, blo[nt]);
                    mma_bf16(d[mt][nt], alo, bhi[nt]);
                }
            }
        }
        __syncthreads();
    }

    // ---- epilogue: C write + fused attn partial dot products ----
    int mlocal = lane >> 2;
    int nlocal = (lane & 3) * 2;
    // this thread's columns (same for all mt): cols[nt] = colBase+wCol*32+nt*8+nlocal (+0,+1)
    float alv[4][2], arv[4][2];
    int head;
    {
        int c0 = colBase + wCol * 32 + nlocal;      // nt=0 col
        head = c0 / O;                              // 32-col warp tile never straddles heads
        #pragma unroll
        for (int nt = 0; nt < 4; nt++) {
            int c = c0 + nt * 8 - head * O;
            alv[nt][0] = al[head * O + c]; alv[nt][1] = al[head * O + c + 1];
            arv[nt][0] = ar[head * O + c]; arv[nt][1] = ar[head * O + c + 1];
        }
    }
    #pragma unroll
    for (int mt = 0; mt < 4; mt++) {
        int row = rowBase + wRow * 64 + mt * 16 + mlocal;
        float pel0 = 0.f, per0 = 0.f, pel8 = 0.f, per8 = 0.f;
        #pragma unroll
        for (int nt = 0; nt < 4; nt++) {
            int col = colBase + wCol * 32 + nt * 8 + nlocal;
            if (row < M)
                *(float2*)&C[(size_t)row * Nd + col] = make_float2(d[mt][nt][0], d[mt][nt][1]);
            if (row + 8 < M)
                *(float2*)&C[(size_t)(row + 8) * Nd + col] = make_float2(d[mt][nt][2], d[mt][nt][3]);
            pel0 += d[mt][nt][0] * alv[nt][0] + d[mt][nt][1] * alv[nt][1];
            per0 += d[mt][nt][0] * arv[nt][0] + d[mt][nt][1] * arv[nt][1];
            pel8 += d[mt][nt][2] * alv[nt][0] + d[mt][nt][3] * alv[nt][1];
            per8 += d[mt][nt][2] * arv[nt][0] + d[mt][nt][3] * arv[nt][1];
        }
        // reduce across the 4 lanes sharing these rows (lane&3 varies)
        #pragma unroll
        for (int o = 1; o < 4; o <<= 1) {
            pel0 += __shfl_xor_sync(0xffffffffu, pel0, o);
            per0 += __shfl_xor_sync(0xffffffffu, per0, o);
            pel8 += __shfl_xor_sync(0xffffffffu, pel8, o);
            per8 += __shfl_xor_sync(0xffffffffu, per8, o);
        }
        if ((lane & 3) == 0) {
            if (row < M) {
                atomicAdd(&el[row * HH + head], pel0);
                atomicAdd(&er[row * HH + head], per0);
            }
            if (row + 8 < M) {
                atomicAdd(&el[(row + 8) * HH + head], pel8);
                atomicAdd(&er[(row + 8) * HH + head], per8);
            }
        }
    }
}

// ---------------- fused softmax + aggregation + epilogue ----------------------
template<int O>
__global__ void __launch_bounds__(128) agg_k(
        const int* __restrict__ off0, const int* __restrict__ csr0,
        const int* __restrict__ off1, const int* __restrict__ csr1,
        const float* __restrict__ el0, const float* __restrict__ er0,
        const float* __restrict__ el1, const float* __restrict__ er1,
        const float* __restrict__ feat0, const float* __restrict__ feat1,
        const float* __restrict__ b0, const float* __restrict__ b1,
        float* __restrict__ out, __nv_bfloat16* __restrict__ outHi,
        __nv_bfloat16* __restrict__ outLo, int do_relu) {
    constexpr int WIDTH = 2 * O;
    constexpr int NV = WIDTH / 128;
    constexpr int CAP = 512;
    __shared__ float2 s_exp[CAP];
    __shared__ float2 s_wred[4];
    __shared__ float  s_out[WIDTH];
    int n = blockIdx.x;
    int tid = threadIdx.x;
    int lane = tid & 31, wid = tid >> 5;
    int head = tid >> 6;
    float acc[NV];
    #pragma unroll
    for (int j = 0; j < NV; j++) acc[j] = 0.f;

    #pragma unroll
    for (int rel = 0; rel < 2; rel++) {
        const int* off = rel ? off1 : off0;
        const int* csr = rel ? csr1 : csr0;
        const float* el = rel ? el1 : el0;
        const float* er = rel ? er1 : er0;
        const float* feat = rel ? feat1 : feat0;
        int beg = off[n];
        int deg = off[n + 1] - beg;
        float ern0 = er[n * 2 + 0], ern1 = er[n * 2 + 1];
        __syncthreads();                 // protect s_exp reuse across relations
        float d0 = 0.f, d1 = 0.f;
        for (int i = tid; i < deg; i += 128) {
            int s = csr[beg + i];
            float v0 = el[s * 2 + 0] + ern0;
            float v1 = el[s * 2 + 1] + ern1;
            v0 = v0 > 0.f ? v0 : 0.2f * v0;
            v1 = v1 > 0.f ? v1 : 0.2f * v1;
            v0 = __expf(v0);
            v1 = __expf(v1);
            if (i < CAP) s_exp[i] = make_float2(v0, v1);
            d0 += v0; d1 += v1;
        }
        #pragma unroll
        for (int o = 16; o; o >>= 1) {
            d0 += __shfl_xor_sync(0xffffffffu, d0, o);
            d1 += __shfl_xor_sync(0xffffffffu, d1, o);
        }
        if (lane == 0) s_wred[wid] = make_float2(d0, d1);
        __syncthreads();
        float t0 = s_wred[0].x + s_wred[1].x + s_wred[2].x + s_wred[3].x;
        float t1 = s_wred[0].y + s_wred[1].y + s_wred[2].y + s_wred[3].y;
        float inv0 = 1.f / fmaxf(t0, 1e-9f);
        float inv1 = 1.f / fmaxf(t1, 1e-9f);
        float inv = head ? inv1 : inv0;
        #pragma unroll 4
        for (int i = 0; i < deg; i++) {
            int s = csr[beg + i];
            float a;
            if (i < CAP) {
                float2 ev = s_exp[i];
                a = (head ? ev.y : ev.x) * inv;
            } else {
                float v = el[s * 2 + head] + (head ? ern1 : ern0);
                v = v > 0.f ? v : 0.2f * v;
                a = __expf(v) * inv;
            }
            const float* fp = feat + (size_t)s * WIDTH + tid * NV;
            if (NV == 4) {
                float4 v = *(const float4*)fp;
                acc[0] += a * v.x; acc[1] += a * v.y;
                acc[2] += a * v.z; acc[3] += a * v.w;
            } else {
                float2 v = *(const float2*)fp;
                acc[0] += a * v.x; acc[1] += a * v.y;
            }
        }
    }
    #pragma unroll
    for (int j = 0; j < NV; j++) s_out[tid * NV + j] = acc[j];
    __syncthreads();
    for (int j = tid; j < O; j += 128) {
        float v = s_out[j] + s_out[j + O]
                + b0[j] + b0[j + O] + b1[j] + b1[j + O];
        v *= 0.5f;
        if (do_relu) v = fmaxf(v, 0.f);
        if (outHi) {
            __nv_bfloat16 h = __float2bfloat16(v);
            outHi[(size_t)n * O + j] = h;
            outLo[(size_t)n * O + j] = __float2bfloat16(v - __bfloat162float(h));
        } else {
            out[(size_t)n * O + j] = v;
        }
    }
}

// ---------------- host launch ---------------------------------------------------
static float* symf(const void* s) { void* p = nullptr; cudaGetSymbolAddress(&p, s); return (float*)p; }
static int*   symi(const void* s) { void* p = nullptr; cudaGetSymbolAddress(&p, s); return (int*)p; }
static __nv_bfloat16* symb(const void* s) { void* p = nullptr; cudaGetSymbolAddress(&p, s); return (__nv_bfloat16*)p; }

struct Ctx {
    cudaStream_t s1, s2;
    cudaEvent_t fork1, join1a, join1b, fork2, join2;
    Ctx() {
        cudaStreamCreateWithFlags(&s1, cudaStreamNonBlocking);
        cudaStreamCreateWithFlags(&s2, cudaStreamNonBlocking);
        cudaEventCreateWithFlags(&fork1,  cudaEventDisableTiming);
        cudaEventCreateWithFlags(&join1a, cudaEventDisableTiming);
        cudaEventCreateWithFlags(&join1b, cudaEventDisableTiming);
        cudaEventCreateWithFlags(&fork2,  cudaEventDisableTiming);
        cudaEventCreateWithFlags(&join2,  cudaEventDisableTiming);
    }
};

extern "C" void kernel_launch(void* const* d_in, const int* in_sizes, int n_in,
                              void* d_out, int out_size) {
    static Ctx ctx;
    const float* x     = (const float*)d_in[0];
    const int*   src0  = (const int*)d_in[1];
    const int*   dst0  = (const int*)d_in[2];
    const int*   src1  = (const int*)d_in[3];
    const int*   dst1  = (const int*)d_in[4];
    const float* W1_0  = (const float*)d_in[5];
    const float* al1_0 = (const float*)d_in[6];
    const float* ar1_0 = (const float*)d_in[7];
    const float* b1_0  = (const float*)d_in[8];
    const float* W1_1  = (const float*)d_in[9];
    const float* al1_1 = (const float*)d_in[10];
    const float* ar1_1 = (const float*)d_in[11];
    const float* b1_1  = (const float*)d_in[12];
    const float* W2_0  = (const float*)d_in[13];
    const float* al2_0 = (const float*)d_in[14];
    const float* ar2_0 = (const float*)d_in[15];
    const float* b2_0  = (const float*)d_in[16];
    const float* W2_1  = (const float*)d_in[17];
    const float* al2_1 = (const float*)d_in[18];
    const float* ar2_1 = (const float*)d_in[19];
    const float* b2_1  = (const float*)d_in[20];
    float* out = (float*)d_out;

    float* feat0 = symf(g_feat0);
    float* feat1 = symf(g_feat1);
    float* el0 = symf(g_el0); float* er0 = symf(g_er0);
    float* el1 = symf(g_el1); float* er1 = symf(g_er1);
    int* deg0 = symi(g_deg0); int* deg1 = symi(g_deg1);
    int* off0 = symi(g_off0); int* off1 = symi(g_off1);
    int* pos0 = symi(g_pos0); int* pos1 = symi(g_pos1);
    int* csr0 = symi(g_csr0); int* csr1 = symi(g_csr1);
    int* bsum = symi(g_bsum);
    __nv_bfloat16* xhi = symb(g_xhi);   __nv_bfloat16* xlo = symb(g_xlo);
    __nv_bfloat16* h1hi = symb(g_h1hi); __nv_bfloat16* h1lo = symb(g_h1lo);
    __nv_bfloat16* w1hi0 = symb(g_w1hi0); __nv_bfloat16* w1lo0 = symb(g_w1lo0);
    __nv_bfloat16* w1hi1 = symb(g_w1hi1); __nv_bfloat16* w1lo1 = symb(g_w1lo1);
    __nv_bfloat16* w2hi0 = symb(g_w2hi0); __nv_bfloat16* w2lo0 = symb(g_w2lo0);
    __nv_bfloat16* w2hi1 = symb(g_w2hi1); __nv_bfloat16* w2lo1 = symb(g_w2lo1);

    cudaStream_t s1 = ctx.s1, s2 = ctx.s2;

    // pre-fork: convert x, zero el/er accumulators (used by layer-1 epilogues)
    convX_k<<<(NN * DD + 255) / 256, 256>>>(x, xhi, xlo, NN * DD);
    zeroEl_k<<<(NN * HH + 255) / 256, 256>>>(el0, er0, el1, er1, NN * HH);

    cudaEventRecord(ctx.fork1, 0);
    cudaStreamWaitEvent(s1, ctx.fork1, 0);
    cudaStreamWaitEvent(s2, ctx.fork1, 0);

    // CSR build (s1)
    zero_k<<<(NN + 255) / 256, 256, 0, s1>>>(deg0, deg1, NN);
    hist_k<<<(EE + 255) / 256, 256, 0, s1>>>(dst0, dst1, deg0, deg1);
    { dim3 g(NB, 2); scanA_k<<<g, 1024, 0, s1>>>(deg0, deg1, off0, off1, bsum); }
    scanB_k<<<1, 64, 0, s1>>>(bsum, off0, off1);
    { dim3 g(NB, 2); scanC_k<<<g, 1024, 0, s1>>>(bsum, off0, off1, pos0, pos1); }
    scat_k<<<(EE + 255) / 256, 256, 0, s1>>>(src0, dst0, src1, dst1, pos0, pos1, csr0, csr1);

    // weight conversions + layer-1 GEMM (attn fused into epilogue)
    convW_k<<<(512 * 128 + 255) / 256, 256>>>(W1_0, w1hi0, w1lo0, 128, 512);
    convW_k<<<(256 * 256 + 255) / 256, 256>>>(W2_0, w2hi0, w2lo0, 256, 256);
    convW_k<<<(512 * 128 + 255) / 256, 256, 0, s2>>>(W1_1, w1hi1, w1lo1, 128, 512);
    convW_k<<<(256 * 256 + 255) / 256, 256, 0, s2>>>(W2_1, w2hi1, w2lo1, 256, 256);

    { dim3 g(4, (NN + 127) / 128);
      gemm_mma_k<128, 256><<<g, 256>>>(xhi, xlo, w1hi0, w1lo0, feat0, NN, 512,
                                       al1_0, ar1_0, el0, er0);
      gemm_mma_k<128, 256><<<g, 256, 0, s2>>>(xhi, xlo, w1hi1, w1lo1, feat1, NN, 512,
                                              al1_1, ar1_1, el1, er1); }

    cudaEventRecord(ctx.join1a, s1);
    cudaEventRecord(ctx.join1b, s2);
    cudaStreamWaitEvent(0, ctx.join1a, 0);
    cudaStreamWaitEvent(0, ctx.join1b, 0);

    agg_k<256><<<NN, 128>>>(off0, csr0, off1, csr1, el0, er0, el1, er1,
                            feat0, feat1, b1_0, b1_1, nullptr, h1hi, h1lo, 1);

    // ---- layer 2 ----
    zeroEl_k<<<(NN * HH + 255) / 256, 256>>>(el0, er0, el1, er1, NN * HH);
    cudaEventRecord(ctx.fork2, 0);
    cudaStreamWaitEvent(s2, ctx.fork2, 0);
    { dim3 g(2, (NN + 127) / 128);
      gemm_mma_k<256, 128><<<g, 256>>>(h1hi, h1lo, w2hi0, w2lo0, feat0, NN, 256,
                                       al2_0, ar2_0, el0, er0);
      gemm_mma_k<256, 128><<<g, 256, 0, s2>>>(h1hi, h1lo, w2hi1, w2lo1, feat1, NN, 256,
                                              al2_1, ar2_1, el1, er1); }
    cudaEventRecord(ctx.join2, s2);
    cudaStreamWaitEvent(0, ctx.join2, 0);

    agg_k<128><<<NN, 128>>>(off0, csr0, off1, csr1, el0, er0, el1, er1,
                            feat0, feat1, b2_0, b2_1, out, nullptr, nullptr, 0);
}

// round 7
// speedup vs baseline: 2.6395x; 1.0252x over previous
#include <cuda_runtime.h>
#include <cuda_bf16.h>
#include <cuda_fp16.h>
#include <cstdint>
#include <math.h>

#define NN   20000
#define EE   320000
#define DD   128
#define HH   2
#define NB   ((NN + 1023) / 1024)

// ---------------- scratch (device globals) ------------------------------------
__device__ __align__(16) __half g_feat0[(size_t)NN * 512];
__device__ __align__(16) __half g_feat1[(size_t)NN * 512];
__device__ float g_el0[NN * 2], g_er0[NN * 2];
__device__ float g_el1[NN * 2], g_er1[NN * 2];
__device__ float g_el2[NN * 2], g_er2[NN * 2];
__device__ float g_el3[NN * 2], g_er3[NN * 2];
__device__ int   g_deg0[NN], g_deg1[NN];
__device__ int   g_off0[NN + 1], g_off1[NN + 1];
__device__ int   g_pos0[NN], g_pos1[NN];
__device__ int   g_csr0[EE], g_csr1[EE];
__device__ int   g_bsum[64];
__device__ __align__(16) __nv_bfloat16 g_xhi[(size_t)NN * DD],  g_xlo[(size_t)NN * DD];
__device__ __align__(16) __nv_bfloat16 g_h1hi[(size_t)NN * 256], g_h1lo[(size_t)NN * 256];
__device__ __align__(16) __nv_bfloat16 g_w1hi0[512 * 128], g_w1lo0[512 * 128];
__device__ __align__(16) __nv_bfloat16 g_w1hi1[512 * 128], g_w1lo1[512 * 128];
__device__ __align__(16) __nv_bfloat16 g_w2hi0[256 * 256], g_w2lo0[256 * 256];
__device__ __align__(16) __nv_bfloat16 g_w2hi1[256 * 256], g_w2lo1[256 * 256];

// ---------------- CSR build -----------------------------------------------------
__global__ void zero_k(int* a, int* b, int n) {
    int i = blockIdx.x * blockDim.x + threadIdx.x;
    if (i < n) { a[i] = 0; b[i] = 0; }
}
__global__ void zeroEl_k(float* el0, float* er0, float* el1, float* er1, int n) {
    int i = blockIdx.x * blockDim.x + threadIdx.x;
    if (i < n) { el0[i] = 0.f; er0[i] = 0.f; el1[i] = 0.f; er1[i] = 0.f; }
}
__global__ void hist_k(const int* __restrict__ dst0, const int* __restrict__ dst1,
                       int* deg0, int* deg1) {
    int i = blockIdx.x * blockDim.x + threadIdx.x;
    if (i < EE) {
        atomicAdd(&deg0[dst0[i]], 1);
        atomicAdd(&deg1[dst1[i]], 1);
    }
}
__global__ void scanA_k(const int* __restrict__ deg0, const int* __restrict__ deg1,
                        int* off0, int* off1, int* bsum) {
    const int* deg = blockIdx.y ? deg1 : deg0;
    int* off = blockIdx.y ? off1 : off0;
    int i = blockIdx.x * 1024 + threadIdx.x;
    int lane = threadIdx.x & 31, wid = threadIdx.x >> 5;
    int v = (i < NN) ? deg[i] : 0;
    int x = v;
    #pragma unroll
    for (int o = 1; o < 32; o <<= 1) {
        int t = __shfl_up_sync(0xffffffffu, x, o);
        if (lane >= o) x += t;
    }
    __shared__ int wsum[32];
    if (lane == 31) wsum[wid] = x;
    __syncthreads();
    if (wid == 0) {
        int w = wsum[lane];
        #pragma unroll
        for (int o = 1; o < 32; o <<= 1) {
            int t = __shfl_up_sync(0xffffffffu, w, o);
            if (lane >= o) w += t;
        }
        wsum[lane] = w;
    }
    __syncthreads();
    int inc = x + (wid ? wsum[wid - 1] : 0);
    if (i < NN) off[i] = inc - v;
    if (threadIdx.x == 1023) bsum[blockIdx.y * 32 + blockIdx.x] = inc;
}
__global__ void scanB_k(int* bsum, int* off0, int* off1) {
    int y = threadIdx.x >> 5, lane = threadIdx.x & 31;
    int v = (lane < NB) ? bsum[y * 32 + lane] : 0;
    int x = v;
    #pragma unroll
    for (int o = 1; o < 32; o <<= 1) {
        int t = __shfl_up_sync(0xffffffffu, x, o);
        if (lane >= o) x += t;
    }
    if (lane < NB) bsum[y * 32 + lane] = x - v;
    if (lane == NB - 1) { int* off = y ? off1 : off0; off[NN] = x; }
}
__global__ void scanC_k(const int* __restrict__ bsum, int* off0, int* off1,
                        int* pos0, int* pos1) {
    int i = blockIdx.x * 1024 + threadIdx.x;
    if (i >= NN) return;
    int y = blockIdx.y;
    int* off = y ? off1 : off0;
    int* pos = y ? pos1 : pos0;
    int val = off[i] + bsum[y * 32 + blockIdx.x];
    off[i] = val; pos[i] = val;
}
__global__ void scat_k(const int* __restrict__ src0, const int* __restrict__ dst0,
                       const int* __restrict__ src1, const int* __restrict__ dst1,
                       int* pos0, int* pos1, int* csr0, int* csr1) {
    int i = blockIdx.x * blockDim.x + threadIdx.x;
    if (i < EE) {
        csr0[atomicAdd(&pos0[dst0[i]], 1)] = src0[i];
        csr1[atomicAdd(&pos1[dst1[i]], 1)] = src1[i];
    }
}

// ---------------- split-bf16 conversion kernels --------------------------------
__global__ void convX_k(const float* __restrict__ x, __nv_bfloat16* hi,
                        __nv_bfloat16* lo, int n) {
    int i = blockIdx.x * blockDim.x + threadIdx.x;
    if (i < n) {
        float v = x[i];
        __nv_bfloat16 h = __float2bfloat16(v);
        hi[i] = h;
        lo[i] = __float2bfloat16(v - __bfloat162float(h));
    }
}
__global__ void convW_k(const float* __restrict__ W, __nv_bfloat16* hi,
                        __nv_bfloat16* lo, int K, int Nd) {
    int i = blockIdx.x * blockDim.x + threadIdx.x;
    if (i >= K * Nd) return;
    int n = i / K, k = i % K;
    float v = W[(size_t)k * Nd + n];
    __nv_bfloat16 h = __float2bfloat16(v);
    hi[i] = h;
    lo[i] = __float2bfloat16(v - __bfloat162float(h));
}

// ---------------- mma.sync helpers ---------------------------------------------
__device__ __forceinline__ uint32_t smem_u32(const void* p) {
    uint32_t a;
    asm("{ .reg .u64 t; cvta.to.shared.u64 t, %1; cvt.u32.u64 %0, t; }" : "=r"(a) : "l"(p));
    return a;
}
__device__ __forceinline__ void ldsm_x4(uint32_t* r, uint32_t addr) {
    asm volatile("ldmatrix.sync.aligned.m8n8.x4.shared.b16 {%0,%1,%2,%3}, [%4];"
                 : "=r"(r[0]), "=r"(r[1]), "=r"(r[2]), "=r"(r[3]) : "r"(addr));
}
__device__ __forceinline__ void ldsm_x2(uint32_t* r, uint32_t addr) {
    asm volatile("ldmatrix.sync.aligned.m8n8.x2.shared.b16 {%0,%1}, [%2];"
                 : "=r"(r[0]), "=r"(r[1]) : "r"(addr));
}
__device__ __forceinline__ void mma_bf16(float* d, const uint32_t* a, const uint32_t* b) {
    asm volatile(
        "mma.sync.aligned.m16n8k16.row.col.f32.bf16.bf16.f32 "
        "{%0,%1,%2,%3}, {%4,%5,%6,%7}, {%8,%9}, {%0,%1,%2,%3};"
        : "+f"(d[0]), "+f"(d[1]), "+f"(d[2]), "+f"(d[3])
        : "r"(a[0]), "r"(a[1]), "r"(a[2]), "r"(a[3]), "r"(b[0]), "r"(b[1]));
}

// ---------------- tensor-core split-bf16 GEMM + fused attn epilogue ------------
// C[M,Nd] = A[M,KTOT]*B[Nd,KTOT]^T, fp16 output; el/er accumulated via atomics.
#define SSTR 40
__device__ __forceinline__ void load_chunk(const __nv_bfloat16* __restrict__ g,
        int ld, int rbase, int kofs, __nv_bfloat16* s, int rlim, int tid) {
    #pragma unroll
    for (int i = 0; i < 2; i++) {
        int id = tid + i * 256;
        int r = id >> 2;
        int c = (id & 3) * 8;
        uint4 v = make_uint4(0u, 0u, 0u, 0u);
        int gr = rbase + r;
        if (gr < rlim)
            v = *(const uint4*)(g + (size_t)gr * ld + kofs + c);
        *(uint4*)(s + r * SSTR + c) = v;
    }
}

template<int KTOT, int O>
__global__ void __launch_bounds__(256) gemm_mma_k(
        const __nv_bfloat16* __restrict__ Ahi, const __nv_bfloat16* __restrict__ Alo,
        const __nv_bfloat16* __restrict__ Bhi, const __nv_bfloat16* __restrict__ Blo,
        __half* __restrict__ C, int M, int Nd,
        const float* __restrict__ al, const float* __restrict__ ar,
        float* __restrict__ el, float* __restrict__ er) {
    __shared__ __align__(16) __nv_bfloat16 sAhi[128 * SSTR];
    __shared__ __align__(16) __nv_bfloat16 sAlo[128 * SSTR];
    __shared__ __align__(16) __nv_bfloat16 sBhi[128 * SSTR];
    __shared__ __align__(16) __nv_bfloat16 sBlo[128 * SSTR];
    const int tid = threadIdx.x;
    const int w = tid >> 5;
    const int lane = tid & 31;
    const int rowBase = blockIdx.y * 128;
    const int colBase = blockIdx.x * 128;
    const int wRow = w >> 2;
    const int wCol = w & 3;

    uint32_t aBaseHi = smem_u32(sAhi), aBaseLo = smem_u32(sAlo);
    uint32_t bBaseHi = smem_u32(sBhi), bBaseLo = smem_u32(sBlo);

    float d[4][4][4];
    #pragma unroll
    for (int i = 0; i < 4; i++)
        #pragma unroll
        for (int j = 0; j < 4; j++)
            #pragma unroll
            for (int q = 0; q < 4; q++) d[i][j][q] = 0.f;

    constexpr int NKC = KTOT / 32;
    for (int kc = 0; kc < NKC; kc++) {
        load_chunk(Ahi, KTOT, rowBase, kc * 32, sAhi, M, tid);
        load_chunk(Alo, KTOT, rowBase, kc * 32, sAlo, M, tid);
        load_chunk(Bhi, KTOT, colBase, kc * 32, sBhi, 1 << 30, tid);
        load_chunk(Blo, KTOT, colBase, kc * 32, sBlo, 1 << 30, tid);
        __syncthreads();
        #pragma unroll
        for (int ks = 0; ks < 32; ks += 16) {
            uint32_t bhi[4][2], blo[4][2];
            {
                int brow = (lane & 7);
                int bcol = ks + ((lane >> 3) & 1) * 8;
                #pragma unroll
                for (int nt = 0; nt < 4; nt++) {
                    uint32_t off = (uint32_t)(((wCol * 32 + nt * 8 + brow) * SSTR + bcol) * 2);
                    ldsm_x2(bhi[nt], bBaseHi + off);
                    ldsm_x2(blo[nt], bBaseLo + off);
                }
            }
            int arow = (lane & 15);
            int acol = ks + (lane >> 4) * 8;
            #pragma unroll
            for (int mt = 0; mt < 4; mt++) {
                uint32_t ahi[4], alo[4];
                uint32_t off = (uint32_t)(((wRow * 64 + mt * 16 + arow) * SSTR + acol) * 2);
                ldsm_x4(ahi, aBaseHi + off);
                ldsm_x4(alo, aBaseLo + off);
                #pragma unroll
                for (int nt = 0; nt < 4; nt++) {
                    mma_bf16(d[mt][nt], ahi, bhi[nt]);
                    mma_bf16(d[mt][nt], ahi, blo[nt]);
                    mma_bf16(d[mt][nt], alo, bhi[nt]);
                }
            }
        }
        __syncthreads();
    }

    // ---- epilogue: fp16 C write + fused attn partial dot products ----
    int mlocal = lane >> 2;
    int nlocal = (lane & 3) * 2;
    float alv[4][2], arv[4][2];
    int head;
    {
        int c0 = colBase + wCol * 32 + nlocal;
        head = c0 / O;                              // 32-col warp tile never straddles heads
        #pragma unroll
        for (int nt = 0; nt < 4; nt++) {
            int c = c0 + nt * 8 - head * O;
            alv[nt][0] = al[head * O + c]; alv[nt][1] = al[head * O + c + 1];
            arv[nt][0] = ar[head * O + c]; arv[nt][1] = ar[head * O + c + 1];
        }
    }
    #pragma unroll
    for (int mt = 0; mt < 4; mt++) {
        int row = rowBase + wRow * 64 + mt * 16 + mlocal;
        float pel0 = 0.f, per0 = 0.f, pel8 = 0.f, per8 = 0.f;
        #pragma unroll
        for (int nt = 0; nt < 4; nt++) {
            int col = colBase + wCol * 32 + nt * 8 + nlocal;
            if (row < M)
                *(__half2*)&C[(size_t)row * Nd + col] =
                    __floats2half2_rn(d[mt][nt][0], d[mt][nt][1]);
            if (row + 8 < M)
                *(__half2*)&C[(size_t)(row + 8) * Nd + col] =
                    __floats2half2_rn(d[mt][nt][2], d[mt][nt][3]);
            pel0 += d[mt][nt][0] * alv[nt][0] + d[mt][nt][1] * alv[nt][1];
            per0 += d[mt][nt][0] * arv[nt][0] + d[mt][nt][1] * arv[nt][1];
            pel8 += d[mt][nt][2] * alv[nt][0] + d[mt][nt][3] * alv[nt][1];
            per8 += d[mt][nt][2] * arv[nt][0] + d[mt][nt][3] * arv[nt][1];
        }
        #pragma unroll
        for (int o = 1; o < 4; o <<= 1) {
            pel0 += __shfl_xor_sync(0xffffffffu, pel0, o);
            per0 += __shfl_xor_sync(0xffffffffu, per0, o);
            pel8 += __shfl_xor_sync(0xffffffffu, pel8, o);
            per8 += __shfl_xor_sync(0xffffffffu, per8, o);
        }
        if ((lane & 3) == 0) {
            if (row < M) {
                atomicAdd(&el[row * HH + head], pel0);
                atomicAdd(&er[row * HH + head], per0);
            }
            if (row + 8 < M) {
                atomicAdd(&el[(row + 8) * HH + head], pel8);
                atomicAdd(&er[(row + 8) * HH + head], per8);
            }
        }
    }
}

// ---------------- fused softmax + aggregation + epilogue ----------------------
template<int O>
__global__ void __launch_bounds__(128) agg_k(
        const int* __restrict__ off0, const int* __restrict__ csr0,
        const int* __restrict__ off1, const int* __restrict__ csr1,
        const float* __restrict__ el0, const float* __restrict__ er0,
        const float* __restrict__ el1, const float* __restrict__ er1,
        const __half* __restrict__ feat0, const __half* __restrict__ feat1,
        const float* __restrict__ b0, const float* __restrict__ b1,
        float* __restrict__ out, __nv_bfloat16* __restrict__ outHi,
        __nv_bfloat16* __restrict__ outLo, int do_relu) {
    constexpr int WIDTH = 2 * O;
    constexpr int NV = WIDTH / 128;     // halves per thread (4 or 2)
    constexpr int CAP = 512;
    __shared__ float2 s_exp[CAP];
    __shared__ float2 s_wred[4];
    __shared__ float  s_out[WIDTH];
    int n = blockIdx.x;
    int tid = threadIdx.x;
    int lane = tid & 31, wid = tid >> 5;
    int head = tid >> 6;
    float acc[NV];
    #pragma unroll
    for (int j = 0; j < NV; j++) acc[j] = 0.f;

    #pragma unroll
    for (int rel = 0; rel < 2; rel++) {
        const int* off = rel ? off1 : off0;
        const int* csr = rel ? csr1 : csr0;
        const float* el = rel ? el1 : el0;
        const float* er = rel ? er1 : er0;
        const __half* feat = rel ? feat1 : feat0;
        int beg = off[n];
        int deg = off[n + 1] - beg;
        float ern0 = er[n * 2 + 0], ern1 = er[n * 2 + 1];
        __syncthreads();
        float d0 = 0.f, d1 = 0.f;
        for (int i = tid; i < deg; i += 128) {
            int s = csr[beg + i];
            float v0 = el[s * 2 + 0] + ern0;
            float v1 = el[s * 2 + 1] + ern1;
            v0 = v0 > 0.f ? v0 : 0.2f * v0;
            v1 = v1 > 0.f ? v1 : 0.2f * v1;
            v0 = __expf(v0);
            v1 = __expf(v1);
            if (i < CAP) s_exp[i] = make_float2(v0, v1);
            d0 += v0; d1 += v1;
        }
        #pragma unroll
        for (int o = 16; o; o >>= 1) {
            d0 += __shfl_xor_sync(0xffffffffu, d0, o);
            d1 += __shfl_xor_sync(0xffffffffu, d1, o);
        }
        if (lane == 0) s_wred[wid] = make_float2(d0, d1);
        __syncthreads();
        float t0 = s_wred[0].x + s_wred[1].x + s_wred[2].x + s_wred[3].x;
        float t1 = s_wred[0].y + s_wred[1].y + s_wred[2].y + s_wred[3].y;
        float inv0 = 1.f / fmaxf(t0, 1e-9f);
        float inv1 = 1.f / fmaxf(t1, 1e-9f);
        float inv = head ? inv1 : inv0;
        #pragma unroll 4
        for (int i = 0; i < deg; i++) {
            int s = csr[beg + i];
            float a;
            if (i < CAP) {
                float2 ev = s_exp[i];
                a = (head ? ev.y : ev.x) * inv;
            } else {
                float v = el[s * 2 + head] + (head ? ern1 : ern0);
                v = v > 0.f ? v : 0.2f * v;
                a = __expf(v) * inv;
            }
            const __half* fp = feat + (size_t)s * WIDTH + tid * NV;
            if (NV == 4) {
                uint2 raw = *(const uint2*)fp;
                float2 f0 = __half22float2(*(__half2*)&raw.x);
                float2 f1 = __half22float2(*(__half2*)&raw.y);
                acc[0] += a * f0.x; acc[1] += a * f0.y;
                acc[2] += a * f1.x; acc[3] += a * f1.y;
            } else {
                uint32_t raw = *(const uint32_t*)fp;
                float2 f0 = __half22float2(*(__half2*)&raw);
                acc[0] += a * f0.x; acc[1] += a * f0.y;
            }
        }
    }
    #pragma unroll
    for (int j = 0; j < NV; j++) s_out[tid * NV + j] = acc[j];
    __syncthreads();
    for (int j = tid; j < O; j += 128) {
        float v = s_out[j] + s_out[j + O]
                + b0[j] + b0[j + O] + b1[j] + b1[j + O];
        v *= 0.5f;
        if (do_relu) v = fmaxf(v, 0.f);
        if (outHi) {
            __nv_bfloat16 h = __float2bfloat16(v);
            outHi[(size_t)n * O + j] = h;
            outLo[(size_t)n * O + j] = __float2bfloat16(v - __bfloat162float(h));
        } else {
            out[(size_t)n * O + j] = v;
        }
    }
}

// ---------------- host launch ---------------------------------------------------
static float* symf(const void* s) { void* p = nullptr; cudaGetSymbolAddress(&p, s); return (float*)p; }
static int*   symi(const void* s) { void* p = nullptr; cudaGetSymbolAddress(&p, s); return (int*)p; }
static __half* symh(const void* s) { void* p = nullptr; cudaGetSymbolAddress(&p, s); return (__half*)p; }
static __nv_bfloat16* symb(const void* s) { void* p = nullptr; cudaGetSymbolAddress(&p, s); return (__nv_bfloat16*)p; }

struct Ctx {
    cudaStream_t s1, s2;
    cudaEvent_t fork1, join1a, join1b, fork2, join2;
    Ctx() {
        cudaStreamCreateWithFlags(&s1, cudaStreamNonBlocking);
        cudaStreamCreateWithFlags(&s2, cudaStreamNonBlocking);
        cudaEventCreateWithFlags(&fork1,  cudaEventDisableTiming);
        cudaEventCreateWithFlags(&join1a, cudaEventDisableTiming);
        cudaEventCreateWithFlags(&join1b, cudaEventDisableTiming);
        cudaEventCreateWithFlags(&fork2,  cudaEventDisableTiming);
        cudaEventCreateWithFlags(&join2,  cudaEventDisableTiming);
    }
};

extern "C" void kernel_launch(void* const* d_in, const int* in_sizes, int n_in,
                              void* d_out, int out_size) {
    static Ctx ctx;
    const float* x     = (const float*)d_in[0];
    const int*   src0  = (const int*)d_in[1];
    const int*   dst0  = (const int*)d_in[2];
    const int*   src1  = (const int*)d_in[3];
    const int*   dst1  = (const int*)d_in[4];
    const float* W1_0  = (const float*)d_in[5];
    const float* al1_0 = (const float*)d_in[6];
    const float* ar1_0 = (const float*)d_in[7];
    const float* b1_0  = (const float*)d_in[8];
    const float* W1_1  = (const float*)d_in[9];
    const float* al1_1 = (const float*)d_in[10];
    const float* ar1_1 = (const float*)d_in[11];
    const float* b1_1  = (const float*)d_in[12];
    const float* W2_0  = (const float*)d_in[13];
    const float* al2_0 = (const float*)d_in[14];
    const float* ar2_0 = (const float*)d_in[15];
    const float* b2_0  = (const float*)d_in[16];
    const float* W2_1  = (const float*)d_in[17];
    const float* al2_1 = (const float*)d_in[18];
    const float* ar2_1 = (const float*)d_in[19];
    const float* b2_1  = (const float*)d_in[20];
    float* out = (float*)d_out;

    __half* feat0 = symh(g_feat0);
    __half* feat1 = symh(g_feat1);
    float* el0 = symf(g_el0); float* er0 = symf(g_er0);
    float* el1 = symf(g_el1); float* er1 = symf(g_er1);
    float* el2 = symf(g_el2); float* er2 = symf(g_er2);
    float* el3 = symf(g_el3); float* er3 = symf(g_er3);
    int* deg0 = symi(g_deg0); int* deg1 = symi(g_deg1);
    int* off0 = symi(g_off0); int* off1 = symi(g_off1);
    int* pos0 = symi(g_pos0); int* pos1 = symi(g_pos1);
    int* csr0 = symi(g_csr0); int* csr1 = symi(g_csr1);
    int* bsum = symi(g_bsum);
    __nv_bfloat16* xhi = symb(g_xhi);   __nv_bfloat16* xlo = symb(g_xlo);
    __nv_bfloat16* h1hi = symb(g_h1hi); __nv_bfloat16* h1lo = symb(g_h1lo);
    __nv_bfloat16* w1hi0 = symb(g_w1hi0); __nv_bfloat16* w1lo0 = symb(g_w1lo0);
    __nv_bfloat16* w1hi1 = symb(g_w1hi1); __nv_bfloat16* w1lo1 = symb(g_w1lo1);
    __nv_bfloat16* w2hi0 = symb(g_w2hi0); __nv_bfloat16* w2lo0 = symb(g_w2lo0);
    __nv_bfloat16* w2hi1 = symb(g_w2hi1); __nv_bfloat16* w2lo1 = symb(g_w2lo1);

    cudaStream_t s1 = ctx.s1, s2 = ctx.s2;

    // pre-fork: convert x; zero layer-1 el/er (layer-2 set zeroed off-path on s1)
    convX_k<<<(NN * DD + 255) / 256, 256>>>(x, xhi, xlo, NN * DD);
    zeroEl_k<<<(NN * HH + 255) / 256, 256>>>(el0, er0, el1, er1, NN * HH);

    cudaEventRecord(ctx.fork1, 0);
    cudaStreamWaitEvent(s1, ctx.fork1, 0);
    cudaStreamWaitEvent(s2, ctx.fork1, 0);

    // CSR build + layer-2 el/er zero (s1, off critical path)
    zeroEl_k<<<(NN * HH + 255) / 256, 256, 0, s1>>>(el2, er2, el3, er3, NN * HH);
    zero_k<<<(NN + 255) / 256, 256, 0, s1>>>(deg0, deg1, NN);
    hist_k<<<(EE + 255) / 256, 256, 0, s1>>>(dst0, dst1, deg0, deg1);
    { dim3 g(NB, 2); scanA_k<<<g, 1024, 0, s1>>>(deg0, deg1, off0, off1, bsum); }
    scanB_k<<<1, 64, 0, s1>>>(bsum, off0, off1);
    { dim3 g(NB, 2); scanC_k<<<g, 1024, 0, s1>>>(bsum, off0, off1, pos0, pos1); }
    scat_k<<<(EE + 255) / 256, 256, 0, s1>>>(src0, dst0, src1, dst1, pos0, pos1, csr0, csr1);

    // weight conversions + layer-1 GEMM (attn fused into epilogue)
    convW_k<<<(512 * 128 + 255) / 256, 256>>>(W1_0, w1hi0, w1lo0, 128, 512);
    convW_k<<<(256 * 256 + 255) / 256, 256>>>(W2_0, w2hi0, w2lo0, 256, 256);
    convW_k<<<(512 * 128 + 255) / 256, 256, 0, s2>>>(W1_1, w1hi1, w1lo1, 128, 512);
    convW_k<<<(256 * 256 + 255) / 256, 256, 0, s2>>>(W2_1, w2hi1, w2lo1, 256, 256);

    { dim3 g(4, (NN + 127) / 128);
      gemm_mma_k<128, 256><<<g, 256>>>(xhi, xlo, w1hi0, w1lo0, feat0, NN, 512,
                                       al1_0, ar1_0, el0, er0);
      gemm_mma_k<128, 256><<<g, 256, 0, s2>>>(xhi, xlo, w1hi1, w1lo1, feat1, NN, 512,
                                              al1_1, ar1_1, el1, er1); }

    cudaEventRecord(ctx.join1a, s1);
    cudaEventRecord(ctx.join1b, s2);
    cudaStreamWaitEvent(0, ctx.join1a, 0);
    cudaStreamWaitEvent(0, ctx.join1b, 0);

    agg_k<256><<<NN, 128>>>(off0, csr0, off1, csr1, el0, er0, el1, er1,
                            feat0, feat1, b1_0, b1_1, nullptr, h1hi, h1lo, 1);

    // ---- layer 2 (uses el2/er2, el3/er3 — already zeroed on s1) ----
    cudaEventRecord(ctx.fork2, 0);
    cudaStreamWaitEvent(s2, ctx.fork2, 0);
    { dim3 g(2, (NN + 127) / 128);
      gemm_mma_k<256, 128><<<g, 256>>>(h1hi, h1lo, w2hi0, w2lo0, feat0, NN, 256,
                                       al2_0, ar2_0, el2, er2);
      gemm_mma_k<256, 128><<<g, 256, 0, s2>>>(h1hi, h1lo, w2hi1, w2lo1, feat1, NN, 256,
                                              al2_1, ar2_1, el3, er3); }
    cudaEventRecord(ctx.join2, s2);
    cudaStreamWaitEvent(0, ctx.join2, 0);

    agg_k<128><<<NN, 128>>>(off0, csr0, off1, csr1, el2, er2, el3, er3,
                            feat0, feat1, b2_0, b2_1, out, nullptr, nullptr, 0);
}

// round 8
// speedup vs baseline: 2.7981x; 1.0601x over previous
#include <cuda_runtime.h>
#include <cuda_bf16.h>
#include <cuda_fp16.h>
#include <cstdint>
#include <math.h>

#define NN   20000
#define EE   320000
#define DD   128
#define HH   2
#define NB   ((NN + 1023) / 1024)

// ---------------- scratch (device globals) ------------------------------------
__device__ __align__(16) __half g_feat0[(size_t)NN * 512];
__device__ __align__(16) __half g_feat1[(size_t)NN * 512];
__device__ float g_el0[NN * 2], g_er0[NN * 2];
__device__ float g_el1[NN * 2], g_er1[NN * 2];
__device__ float g_el2[NN * 2], g_er2[NN * 2];
__device__ float g_el3[NN * 2], g_er3[NN * 2];
__device__ int   g_deg0[NN], g_deg1[NN];
__device__ int   g_off0[NN + 1], g_off1[NN + 1];
__device__ int   g_pos0[NN], g_pos1[NN];
__device__ int   g_csr0[EE], g_csr1[EE];
__device__ int   g_bsum[64];
__device__ __align__(16) __nv_bfloat16 g_xhi[(size_t)NN * DD],  g_xlo[(size_t)NN * DD];
__device__ __align__(16) __nv_bfloat16 g_h1hi[(size_t)NN * 256], g_h1lo[(size_t)NN * 256];
__device__ __align__(16) __nv_bfloat16 g_w1hi0[512 * 128], g_w1lo0[512 * 128];
__device__ __align__(16) __nv_bfloat16 g_w1hi1[512 * 128], g_w1lo1[512 * 128];
__device__ __align__(16) __nv_bfloat16 g_w2hi0[256 * 256], g_w2lo0[256 * 256];
__device__ __align__(16) __nv_bfloat16 g_w2hi1[256 * 256], g_w2lo1[256 * 256];

// ---------------- CSR build -----------------------------------------------------
__global__ void zero_k(int* a, int* b, int n) {
    int i = blockIdx.x * blockDim.x + threadIdx.x;
    if (i < n) { a[i] = 0; b[i] = 0; }
}
__global__ void zeroEl_k(float* el0, float* er0, float* el1, float* er1, int n) {
    int i = blockIdx.x * blockDim.x + threadIdx.x;
    if (i < n) { el0[i] = 0.f; er0[i] = 0.f; el1[i] = 0.f; er1[i] = 0.f; }
}
__global__ void hist_k(const int* __restrict__ dst0, const int* __restrict__ dst1,
                       int* deg0, int* deg1) {
    int i = blockIdx.x * blockDim.x + threadIdx.x;
    if (i < EE) {
        atomicAdd(&deg0[dst0[i]], 1);
        atomicAdd(&deg1[dst1[i]], 1);
    }
}
__global__ void scanA_k(const int* __restrict__ deg0, const int* __restrict__ deg1,
                        int* off0, int* off1, int* bsum) {
    const int* deg = blockIdx.y ? deg1 : deg0;
    int* off = blockIdx.y ? off1 : off0;
    int i = blockIdx.x * 1024 + threadIdx.x;
    int lane = threadIdx.x & 31, wid = threadIdx.x >> 5;
    int v = (i < NN) ? deg[i] : 0;
    int x = v;
    #pragma unroll
    for (int o = 1; o < 32; o <<= 1) {
        int t = __shfl_up_sync(0xffffffffu, x, o);
        if (lane >= o) x += t;
    }
    __shared__ int wsum[32];
    if (lane == 31) wsum[wid] = x;
    __syncthreads();
    if (wid == 0) {
        int w = wsum[lane];
        #pragma unroll
        for (int o = 1; o < 32; o <<= 1) {
            int t = __shfl_up_sync(0xffffffffu, w, o);
            if (lane >= o) w += t;
        }
        wsum[lane] = w;
    }
    __syncthreads();
    int inc = x + (wid ? wsum[wid - 1] : 0);
    if (i < NN) off[i] = inc - v;
    if (threadIdx.x == 1023) bsum[blockIdx.y * 32 + blockIdx.x] = inc;
}
__global__ void scanB_k(int* bsum, int* off0, int* off1) {
    int y = threadIdx.x >> 5, lane = threadIdx.x & 31;
    int v = (lane < NB) ? bsum[y * 32 + lane] : 0;
    int x = v;
    #pragma unroll
    for (int o = 1; o < 32; o <<= 1) {
        int t = __shfl_up_sync(0xffffffffu, x, o);
        if (lane >= o) x += t;
    }
    if (lane < NB) bsum[y * 32 + lane] = x - v;
    if (lane == NB - 1) { int* off = y ? off1 : off0; off[NN] = x; }
}
__global__ void scanC_k(const int* __restrict__ bsum, int* off0, int* off1,
                        int* pos0, int* pos1) {
    int i = blockIdx.x * 1024 + threadIdx.x;
    if (i >= NN) return;
    int y = blockIdx.y;
    int* off = y ? off1 : off0;
    int* pos = y ? pos1 : pos0;
    int val = off[i] + bsum[y * 32 + blockIdx.x];
    off[i] = val; pos[i] = val;
}
__global__ void scat_k(const int* __restrict__ src0, const int* __restrict__ dst0,
                       const int* __restrict__ src1, const int* __restrict__ dst1,
                       int* pos0, int* pos1, int* csr0, int* csr1) {
    int i = blockIdx.x * blockDim.x + threadIdx.x;
    if (i < EE) {
        csr0[atomicAdd(&pos0[dst0[i]], 1)] = src0[i];
        csr1[atomicAdd(&pos1[dst1[i]], 1)] = src1[i];
    }
}

// ---------------- split-bf16 conversion kernels --------------------------------
__global__ void convX_k(const float* __restrict__ x, __nv_bfloat16* hi,
                        __nv_bfloat16* lo, int n) {
    int i = blockIdx.x * blockDim.x + threadIdx.x;
    if (i < n) {
        float v = x[i];
        __nv_bfloat16 h = __float2bfloat16(v);
        hi[i] = h;
        lo[i] = __float2bfloat16(v - __bfloat162float(h));
    }
}
__global__ void convW_k(const float* __restrict__ W, __nv_bfloat16* hi,
                        __nv_bfloat16* lo, int K, int Nd) {
    int i = blockIdx.x * blockDim.x + threadIdx.x;
    if (i >= K * Nd) return;
    int n = i / K, k = i % K;
    float v = W[(size_t)k * Nd + n];
    __nv_bfloat16 h = __float2bfloat16(v);
    hi[i] = h;
    lo[i] = __float2bfloat16(v - __bfloat162float(h));
}

// ---------------- mma.sync helpers ---------------------------------------------
__device__ __forceinline__ uint32_t smem_u32(const void* p) {
    uint32_t a;
    asm("{ .reg .u64 t; cvta.to.shared.u64 t, %1; cvt.u32.u64 %0, t; }" : "=r"(a) : "l"(p));
    return a;
}
__device__ __forceinline__ void ldsm_x4(uint32_t* r, uint32_t addr) {
    asm volatile("ldmatrix.sync.aligned.m8n8.x4.shared.b16 {%0,%1,%2,%3}, [%4];"
                 : "=r"(r[0]), "=r"(r[1]), "=r"(r[2]), "=r"(r[3]) : "r"(addr));
}
__device__ __forceinline__ void ldsm_x2(uint32_t* r, uint32_t addr) {
    asm volatile("ldmatrix.sync.aligned.m8n8.x2.shared.b16 {%0,%1}, [%2];"
                 : "=r"(r[0]), "=r"(r[1]) : "r"(addr));
}
__device__ __forceinline__ void mma_bf16(float* d, const uint32_t* a, const uint32_t* b) {
    asm volatile(
        "mma.sync.aligned.m16n8k16.row.col.f32.bf16.bf16.f32 "
        "{%0,%1,%2,%3}, {%4,%5,%6,%7}, {%8,%9}, {%0,%1,%2,%3};"
        : "+f"(d[0]), "+f"(d[1]), "+f"(d[2]), "+f"(d[3])
        : "r"(a[0]), "r"(a[1]), "r"(a[2]), "r"(a[3]), "r"(b[0]), "r"(b[1]));
}

// ---------------- tensor-core split-bf16 GEMM + fused attn epilogue ------------
#define SSTR 40
__device__ __forceinline__ void load_chunk(const __nv_bfloat16* __restrict__ g,
        int ld, int rbase, int kofs, __nv_bfloat16* s, int rlim, int tid) {
    #pragma unroll
    for (int i = 0; i < 2; i++) {
        int id = tid + i * 256;
        int r = id >> 2;
        int c = (id & 3) * 8;
        uint4 v = make_uint4(0u, 0u, 0u, 0u);
        int gr = rbase + r;
        if (gr < rlim)
            v = *(const uint4*)(g + (size_t)gr * ld + kofs + c);
        *(uint4*)(s + r * SSTR + c) = v;
    }
}

template<int KTOT, int O>
__global__ void __launch_bounds__(256) gemm_mma_k(
        const __nv_bfloat16* __restrict__ Ahi, const __nv_bfloat16* __restrict__ Alo,
        const __nv_bfloat16* __restrict__ Bhi, const __nv_bfloat16* __restrict__ Blo,
        __half* __restrict__ C, int M, int Nd,
        const float* __restrict__ al, const float* __restrict__ ar,
        float* __restrict__ el, float* __restrict__ er) {
    __shared__ __align__(16) __nv_bfloat16 sAhi[128 * SSTR];
    __shared__ __align__(16) __nv_bfloat16 sAlo[128 * SSTR];
    __shared__ __align__(16) __nv_bfloat16 sBhi[128 * SSTR];
    __shared__ __align__(16) __nv_bfloat16 sBlo[128 * SSTR];
    const int tid = threadIdx.x;
    const int w = tid >> 5;
    const int lane = tid & 31;
    const int rowBase = blockIdx.y * 128;
    const int colBase = blockIdx.x * 128;
    const int wRow = w >> 2;
    const int wCol = w & 3;

    uint32_t aBaseHi = smem_u32(sAhi), aBaseLo = smem_u32(sAlo);
    uint32_t bBaseHi = smem_u32(sBhi), bBaseLo = smem_u32(sBlo);

    float d[4][4][4];
    #pragma unroll
    for (int i = 0; i < 4; i++)
        #pragma unroll
        for (int j = 0; j < 4; j++)
            #pragma unroll
            for (int q = 0; q < 4; q++) d[i][j][q] = 0.f;

    constexpr int NKC = KTOT / 32;
    for (int kc = 0; kc < NKC; kc++) {
        load_chunk(Ahi, KTOT, rowBase, kc * 32, sAhi, M, tid);
        load_chunk(Alo, KTOT, rowBase, kc * 32, sAlo, M, tid);
        load_chunk(Bhi, KTOT, colBase, kc * 32, sBhi, 1 << 30, tid);
        load_chunk(Blo, KTOT, colBase, kc * 32, sBlo, 1 << 30, tid);
        __syncthreads();
        #pragma unroll
        for (int ks = 0; ks < 32; ks += 16) {
            uint32_t bhi[4][2], blo[4][2];
            {
                int brow = (lane & 7);
                int bcol = ks + ((lane >> 3) & 1) * 8;
                #pragma unroll
                for (int nt = 0; nt < 4; nt++) {
                    uint32_t off = (uint32_t)(((wCol * 32 + nt * 8 + brow) * SSTR + bcol) * 2);
                    ldsm_x2(bhi[nt], bBaseHi + off);
                    ldsm_x2(blo[nt], bBaseLo + off);
                }
            }
            int arow = (lane & 15);
            int acol = ks + (lane >> 4) * 8;
            #pragma unroll
            for (int mt = 0; mt < 4; mt++) {
                uint32_t ahi[4], alo[4];
                uint32_t off = (uint32_t)(((wRow * 64 + mt * 16 + arow) * SSTR + acol) * 2);
                ldsm_x4(ahi, aBaseHi + off);
                ldsm_x4(alo, aBaseLo + off);
                #pragma unroll
                for (int nt = 0; nt < 4; nt++) {
                    mma_bf16(d[mt][nt], ahi, bhi[nt]);
                    mma_bf16(d[mt][nt], ahi, blo[nt]);
                    mma_bf16(d[mt][nt], alo, bhi[nt]);
                }
            }
        }
        __syncthreads();
    }

    // ---- epilogue: fp16 C write + fused attn partial dot products ----
    int mlocal = lane >> 2;
    int nlocal = (lane & 3) * 2;
    float alv[4][2], arv[4][2];
    int head;
    {
        int c0 = colBase + wCol * 32 + nlocal;
        head = c0 / O;
        #pragma unroll
        for (int nt = 0; nt < 4; nt++) {
            int c = c0 + nt * 8 - head * O;
            alv[nt][0] = al[head * O + c]; alv[nt][1] = al[head * O + c + 1];
            arv[nt][0] = ar[head * O + c]; arv[nt][1] = ar[head * O + c + 1];
        }
    }
    #pragma unroll
    for (int mt = 0; mt < 4; mt++) {
        int row = rowBase + wRow * 64 + mt * 16 + mlocal;
        float pel0 = 0.f, per0 = 0.f, pel8 = 0.f, per8 = 0.f;
        #pragma unroll
        for (int nt = 0; nt < 4; nt++) {
            int col = colBase + wCol * 32 + nt * 8 + nlocal;
            if (row < M)
                *(__half2*)&C[(size_t)row * Nd + col] =
                    __floats2half2_rn(d[mt][nt][0], d[mt][nt][1]);
            if (row + 8 < M)
                *(__half2*)&C[(size_t)(row + 8) * Nd + col] =
                    __floats2half2_rn(d[mt][nt][2], d[mt][nt][3]);
            pel0 += d[mt][nt][0] * alv[nt][0] + d[mt][nt][1] * alv[nt][1];
            per0 += d[mt][nt][0] * arv[nt][0] + d[mt][nt][1] * arv[nt][1];
            pel8 += d[mt][nt][2] * alv[nt][0] + d[mt][nt][3] * alv[nt][1];
            per8 += d[mt][nt][2] * arv[nt][0] + d[mt][nt][3] * arv[nt][1];
        }
        #pragma unroll
        for (int o = 1; o < 4; o <<= 1) {
            pel0 += __shfl_xor_sync(0xffffffffu, pel0, o);
            per0 += __shfl_xor_sync(0xffffffffu, per0, o);
            pel8 += __shfl_xor_sync(0xffffffffu, pel8, o);
            per8 += __shfl_xor_sync(0xffffffffu, per8, o);
        }
        if ((lane & 3) == 0) {
            if (row < M) {
                atomicAdd(&el[row * HH + head], pel0);
                atomicAdd(&er[row * HH + head], per0);
            }
            if (row + 8 < M) {
                atomicAdd(&el[(row + 8) * HH + head], pel8);
                atomicAdd(&er[(row + 8) * HH + head], per8);
            }
        }
    }
}

// ---------------- warp-per-node softmax + aggregation + epilogue ---------------
// One warp per dst node; no __syncthreads, no smem. Lane covers NV halves of the
// [WIDTH] feature row; lanes 0-15 are head 0, 16-31 head 1. Mean-over-heads via
// shfl_down(16) in the epilogue.
template<int O>
__global__ void __launch_bounds__(256) aggw_k(
        const int* __restrict__ off0, const int* __restrict__ csr0,
        const int* __restrict__ off1, const int* __restrict__ csr1,
        const float* __restrict__ el0, const float* __restrict__ er0,
        const float* __restrict__ el1, const float* __restrict__ er1,
        const __half* __restrict__ feat0, const __half* __restrict__ feat1,
        const float* __restrict__ b0, const float* __restrict__ b1,
        float* __restrict__ out, __nv_bfloat16* __restrict__ outHi,
        __nv_bfloat16* __restrict__ outLo, int do_relu) {
    constexpr int WIDTH = 2 * O;
    constexpr int NV = WIDTH / 32;          // halves per lane: 16 (O=256) or 8 (O=128)
    int n = (blockIdx.x * blockDim.x + threadIdx.x) >> 5;
    if (n >= NN) return;
    int lane = threadIdx.x & 31;
    int head = lane >> 4;
    float acc[NV];
    #pragma unroll
    for (int j = 0; j < NV; j++) acc[j] = 0.f;

    #pragma unroll
    for (int rel = 0; rel < 2; rel++) {
        const int* off = rel ? off1 : off0;
        const int* csr = rel ? csr1 : csr0;
        const float* el = rel ? el1 : el0;
        const float* er = rel ? er1 : er0;
        const __half* feat = rel ? feat1 : feat0;
        int beg = off[n];
        int deg = off[n + 1] - beg;
        float ern0 = er[n * 2 + 0], ern1 = er[n * 2 + 1];
        // phase 1: denominators for both heads, lane-strided + butterfly reduce
        float d0 = 0.f, d1 = 0.f;
        for (int i = lane; i < deg; i += 32) {
            int s = csr[beg + i];
            float v0 = el[s * 2 + 0] + ern0;
            float v1 = el[s * 2 + 1] + ern1;
            v0 = v0 > 0.f ? v0 : 0.2f * v0;
            v1 = v1 > 0.f ? v1 : 0.2f * v1;
            d0 += __expf(v0);
            d1 += __expf(v1);
        }
        #pragma unroll
        for (int o = 16; o; o >>= 1) {
            d0 += __shfl_xor_sync(0xffffffffu, d0, o);
            d1 += __shfl_xor_sync(0xffffffffu, d1, o);
        }
        float inv = (head ? 1.f / fmaxf(d1, 1e-9f) : 1.f / fmaxf(d0, 1e-9f));
        float ern = head ? ern1 : ern0;
        // phase 2: per-edge alpha (recompute exp) + coalesced row gather
        #pragma unroll 2
        for (int i = 0; i < deg; i++) {
            int s = csr[beg + i];               // uniform address -> broadcast
            float v = el[s * 2 + head] + ern;
            v = v > 0.f ? v : 0.2f * v;
            float a = __expf(v) * inv;
            const __half* fp = feat + (size_t)s * WIDTH + lane * NV;
            if (NV == 16) {
                uint4 r0 = *(const uint4*)fp;
                uint4 r1 = *(const uint4*)(fp + 8);
                float2 f;
                f = __half22float2(*(__half2*)&r0.x); acc[0] += a * f.x; acc[1] += a * f.y;
                f = __half22float2(*(__half2*)&r0.y); acc[2] += a * f.x; acc[3] += a * f.y;
                f = __half22float2(*(__half2*)&r0.z); acc[4] += a * f.x; acc[5] += a * f.y;
                f = __half22float2(*(__half2*)&r0.w); acc[6] += a * f.x; acc[7] += a * f.y;
                f = __half22float2(*(__half2*)&r1.x); acc[8] += a * f.x; acc[9] += a * f.y;
                f = __half22float2(*(__half2*)&r1.y); acc[10] += a * f.x; acc[11] += a * f.y;
                f = __half22float2(*(__half2*)&r1.z); acc[12] += a * f.x; acc[13] += a * f.y;
                f = __half22float2(*(__half2*)&r1.w); acc[14] += a * f.x; acc[15] += a * f.y;
            } else {
                uint4 r0 = *(const uint4*)fp;
                float2 f;
                f = __half22float2(*(__half2*)&r0.x); acc[0] += a * f.x; acc[1] += a * f.y;
                f = __half22float2(*(__half2*)&r0.y); acc[2] += a * f.x; acc[3] += a * f.y;
                f = __half22float2(*(__half2*)&r0.z); acc[4] += a * f.x; acc[5] += a * f.y;
                f = __half22float2(*(__half2*)&r0.w); acc[6] += a * f.x; acc[7] += a * f.y;
            }
        }
    }
    // epilogue: lane l (<16) combines its cols j=l*NV+k with lane l+16's j+O
    float other[NV];
    #pragma unroll
    for (int j = 0; j < NV; j++)
        other[j] = __shfl_down_sync(0xffffffffu, acc[j], 16);
    if (lane < 16) {
        #pragma unroll
        for (int k = 0; k < NV; k++) {
            int j = lane * NV + k;
            float v = acc[k] + other[k]
                    + b0[j] + b0[j + O] + b1[j] + b1[j + O];
            v *= 0.5f;
            if (do_relu) v = fmaxf(v, 0.f);
            if (outHi) {
                __nv_bfloat16 h = __float2bfloat16(v);
                outHi[(size_t)n * O + j] = h;
                outLo[(size_t)n * O + j] = __float2bfloat16(v - __bfloat162float(h));
            } else {
                out[(size_t)n * O + j] = v;
            }
        }
    }
}

// ---------------- host launch ---------------------------------------------------
static float* symf(const void* s) { void* p = nullptr; cudaGetSymbolAddress(&p, s); return (float*)p; }
static int*   symi(const void* s) { void* p = nullptr; cudaGetSymbolAddress(&p, s); return (int*)p; }
static __half* symh(const void* s) { void* p = nullptr; cudaGetSymbolAddress(&p, s); return (__half*)p; }
static __nv_bfloat16* symb(const void* s) { void* p = nullptr; cudaGetSymbolAddress(&p, s); return (__nv_bfloat16*)p; }

struct Ctx {
    cudaStream_t s1, s2;
    cudaEvent_t fork1, join1a, join1b, fork2, join2;
    Ctx() {
        cudaStreamCreateWithFlags(&s1, cudaStreamNonBlocking);
        cudaStreamCreateWithFlags(&s2, cudaStreamNonBlocking);
        cudaEventCreateWithFlags(&fork1,  cudaEventDisableTiming);
        cudaEventCreateWithFlags(&join1a, cudaEventDisableTiming);
        cudaEventCreateWithFlags(&join1b, cudaEventDisableTiming);
        cudaEventCreateWithFlags(&fork2,  cudaEventDisableTiming);
        cudaEventCreateWithFlags(&join2,  cudaEventDisableTiming);
    }
};

extern "C" void kernel_launch(void* const* d_in, const int* in_sizes, int n_in,
                              void* d_out, int out_size) {
    static Ctx ctx;
    const float* x     = (const float*)d_in[0];
    const int*   src0  = (const int*)d_in[1];
    const int*   dst0  = (const int*)d_in[2];
    const int*   src1  = (const int*)d_in[3];
    const int*   dst1  = (const int*)d_in[4];
    const float* W1_0  = (const float*)d_in[5];
    const float* al1_0 = (const float*)d_in[6];
    const float* ar1_0 = (const float*)d_in[7];
    const float* b1_0  = (const float*)d_in[8];
    const float* W1_1  = (const float*)d_in[9];
    const float* al1_1 = (const float*)d_in[10];
    const float* ar1_1 = (const float*)d_in[11];
    const float* b1_1  = (const float*)d_in[12];
    const float* W2_0  = (const float*)d_in[13];
    const float* al2_0 = (const float*)d_in[14];
    const float* ar2_0 = (const float*)d_in[15];
    const float* b2_0  = (const float*)d_in[16];
    const float* W2_1  = (const float*)d_in[17];
    const float* al2_1 = (const float*)d_in[18];
    const float* ar2_1 = (const float*)d_in[19];
    const float* b2_1  = (const float*)d_in[20];
    float* out = (float*)d_out;

    __half* feat0 = symh(g_feat0);
    __half* feat1 = symh(g_feat1);
    float* el0 = symf(g_el0); float* er0 = symf(g_er0);
    float* el1 = symf(g_el1); float* er1 = symf(g_er1);
    float* el2 = symf(g_el2); float* er2 = symf(g_er2);
    float* el3 = symf(g_el3); float* er3 = symf(g_er3);
    int* deg0 = symi(g_deg0); int* deg1 = symi(g_deg1);
    int* off0 = symi(g_off0); int* off1 = symi(g_off1);
    int* pos0 = symi(g_pos0); int* pos1 = symi(g_pos1);
    int* csr0 = symi(g_csr0); int* csr1 = symi(g_csr1);
    int* bsum = symi(g_bsum);
    __nv_bfloat16* xhi = symb(g_xhi);   __nv_bfloat16* xlo = symb(g_xlo);
    __nv_bfloat16* h1hi = symb(g_h1hi); __nv_bfloat16* h1lo = symb(g_h1lo);
    __nv_bfloat16* w1hi0 = symb(g_w1hi0); __nv_bfloat16* w1lo0 = symb(g_w1lo0);
    __nv_bfloat16* w1hi1 = symb(g_w1hi1); __nv_bfloat16* w1lo1 = symb(g_w1lo1);
    __nv_bfloat16* w2hi0 = symb(g_w2hi0); __nv_bfloat16* w2lo0 = symb(g_w2lo0);
    __nv_bfloat16* w2hi1 = symb(g_w2hi1); __nv_bfloat16* w2lo1 = symb(g_w2lo1);

    cudaStream_t s1 = ctx.s1, s2 = ctx.s2;

    convX_k<<<(NN * DD + 255) / 256, 256>>>(x, xhi, xlo, NN * DD);
    zeroEl_k<<<(NN * HH + 255) / 256, 256>>>(el0, er0, el1, er1, NN * HH);

    cudaEventRecord(ctx.fork1, 0);
    cudaStreamWaitEvent(s1, ctx.fork1, 0);
    cudaStreamWaitEvent(s2, ctx.fork1, 0);

    // CSR build + layer-2 el/er zero (s1, off critical path)
    zeroEl_k<<<(NN * HH + 255) / 256, 256, 0, s1>>>(el2, er2, el3, er3, NN * HH);
    zero_k<<<(NN + 255) / 256, 256, 0, s1>>>(deg0, deg1, NN);
    hist_k<<<(EE + 255) / 256, 256, 0, s1>>>(dst0, dst1, deg0, deg1);
    { dim3 g(NB, 2); scanA_k<<<g, 1024, 0, s1>>>(deg0, deg1, off0, off1, bsum); }
    scanB_k<<<1, 64, 0, s1>>>(bsum, off0, off1);
    { dim3 g(NB, 2); scanC_k<<<g, 1024, 0, s1>>>(bsum, off0, off1, pos0, pos1); }
    scat_k<<<(EE + 255) / 256, 256, 0, s1>>>(src0, dst0, src1, dst1, pos0, pos1, csr0, csr1);

    convW_k<<<(512 * 128 + 255) / 256, 256>>>(W1_0, w1hi0, w1lo0, 128, 512);
    convW_k<<<(256 * 256 + 255) / 256, 256>>>(W2_0, w2hi0, w2lo0, 256, 256);
    convW_k<<<(512 * 128 + 255) / 256, 256, 0, s2>>>(W1_1, w1hi1, w1lo1, 128, 512);
    convW_k<<<(256 * 256 + 255) / 256, 256, 0, s2>>>(W2_1, w2hi1, w2lo1, 256, 256);

    { dim3 g(4, (NN + 127) / 128);
      gemm_mma_k<128, 256><<<g, 256>>>(xhi, xlo, w1hi0, w1lo0, feat0, NN, 512,
                                       al1_0, ar1_0, el0, er0);
      gemm_mma_k<128, 256><<<g, 256, 0, s2>>>(xhi, xlo, w1hi1, w1lo1, feat1, NN, 512,
                                              al1_1, ar1_1, el1, er1); }

    cudaEventRecord(ctx.join1a, s1);
    cudaEventRecord(ctx.join1b, s2);
    cudaStreamWaitEvent(0, ctx.join1a, 0);
    cudaStreamWaitEvent(0, ctx.join1b, 0);

    aggw_k<256><<<(NN * 32 + 255) / 256, 256>>>(off0, csr0, off1, csr1,
                            el0, er0, el1, er1,
                            feat0, feat1, b1_0, b1_1, nullptr, h1hi, h1lo, 1);

    // ---- layer 2 ----
    cudaEventRecord(ctx.fork2, 0);
    cudaStreamWaitEvent(s2, ctx.fork2, 0);
    { dim3 g(2, (NN + 127) / 128);
      gemm_mma_k<256, 128><<<g, 256>>>(h1hi, h1lo, w2hi0, w2lo0, feat0, NN, 256,
                                       al2_0, ar2_0, el2, er2);
      gemm_mma_k<256, 128><<<g, 256, 0, s2>>>(h1hi, h1lo, w2hi1, w2lo1, feat1, NN, 256,
                                              al2_1, ar2_1, el3, er3); }
    cudaEventRecord(ctx.join2, s2);
    cudaStreamWaitEvent(0, ctx.join2, 0);

    aggw_k<128><<<(NN * 32 + 255) / 256, 256>>>(off0, csr0, off1, csr1,
                            el2, er2, el3, er3,
                            feat0, feat1, b2_0, b2_1, out, nullptr, nullptr, 0);
}

// round 9
// speedup vs baseline: 3.1309x; 1.1189x over previous
#include <cuda_runtime.h>
#include <cuda_fp16.h>
#include <cstdint>
#include <math.h>

#define NN   20000
#define EE   320000
#define DD   128
#define HH   2
#define NB   ((NN + 1023) / 1024)

// ---------------- scratch (device globals) ------------------------------------
__device__ __align__(16) __half g_feat0[(size_t)NN * 512];
__device__ __align__(16) __half g_feat1[(size_t)NN * 512];
__device__ float g_el0[NN * 2], g_er0[NN * 2];
__device__ float g_el1[NN * 2], g_er1[NN * 2];
__device__ float g_el2[NN * 2], g_er2[NN * 2];
__device__ float g_el3[NN * 2], g_er3[NN * 2];
__device__ int   g_deg0[NN], g_deg1[NN];
__device__ int   g_off0[NN + 1], g_off1[NN + 1];
__device__ int   g_pos0[NN], g_pos1[NN];
__device__ int   g_csr0[EE], g_csr1[EE];
__device__ int   g_bsum[64];
__device__ __align__(16) __half g_xh[(size_t)NN * DD];
__device__ __align__(16) __half g_h1[(size_t)NN * 256];
__device__ __align__(16) __half g_w1hi0[512 * 128], g_w1lo0[512 * 128];
__device__ __align__(16) __half g_w1hi1[512 * 128], g_w1lo1[512 * 128];
__device__ __align__(16) __half g_w2hi0[256 * 256], g_w2lo0[256 * 256];
__device__ __align__(16) __half g_w2hi1[256 * 256], g_w2lo1[256 * 256];

// ---------------- CSR build -----------------------------------------------------
__global__ void zero_k(int* a, int* b, int n) {
    int i = blockIdx.x * blockDim.x + threadIdx.x;
    if (i < n) { a[i] = 0; b[i] = 0; }
}
__global__ void zeroEl_k(float* el0, float* er0, float* el1, float* er1, int n) {
    int i = blockIdx.x * blockDim.x + threadIdx.x;
    if (i < n) { el0[i] = 0.f; er0[i] = 0.f; el1[i] = 0.f; er1[i] = 0.f; }
}
__global__ void hist_k(const int* __restrict__ dst0, const int* __restrict__ dst1,
                       int* deg0, int* deg1) {
    int i = blockIdx.x * blockDim.x + threadIdx.x;
    if (i < EE) {
        atomicAdd(&deg0[dst0[i]], 1);
        atomicAdd(&deg1[dst1[i]], 1);
    }
}
__global__ void scanA_k(const int* __restrict__ deg0, const int* __restrict__ deg1,
                        int* off0, int* off1, int* bsum) {
    const int* deg = blockIdx.y ? deg1 : deg0;
    int* off = blockIdx.y ? off1 : off0;
    int i = blockIdx.x * 1024 + threadIdx.x;
    int lane = threadIdx.x & 31, wid = threadIdx.x >> 5;
    int v = (i < NN) ? deg[i] : 0;
    int x = v;
    #pragma unroll
    for (int o = 1; o < 32; o <<= 1) {
        int t = __shfl_up_sync(0xffffffffu, x, o);
        if (lane >= o) x += t;
    }
    __shared__ int wsum[32];
    if (lane == 31) wsum[wid] = x;
    __syncthreads();
    if (wid == 0) {
        int w = wsum[lane];
        #pragma unroll
        for (int o = 1; o < 32; o <<= 1) {
            int t = __shfl_up_sync(0xffffffffu, w, o);
            if (lane >= o) w += t;
        }
        wsum[lane] = w;
    }
    __syncthreads();
    int inc = x + (wid ? wsum[wid - 1] : 0);
    if (i < NN) off[i] = inc - v;
    if (threadIdx.x == 1023) bsum[blockIdx.y * 32 + blockIdx.x] = inc;
}
__global__ void scanB_k(int* bsum, int* off0, int* off1) {
    int y = threadIdx.x >> 5, lane = threadIdx.x & 31;
    int v = (lane < NB) ? bsum[y * 32 + lane] : 0;
    int x = v;
    #pragma unroll
    for (int o = 1; o < 32; o <<= 1) {
        int t = __shfl_up_sync(0xffffffffu, x, o);
        if (lane >= o) x += t;
    }
    if (lane < NB) bsum[y * 32 + lane] = x - v;
    if (lane == NB - 1) { int* off = y ? off1 : off0; off[NN] = x; }
}
__global__ void scanC_k(const int* __restrict__ bsum, int* off0, int* off1,
                        int* pos0, int* pos1) {
    int i = blockIdx.x * 1024 + threadIdx.x;
    if (i >= NN) return;
    int y = blockIdx.y;
    int* off = y ? off1 : off0;
    int* pos = y ? pos1 : pos0;
    int val = off[i] + bsum[y * 32 + blockIdx.x];
    off[i] = val; pos[i] = val;
}
__global__ void scat_k(const int* __restrict__ src0, const int* __restrict__ dst0,
                       const int* __restrict__ src1, const int* __restrict__ dst1,
                       int* pos0, int* pos1, int* csr0, int* csr1) {
    int i = blockIdx.x * blockDim.x + threadIdx.x;
    if (i < EE) {
        csr0[atomicAdd(&pos0[dst0[i]], 1)] = src0[i];
        csr1[atomicAdd(&pos1[dst1[i]], 1)] = src1[i];
    }
}

// ---------------- conversion kernels --------------------------------------------
__global__ void convX_k(const float* __restrict__ x, __half* xh, int n) {
    int i = blockIdx.x * blockDim.x + threadIdx.x;
    if (i < n) xh[i] = __float2half_rn(x[i]);
}
// transpose W[K][Nd] -> Wt[Nd][K] with fp16 hi/lo split
__global__ void convW_k(const float* __restrict__ W, __half* hi,
                        __half* lo, int K, int Nd) {
    int i = blockIdx.x * blockDim.x + threadIdx.x;
    if (i >= K * Nd) return;
    int n = i / K, k = i % K;
    float v = W[(size_t)k * Nd + n];
    __half h = __float2half_rn(v);
    hi[i] = h;
    lo[i] = __float2half_rn(v - __half2float(h));
}

// ---------------- mma.sync helpers ---------------------------------------------
__device__ __forceinline__ uint32_t smem_u32(const void* p) {
    uint32_t a;
    asm("{ .reg .u64 t; cvta.to.shared.u64 t, %1; cvt.u32.u64 %0, t; }" : "=r"(a) : "l"(p));
    return a;
}
__device__ __forceinline__ void ldsm_x4(uint32_t* r, uint32_t addr) {
    asm volatile("ldmatrix.sync.aligned.m8n8.x4.shared.b16 {%0,%1,%2,%3}, [%4];"
                 : "=r"(r[0]), "=r"(r[1]), "=r"(r[2]), "=r"(r[3]) : "r"(addr));
}
__device__ __forceinline__ void ldsm_x2(uint32_t* r, uint32_t addr) {
    asm volatile("ldmatrix.sync.aligned.m8n8.x2.shared.b16 {%0,%1}, [%2];"
                 : "=r"(r[0]), "=r"(r[1]) : "r"(addr));
}
__device__ __forceinline__ void mma_fp16(float* d, const uint32_t* a, const uint32_t* b) {
    asm volatile(
        "mma.sync.aligned.m16n8k16.row.col.f32.f16.f16.f32 "
        "{%0,%1,%2,%3}, {%4,%5,%6,%7}, {%8,%9}, {%0,%1,%2,%3};"
        : "+f"(d[0]), "+f"(d[1]), "+f"(d[2]), "+f"(d[3])
        : "r"(a[0]), "r"(a[1]), "r"(a[2]), "r"(a[3]), "r"(b[0]), "r"(b[1]));
}

// ---------------- tensor-core fp16 GEMM + fused attn epilogue ------------------
// C[M,Nd] = A[M,KTOT] * (Whi+Wlo)[Nd,KTOT]^T; 2-term compensation.
#define SSTR 40
__device__ __forceinline__ void load_chunk(const __half* __restrict__ g,
        int ld, int rbase, int kofs, __half* s, int rlim, int tid) {
    #pragma unroll
    for (int i = 0; i < 2; i++) {
        int id = tid + i * 256;
        int r = id >> 2;
        int c = (id & 3) * 8;
        uint4 v = make_uint4(0u, 0u, 0u, 0u);
        int gr = rbase + r;
        if (gr < rlim)
            v = *(const uint4*)(g + (size_t)gr * ld + kofs + c);
        *(uint4*)(s + r * SSTR + c) = v;
    }
}

template<int KTOT, int O>
__global__ void __launch_bounds__(256) gemm_mma_k(
        const __half* __restrict__ A,
        const __half* __restrict__ Bhi, const __half* __restrict__ Blo,
        __half* __restrict__ C, int M, int Nd,
        const float* __restrict__ al, const float* __restrict__ ar,
        float* __restrict__ el, float* __restrict__ er) {
    __shared__ __align__(16) __half sA[128 * SSTR];
    __shared__ __align__(16) __half sBhi[128 * SSTR];
    __shared__ __align__(16) __half sBlo[128 * SSTR];
    const int tid = threadIdx.x;
    const int w = tid >> 5;
    const int lane = tid & 31;
    const int rowBase = blockIdx.y * 128;
    const int colBase = blockIdx.x * 128;
    const int wRow = w >> 2;
    const int wCol = w & 3;

    uint32_t aBase = smem_u32(sA);
    uint32_t bBaseHi = smem_u32(sBhi), bBaseLo = smem_u32(sBlo);

    float d[4][4][4];
    #pragma unroll
    for (int i = 0; i < 4; i++)
        #pragma unroll
        for (int j = 0; j < 4; j++)
            #pragma unroll
            for (int q = 0; q < 4; q++) d[i][j][q] = 0.f;

    constexpr int NKC = KTOT / 32;
    for (int kc = 0; kc < NKC; kc++) {
        load_chunk(A,   KTOT, rowBase, kc * 32, sA,   M, tid);
        load_chunk(Bhi, KTOT, colBase, kc * 32, sBhi, 1 << 30, tid);
        load_chunk(Blo, KTOT, colBase, kc * 32, sBlo, 1 << 30, tid);
        __syncthreads();
        #pragma unroll
        for (int ks = 0; ks < 32; ks += 16) {
            uint32_t bhi[4][2], blo[4][2];
            {
                int brow = (lane & 7);
                int bcol = ks + ((lane >> 3) & 1) * 8;
                #pragma unroll
                for (int nt = 0; nt < 4; nt++) {
                    uint32_t off = (uint32_t)(((wCol * 32 + nt * 8 + brow) * SSTR + bcol) * 2);
                    ldsm_x2(bhi[nt], bBaseHi + off);
                    ldsm_x2(blo[nt], bBaseLo + off);
                }
            }
            int arow = (lane & 15);
            int acol = ks + (lane >> 4) * 8;
            #pragma unroll
            for (int mt = 0; mt < 4; mt++) {
                uint32_t a[4];
                uint32_t off = (uint32_t)(((wRow * 64 + mt * 16 + arow) * SSTR + acol) * 2);
                ldsm_x4(a, aBase + off);
                #pragma unroll
                for (int nt = 0; nt < 4; nt++) {
                    mma_fp16(d[mt][nt], a, bhi[nt]);
                    mma_fp16(d[mt][nt], a, blo[nt]);
                }
            }
        }
        __syncthreads();
    }

    // ---- epilogue: fp16 C write + fused attn partial dot products ----
    int mlocal = lane >> 2;
    int nlocal = (lane & 3) * 2;
    float alv[4][2], arv[4][2];
    int head;
    {
        int c0 = colBase + wCol * 32 + nlocal;
        head = c0 / O;                              // 32-col warp tile never straddles heads
        #pragma unroll
        for (int nt = 0; nt < 4; nt++) {
            int c = c0 + nt * 8 - head * O;
            alv[nt][0] = al[head * O + c]; alv[nt][1] = al[head * O + c + 1];
            arv[nt][0] = ar[head * O + c]; arv[nt][1] = ar[head * O + c + 1];
        }
    }
    #pragma unroll
    for (int mt = 0; mt < 4; mt++) {
        int row = rowBase + wRow * 64 + mt * 16 + mlocal;
        float pel0 = 0.f, per0 = 0.f, pel8 = 0.f, per8 = 0.f;
        #pragma unroll
        for (int nt = 0; nt < 4; nt++) {
            int col = colBase + wCol * 32 + nt * 8 + nlocal;
            if (row < M)
                *(__half2*)&C[(size_t)row * Nd + col] =
                    __floats2half2_rn(d[mt][nt][0], d[mt][nt][1]);
            if (row + 8 < M)
                *(__half2*)&C[(size_t)(row + 8) * Nd + col] =
                    __floats2half2_rn(d[mt][nt][2], d[mt][nt][3]);
            pel0 += d[mt][nt][0] * alv[nt][0] + d[mt][nt][1] * alv[nt][1];
            per0 += d[mt][nt][0] * arv[nt][0] + d[mt][nt][1] * arv[nt][1];
            pel8 += d[mt][nt][2] * alv[nt][0] + d[mt][nt][3] * alv[nt][1];
            per8 += d[mt][nt][2] * arv[nt][0] + d[mt][nt][3] * arv[nt][1];
        }
        #pragma unroll
        for (int o = 1; o < 4; o <<= 1) {
            pel0 += __shfl_xor_sync(0xffffffffu, pel0, o);
            per0 += __shfl_xor_sync(0xffffffffu, per0, o);
            pel8 += __shfl_xor_sync(0xffffffffu, pel8, o);
            per8 += __shfl_xor_sync(0xffffffffu, per8, o);
        }
        if ((lane & 3) == 0) {
            if (row < M) {
                atomicAdd(&el[row * HH + head], pel0);
                atomicAdd(&er[row * HH + head], per0);
            }
            if (row + 8 < M) {
                atomicAdd(&el[(row + 8) * HH + head], pel8);
                atomicAdd(&er[(row + 8) * HH + head], per8);
            }
        }
    }
}

// ---------------- warp-per-node softmax + aggregation + epilogue ---------------
template<int O>
__global__ void __launch_bounds__(256) aggw_k(
        const int* __restrict__ off0, const int* __restrict__ csr0,
        const int* __restrict__ off1, const int* __restrict__ csr1,
        const float* __restrict__ el0, const float* __restrict__ er0,
        const float* __restrict__ el1, const float* __restrict__ er1,
        const __half* __restrict__ feat0, const __half* __restrict__ feat1,
        const float* __restrict__ b0, const float* __restrict__ b1,
        float* __restrict__ out, __half* __restrict__ outH, int do_relu) {
    constexpr int WIDTH = 2 * O;
    constexpr int NV = WIDTH / 32;          // halves per lane: 16 (O=256) or 8 (O=128)
    int n = (blockIdx.x * blockDim.x + threadIdx.x) >> 5;
    if (n >= NN) return;
    int lane = threadIdx.x & 31;
    int head = lane >> 4;
    float acc[NV];
    #pragma unroll
    for (int j = 0; j < NV; j++) acc[j] = 0.f;

    #pragma unroll
    for (int rel = 0; rel < 2; rel++) {
        const int* off = rel ? off1 : off0;
        const int* csr = rel ? csr1 : csr0;
        const float* el = rel ? el1 : el0;
        const float* er = rel ? er1 : er0;
        const __half* feat = rel ? feat1 : feat0;
        int beg = off[n];
        int deg = off[n + 1] - beg;
        float ern0 = er[n * 2 + 0], ern1 = er[n * 2 + 1];
        float d0 = 0.f, d1 = 0.f;
        for (int i = lane; i < deg; i += 32) {
            int s = csr[beg + i];
            float v0 = el[s * 2 + 0] + ern0;
            float v1 = el[s * 2 + 1] + ern1;
            v0 = v0 > 0.f ? v0 : 0.2f * v0;
            v1 = v1 > 0.f ? v1 : 0.2f * v1;
            d0 += __expf(v0);
            d1 += __expf(v1);
        }
        #pragma unroll
        for (int o = 16; o; o >>= 1) {
            d0 += __shfl_xor_sync(0xffffffffu, d0, o);
            d1 += __shfl_xor_sync(0xffffffffu, d1, o);
        }
        float inv = (head ? 1.f / fmaxf(d1, 1e-9f) : 1.f / fmaxf(d0, 1e-9f));
        float ern = head ? ern1 : ern0;
        #pragma unroll 2
        for (int i = 0; i < deg; i++) {
            int s = csr[beg + i];               // uniform address -> broadcast
            float v = el[s * 2 + head] + ern;
            v = v > 0.f ? v : 0.2f * v;
            float a = __expf(v) * inv;
            const __half* fp = feat + (size_t)s * WIDTH + lane * NV;
            if (NV == 16) {
                uint4 r0 = *(const uint4*)fp;
                uint4 r1 = *(const uint4*)(fp + 8);
                float2 f;
                f = __half22float2(*(__half2*)&r0.x); acc[0] += a * f.x; acc[1] += a * f.y;
                f = __half22float2(*(__half2*)&r0.y); acc[2] += a * f.x; acc[3] += a * f.y;
                f = __half22float2(*(__half2*)&r0.z); acc[4] += a * f.x; acc[5] += a * f.y;
                f = __half22float2(*(__half2*)&r0.w); acc[6] += a * f.x; acc[7] += a * f.y;
                f = __half22float2(*(__half2*)&r1.x); acc[8] += a * f.x; acc[9] += a * f.y;
                f = __half22float2(*(__half2*)&r1.y); acc[10] += a * f.x; acc[11] += a * f.y;
                f = __half22float2(*(__half2*)&r1.z); acc[12] += a * f.x; acc[13] += a * f.y;
                f = __half22float2(*(__half2*)&r1.w); acc[14] += a * f.x; acc[15] += a * f.y;
            } else {
                uint4 r0 = *(const uint4*)fp;
                float2 f;
                f = __half22float2(*(__half2*)&r0.x); acc[0] += a * f.x; acc[1] += a * f.y;
                f = __half22float2(*(__half2*)&r0.y); acc[2] += a * f.x; acc[3] += a * f.y;
                f = __half22float2(*(__half2*)&r0.z); acc[4] += a * f.x; acc[5] += a * f.y;
                f = __half22float2(*(__half2*)&r0.w); acc[6] += a * f.x; acc[7] += a * f.y;
            }
        }
    }
    // epilogue: lane l (<16) combines its cols j=l*NV+k with lane l+16's j+O
    float other[NV];
    #pragma unroll
    for (int j = 0; j < NV; j++)
        other[j] = __shfl_down_sync(0xffffffffu, acc[j], 16);
    if (lane < 16) {
        #pragma unroll
        for (int k = 0; k < NV; k++) {
            int j = lane * NV + k;
            float v = acc[k] + other[k]
                    + b0[j] + b0[j + O] + b1[j] + b1[j + O];
            v *= 0.5f;
            if (do_relu) v = fmaxf(v, 0.f);
            if (outH) outH[(size_t)n * O + j] = __float2half_rn(v);
            else      out[(size_t)n * O + j] = v;
        }
    }
}

// ---------------- host launch ---------------------------------------------------
static float* symf(const void* s) { void* p = nullptr; cudaGetSymbolAddress(&p, s); return (float*)p; }
static int*   symi(const void* s) { void* p = nullptr; cudaGetSymbolAddress(&p, s); return (int*)p; }
static __half* symh(const void* s) { void* p = nullptr; cudaGetSymbolAddress(&p, s); return (__half*)p; }

struct Ctx {
    cudaStream_t s1, s2;
    cudaEvent_t fork1, join1a, join1b, fork2, join2;
    Ctx() {
        cudaStreamCreateWithFlags(&s1, cudaStreamNonBlocking);
        cudaStreamCreateWithFlags(&s2, cudaStreamNonBlocking);
        cudaEventCreateWithFlags(&fork1,  cudaEventDisableTiming);
        cudaEventCreateWithFlags(&join1a, cudaEventDisableTiming);
        cudaEventCreateWithFlags(&join1b, cudaEventDisableTiming);
        cudaEventCreateWithFlags(&fork2,  cudaEventDisableTiming);
        cudaEventCreateWithFlags(&join2,  cudaEventDisableTiming);
    }
};

extern "C" void kernel_launch(void* const* d_in, const int* in_sizes, int n_in,
                              void* d_out, int out_size) {
    static Ctx ctx;
    const float* x     = (const float*)d_in[0];
    const int*   src0  = (const int*)d_in[1];
    const int*   dst0  = (const int*)d_in[2];
    const int*   src1  = (const int*)d_in[3];
    const int*   dst1  = (const int*)d_in[4];
    const float* W1_0  = (const float*)d_in[5];
    const float* al1_0 = (const float*)d_in[6];
    const float* ar1_0 = (const float*)d_in[7];
    const float* b1_0  = (const float*)d_in[8];
    const float* W1_1  = (const float*)d_in[9];
    const float* al1_1 = (const float*)d_in[10];
    const float* ar1_1 = (const float*)d_in[11];
    const float* b1_1  = (const float*)d_in[12];
    const float* W2_0  = (const float*)d_in[13];
    const float* al2_0 = (const float*)d_in[14];
    const float* ar2_0 = (const float*)d_in[15];
    const float* b2_0  = (const float*)d_in[16];
    const float* W2_1  = (const float*)d_in[17];
    const float* al2_1 = (const float*)d_in[18];
    const float* ar2_1 = (const float*)d_in[19];
    const float* b2_1  = (const float*)d_in[20];
    float* out = (float*)d_out;

    __half* feat0 = symh(g_feat0);
    __half* feat1 = symh(g_feat1);
    float* el0 = symf(g_el0); float* er0 = symf(g_er0);
    float* el1 = symf(g_el1); float* er1 = symf(g_er1);
    float* el2 = symf(g_el2); float* er2 = symf(g_er2);
    float* el3 = symf(g_el3); float* er3 = symf(g_er3);
    int* deg0 = symi(g_deg0); int* deg1 = symi(g_deg1);
    int* off0 = symi(g_off0); int* off1 = symi(g_off1);
    int* pos0 = symi(g_pos0); int* pos1 = symi(g_pos1);
    int* csr0 = symi(g_csr0); int* csr1 = symi(g_csr1);
    int* bsum = symi(g_bsum);
    __half* xh = symh(g_xh);
    __half* h1 = symh(g_h1);
    __half* w1hi0 = symh(g_w1hi0); __half* w1lo0 = symh(g_w1lo0);
    __half* w1hi1 = symh(g_w1hi1); __half* w1lo1 = symh(g_w1lo1);
    __half* w2hi0 = symh(g_w2hi0); __half* w2lo0 = symh(g_w2lo0);
    __half* w2hi1 = symh(g_w2hi1); __half* w2lo1 = symh(g_w2lo1);

    cudaStream_t s1 = ctx.s1, s2 = ctx.s2;

    convX_k<<<(NN * DD + 255) / 256, 256>>>(x, xh, NN * DD);
    zeroEl_k<<<(NN * HH + 255) / 256, 256>>>(el0, er0, el1, er1, NN * HH);

    cudaEventRecord(ctx.fork1, 0);
    cudaStreamWaitEvent(s1, ctx.fork1, 0);
    cudaStreamWaitEvent(s2, ctx.fork1, 0);

    // CSR build + layer-2 el/er zero (s1, off critical path)
    zeroEl_k<<<(NN * HH + 255) / 256, 256, 0, s1>>>(el2, er2, el3, er3, NN * HH);
    zero_k<<<(NN + 255) / 256, 256, 0, s1>>>(deg0, deg1, NN);
    hist_k<<<(EE + 255) / 256, 256, 0, s1>>>(dst0, dst1, deg0, deg1);
    { dim3 g(NB, 2); scanA_k<<<g, 1024, 0, s1>>>(deg0, deg1, off0, off1, bsum); }
    scanB_k<<<1, 64, 0, s1>>>(bsum, off0, off1);
    { dim3 g(NB, 2); scanC_k<<<g, 1024, 0, s1>>>(bsum, off0, off1, pos0, pos1); }
    scat_k<<<(EE + 255) / 256, 256, 0, s1>>>(src0, dst0, src1, dst1, pos0, pos1, csr0, csr1);

    convW_k<<<(512 * 128 + 255) / 256, 256>>>(W1_0, w1hi0, w1lo0, 128, 512);
    convW_k<<<(256 * 256 + 255) / 256, 256>>>(W2_0, w2hi0, w2lo0, 256, 256);
    convW_k<<<(512 * 128 + 255) / 256, 256, 0, s2>>>(W1_1, w1hi1, w1lo1, 128, 512);
    convW_k<<<(256 * 256 + 255) / 256, 256, 0, s2>>>(W2_1, w2hi1, w2lo1, 256, 256);

    { dim3 g(4, (NN + 127) / 128);
      gemm_mma_k<128, 256><<<g, 256>>>(xh, w1hi0, w1lo0, feat0, NN, 512,
                                       al1_0, ar1_0, el0, er0);
      gemm_mma_k<128, 256><<<g, 256, 0, s2>>>(xh, w1hi1, w1lo1, feat1, NN, 512,
                                              al1_1, ar1_1, el1, er1); }

    cudaEventRecord(ctx.join1a, s1);
    cudaEventRecord(ctx.join1b, s2);
    cudaStreamWaitEvent(0, ctx.join1a, 0);
    cudaStreamWaitEvent(0, ctx.join1b, 0);

    aggw_k<256><<<(NN * 32 + 255) / 256, 256>>>(off0, csr0, off1, csr1,
                            el0, er0, el1, er1,
                            feat0, feat1, b1_0, b1_1, nullptr, h1, 1);

    // ---- layer 2 ----
    cudaEventRecord(ctx.fork2, 0);
    cudaStreamWaitEvent(s2, ctx.fork2, 0);
    { dim3 g(2, (NN + 127) / 128);
      gemm_mma_k<256, 128><<<g, 256>>>(h1, w2hi0, w2lo0, feat0, NN, 256,
                                       al2_0, ar2_0, el2, er2);
      gemm_mma_k<256, 128><<<g, 256, 0, s2>>>(h1, w2hi1, w2lo1, feat1, NN, 256,
                                              al2_1, ar2_1, el3, er3); }
    cudaEventRecord(ctx.join2, s2);
    cudaStreamWaitEvent(0, ctx.join2, 0);

    aggw_k<128><<<(NN * 32 + 255) / 256, 256>>>(off0, csr0, off1, csr1,
                            el2, er2, el3, er3,
                            feat0, feat1, b2_0, b2_1, out, nullptr, 0);
}

// round 10
// speedup vs baseline: 3.7411x; 1.1949x over previous
#include <cuda_runtime.h>
#include <cuda_fp16.h>
#include <cstdint>
#include <math.h>

#define NN   20000
#define EE   320000
#define DD   128
#define HH   2
#define NB   ((NN + 1023) / 1024)

// ---------------- scratch (device globals) ------------------------------------
__device__ __align__(16) __half g_feat0[(size_t)NN * 512];
__device__ __align__(16) __half g_feat1[(size_t)NN * 512];
__device__ float g_el0[NN * 2], g_er0[NN * 2];
__device__ float g_el1[NN * 2], g_er1[NN * 2];
__device__ float g_el2[NN * 2], g_er2[NN * 2];
__device__ float g_el3[NN * 2], g_er3[NN * 2];
__device__ int   g_deg0[NN], g_deg1[NN];
__device__ int   g_off0[NN + 1], g_off1[NN + 1];
__device__ int   g_pos0[NN], g_pos1[NN];
__device__ int   g_csr0[EE], g_csr1[EE];
__device__ int   g_bsum[64];
__device__ __align__(16) __half g_xh[(size_t)NN * DD];
__device__ __align__(16) __half g_h1[(size_t)NN * 256];
__device__ __align__(16) __half g_w1_0[512 * 128];
__device__ __align__(16) __half g_w1_1[512 * 128];
__device__ __align__(16) __half g_w2_0[256 * 256];
__device__ __align__(16) __half g_w2_1[256 * 256];

// ---------------- CSR build -----------------------------------------------------
__global__ void zero_k(int* a, int* b, int n) {
    int i = blockIdx.x * blockDim.x + threadIdx.x;
    if (i < n) { a[i] = 0; b[i] = 0; }
}
__global__ void zeroEl_k(float* el0, float* er0, float* el1, float* er1, int n) {
    int i = blockIdx.x * blockDim.x + threadIdx.x;
    if (i < n) { el0[i] = 0.f; er0[i] = 0.f; el1[i] = 0.f; er1[i] = 0.f; }
}
__global__ void hist_k(const int* __restrict__ dst0, const int* __restrict__ dst1,
                       int* deg0, int* deg1) {
    int i = blockIdx.x * blockDim.x + threadIdx.x;
    if (i < EE) {
        atomicAdd(&deg0[dst0[i]], 1);
        atomicAdd(&deg1[dst1[i]], 1);
    }
}
__global__ void scanA_k(const int* __restrict__ deg0, const int* __restrict__ deg1,
                        int* off0, int* off1, int* bsum) {
    const int* deg = blockIdx.y ? deg1 : deg0;
    int* off = blockIdx.y ? off1 : off0;
    int i = blockIdx.x * 1024 + threadIdx.x;
    int lane = threadIdx.x & 31, wid = threadIdx.x >> 5;
    int v = (i < NN) ? deg[i] : 0;
    int x = v;
    #pragma unroll
    for (int o = 1; o < 32; o <<= 1) {
        int t = __shfl_up_sync(0xffffffffu, x, o);
        if (lane >= o) x += t;
    }
    __shared__ int wsum[32];
    if (lane == 31) wsum[wid] = x;
    __syncthreads();
    if (wid == 0) {
        int w = wsum[lane];
        #pragma unroll
        for (int o = 1; o < 32; o <<= 1) {
            int t = __shfl_up_sync(0xffffffffu, w, o);
            if (lane >= o) w += t;
        }
        wsum[lane] = w;
    }
    __syncthreads();
    int inc = x + (wid ? wsum[wid - 1] : 0);
    if (i < NN) off[i] = inc - v;
    if (threadIdx.x == 1023) bsum[blockIdx.y * 32 + blockIdx.x] = inc;
}
__global__ void scanB_k(int* bsum, int* off0, int* off1) {
    int y = threadIdx.x >> 5, lane = threadIdx.x & 31;
    int v = (lane < NB) ? bsum[y * 32 + lane] : 0;
    int x = v;
    #pragma unroll
    for (int o = 1; o < 32; o <<= 1) {
        int t = __shfl_up_sync(0xffffffffu, x, o);
        if (lane >= o) x += t;
    }
    if (lane < NB) bsum[y * 32 + lane] = x - v;
    if (lane == NB - 1) { int* off = y ? off1 : off0; off[NN] = x; }
}
__global__ void scanC_k(const int* __restrict__ bsum, int* off0, int* off1,
                        int* pos0, int* pos1) {
    int i = blockIdx.x * 1024 + threadIdx.x;
    if (i >= NN) return;
    int y = blockIdx.y;
    int* off = y ? off1 : off0;
    int* pos = y ? pos1 : pos0;
    int val = off[i] + bsum[y * 32 + blockIdx.x];
    off[i] = val; pos[i] = val;
}
__global__ void scat_k(const int* __restrict__ src0, const int* __restrict__ dst0,
                       const int* __restrict__ src1, const int* __restrict__ dst1,
                       int* pos0, int* pos1, int* csr0, int* csr1) {
    int i = blockIdx.x * blockDim.x + threadIdx.x;
    if (i < EE) {
        csr0[atomicAdd(&pos0[dst0[i]], 1)] = src0[i];
        csr1[atomicAdd(&pos1[dst1[i]], 1)] = src1[i];
    }
}

// ---------------- conversion kernels --------------------------------------------
__global__ void convX_k(const float* __restrict__ x, __half* xh, int n) {
    int i = blockIdx.x * blockDim.x + threadIdx.x;
    if (i < n) xh[i] = __float2half_rn(x[i]);
}
// transpose W[K][Nd] -> Wt[Nd][K], fp16
__global__ void convW_k(const float* __restrict__ W, __half* wt, int K, int Nd) {
    int i = blockIdx.x * blockDim.x + threadIdx.x;
    if (i >= K * Nd) return;
    int n = i / K, k = i % K;
    wt[i] = __float2half_rn(W[(size_t)k * Nd + n]);
}

// ---------------- mma.sync helpers ---------------------------------------------
__device__ __forceinline__ uint32_t smem_u32(const void* p) {
    uint32_t a;
    asm("{ .reg .u64 t; cvta.to.shared.u64 t, %1; cvt.u32.u64 %0, t; }" : "=r"(a) : "l"(p));
    return a;
}
__device__ __forceinline__ void ldsm_x4(uint32_t* r, uint32_t addr) {
    asm volatile("ldmatrix.sync.aligned.m8n8.x4.shared.b16 {%0,%1,%2,%3}, [%4];"
                 : "=r"(r[0]), "=r"(r[1]), "=r"(r[2]), "=r"(r[3]) : "r"(addr));
}
__device__ __forceinline__ void ldsm_x2(uint32_t* r, uint32_t addr) {
    asm volatile("ldmatrix.sync.aligned.m8n8.x2.shared.b16 {%0,%1}, [%2];"
                 : "=r"(r[0]), "=r"(r[1]) : "r"(addr));
}
__device__ __forceinline__ void mma_fp16(float* d, const uint32_t* a, const uint32_t* b) {
    asm volatile(
        "mma.sync.aligned.m16n8k16.row.col.f32.f16.f16.f32 "
        "{%0,%1,%2,%3}, {%4,%5,%6,%7}, {%8,%9}, {%0,%1,%2,%3};"
        : "+f"(d[0]), "+f"(d[1]), "+f"(d[2]), "+f"(d[3])
        : "r"(a[0]), "r"(a[1]), "r"(a[2]), "r"(a[3]), "r"(b[0]), "r"(b[1]));
}

// ---------------- tensor-core fp16 GEMM + fused attn epilogue ------------------
// C[M,Nd] = A[M,KTOT] * W[Nd,KTOT]^T, pure fp16 operands, fp32 accum.
#define SSTR 40
__device__ __forceinline__ void load_chunk(const __half* __restrict__ g,
        int ld, int rbase, int kofs, __half* s, int rlim, int tid) {
    #pragma unroll
    for (int i = 0; i < 2; i++) {
        int id = tid + i * 256;
        int r = id >> 2;
        int c = (id & 3) * 8;
        uint4 v = make_uint4(0u, 0u, 0u, 0u);
        int gr = rbase + r;
        if (gr < rlim)
            v = *(const uint4*)(g + (size_t)gr * ld + kofs + c);
        *(uint4*)(s + r * SSTR + c) = v;
    }
}

template<int KTOT, int O>
__global__ void __launch_bounds__(256) gemm_mma_k(
        const __half* __restrict__ A, const __half* __restrict__ B,
        __half* __restrict__ C, int M, int Nd,
        const float* __restrict__ al, const float* __restrict__ ar,
        float* __restrict__ el, float* __restrict__ er) {
    __shared__ __align__(16) __half sA[128 * SSTR];
    __shared__ __align__(16) __half sB[128 * SSTR];
    const int tid = threadIdx.x;
    const int w = tid >> 5;
    const int lane = tid & 31;
    const int rowBase = blockIdx.y * 128;
    const int colBase = blockIdx.x * 128;
    const int wRow = w >> 2;
    const int wCol = w & 3;

    uint32_t aBase = smem_u32(sA);
    uint32_t bBase = smem_u32(sB);

    float d[4][4][4];
    #pragma unroll
    for (int i = 0; i < 4; i++)
        #pragma unroll
        for (int j = 0; j < 4; j++)
            #pragma unroll
            for (int q = 0; q < 4; q++) d[i][j][q] = 0.f;

    constexpr int NKC = KTOT / 32;
    for (int kc = 0; kc < NKC; kc++) {
        load_chunk(A, KTOT, rowBase, kc * 32, sA, M, tid);
        load_chunk(B, KTOT, colBase, kc * 32, sB, 1 << 30, tid);
        __syncthreads();
        #pragma unroll
        for (int ks = 0; ks < 32; ks += 16) {
            uint32_t b[4][2];
            {
                int brow = (lane & 7);
                int bcol = ks + ((lane >> 3) & 1) * 8;
                #pragma unroll
                for (int nt = 0; nt < 4; nt++) {
                    uint32_t off = (uint32_t)(((wCol * 32 + nt * 8 + brow) * SSTR + bcol) * 2);
                    ldsm_x2(b[nt], bBase + off);
                }
            }
            int arow = (lane & 15);
            int acol = ks + (lane >> 4) * 8;
            #pragma unroll
            for (int mt = 0; mt < 4; mt++) {
                uint32_t a[4];
                uint32_t off = (uint32_t)(((wRow * 64 + mt * 16 + arow) * SSTR + acol) * 2);
                ldsm_x4(a, aBase + off);
                #pragma unroll
                for (int nt = 0; nt < 4; nt++)
                    mma_fp16(d[mt][nt], a, b[nt]);
            }
        }
        __syncthreads();
    }

    // ---- epilogue: fp16 C write + fused attn partial dot products ----
    int mlocal = lane >> 2;
    int nlocal = (lane & 3) * 2;
    float alv[4][2], arv[4][2];
    int head;
    {
        int c0 = colBase + wCol * 32 + nlocal;
        head = c0 / O;                              // 32-col warp tile never straddles heads
        #pragma unroll
        for (int nt = 0; nt < 4; nt++) {
            int c = c0 + nt * 8 - head * O;
            alv[nt][0] = al[head * O + c]; alv[nt][1] = al[head * O + c + 1];
            arv[nt][0] = ar[head * O + c]; arv[nt][1] = ar[head * O + c + 1];
        }
    }
    #pragma unroll
    for (int mt = 0; mt < 4; mt++) {
        int row = rowBase + wRow * 64 + mt * 16 + mlocal;
        float pel0 = 0.f, per0 = 0.f, pel8 = 0.f, per8 = 0.f;
        #pragma unroll
        for (int nt = 0; nt < 4; nt++) {
            int col = colBase + wCol * 32 + nt * 8 + nlocal;
            if (row < M)
                *(__half2*)&C[(size_t)row * Nd + col] =
                    __floats2half2_rn(d[mt][nt][0], d[mt][nt][1]);
            if (row + 8 < M)
                *(__half2*)&C[(size_t)(row + 8) * Nd + col] =
                    __floats2half2_rn(d[mt][nt][2], d[mt][nt][3]);
            pel0 += d[mt][nt][0] * alv[nt][0] + d[mt][nt][1] * alv[nt][1];
            per0 += d[mt][nt][0] * arv[nt][0] + d[mt][nt][1] * arv[nt][1];
            pel8 += d[mt][nt][2] * alv[nt][0] + d[mt][nt][3] * alv[nt][1];
            per8 += d[mt][nt][2] * arv[nt][0] + d[mt][nt][3] * arv[nt][1];
        }
        #pragma unroll
        for (int o = 1; o < 4; o <<= 1) {
            pel0 += __shfl_xor_sync(0xffffffffu, pel0, o);
            per0 += __shfl_xor_sync(0xffffffffu, per0, o);
            pel8 += __shfl_xor_sync(0xffffffffu, pel8, o);
            per8 += __shfl_xor_sync(0xffffffffu, per8, o);
        }
        if ((lane & 3) == 0) {
            if (row < M) {
                atomicAdd(&el[row * HH + head], pel0);
                atomicAdd(&er[row * HH + head], per0);
            }
            if (row + 8 < M) {
                atomicAdd(&el[(row + 8) * HH + head], pel8);
                atomicAdd(&er[(row + 8) * HH + head], per8);
            }
        }
    }
}

// ---------------- warp-per-node softmax + aggregation + epilogue ---------------
template<int O>
__global__ void __launch_bounds__(256) aggw_k(
        const int* __restrict__ off0, const int* __restrict__ csr0,
        const int* __restrict__ off1, const int* __restrict__ csr1,
        const float* __restrict__ el0, const float* __restrict__ er0,
        const float* __restrict__ el1, const float* __restrict__ er1,
        const __half* __restrict__ feat0, const __half* __restrict__ feat1,
        const float* __restrict__ b0, const float* __restrict__ b1,
        float* __restrict__ out, __half* __restrict__ outH, int do_relu) {
    constexpr int WIDTH = 2 * O;
    constexpr int NV = WIDTH / 32;          // halves per lane: 16 (O=256) or 8 (O=128)
    int n = (blockIdx.x * blockDim.x + threadIdx.x) >> 5;
    if (n >= NN) return;
    int lane = threadIdx.x & 31;
    int head = lane >> 4;
    float acc[NV];
    #pragma unroll
    for (int j = 0; j < NV; j++) acc[j] = 0.f;

    #pragma unroll
    for (int rel = 0; rel < 2; rel++) {
        const int* off = rel ? off1 : off0;
        const int* csr = rel ? csr1 : csr0;
        const float* el = rel ? el1 : el0;
        const float* er = rel ? er1 : er0;
        const __half* feat = rel ? feat1 : feat0;
        int beg = off[n];
        int deg = off[n + 1] - beg;
        float ern0 = er[n * 2 + 0], ern1 = er[n * 2 + 1];
        float d0 = 0.f, d1 = 0.f;
        for (int i = lane; i < deg; i += 32) {
            int s = csr[beg + i];
            float v0 = el[s * 2 + 0] + ern0;
            float v1 = el[s * 2 + 1] + ern1;
            v0 = v0 > 0.f ? v0 : 0.2f * v0;
            v1 = v1 > 0.f ? v1 : 0.2f * v1;
            d0 += __expf(v0);
            d1 += __expf(v1);
        }
        #pragma unroll
        for (int o = 16; o; o >>= 1) {
            d0 += __shfl_xor_sync(0xffffffffu, d0, o);
            d1 += __shfl_xor_sync(0xffffffffu, d1, o);
        }
        float inv = (head ? 1.f / fmaxf(d1, 1e-9f) : 1.f / fmaxf(d0, 1e-9f));
        float ern = head ? ern1 : ern0;
        #pragma unroll 2
        for (int i = 0; i < deg; i++) {
            int s = csr[beg + i];               // uniform address -> broadcast
            float v = el[s * 2 + head] + ern;
            v = v > 0.f ? v : 0.2f * v;
            float a = __expf(v) * inv;
            const __half* fp = feat + (size_t)s * WIDTH + lane * NV;
            if (NV == 16) {
                uint4 r0 = *(const uint4*)fp;
                uint4 r1 = *(const uint4*)(fp + 8);
                float2 f;
                f = __half22float2(*(__half2*)&r0.x); acc[0] += a * f.x; acc[1] += a * f.y;
                f = __half22float2(*(__half2*)&r0.y); acc[2] += a * f.x; acc[3] += a * f.y;
                f = __half22float2(*(__half2*)&r0.z); acc[4] += a * f.x; acc[5] += a * f.y;
                f = __half22float2(*(__half2*)&r0.w); acc[6] += a * f.x; acc[7] += a * f.y;
                f = __half22float2(*(__half2*)&r1.x); acc[8] += a * f.x; acc[9] += a * f.y;
                f = __half22float2(*(__half2*)&r1.y); acc[10] += a * f.x; acc[11] += a * f.y;
                f = __half22float2(*(__half2*)&r1.z); acc[12] += a * f.x; acc[13] += a * f.y;
                f = __half22float2(*(__half2*)&r1.w); acc[14] += a * f.x; acc[15] += a * f.y;
            } else {
                uint4 r0 = *(const uint4*)fp;
                float2 f;
                f = __half22float2(*(__half2*)&r0.x); acc[0] += a * f.x; acc[1] += a * f.y;
                f = __half22float2(*(__half2*)&r0.y); acc[2] += a * f.x; acc[3] += a * f.y;
                f = __half22float2(*(__half2*)&r0.z); acc[4] += a * f.x; acc[5] += a * f.y;
                f = __half22float2(*(__half2*)&r0.w); acc[6] += a * f.x; acc[7] += a * f.y;
            }
        }
    }
    // epilogue: lane l (<16) combines its cols j=l*NV+k with lane l+16's j+O
    float other[NV];
    #pragma unroll
    for (int j = 0; j < NV; j++)
        other[j] = __shfl_down_sync(0xffffffffu, acc[j], 16);
    if (lane < 16) {
        #pragma unroll
        for (int k = 0; k < NV; k++) {
            int j = lane * NV + k;
            float v = acc[k] + other[k]
                    + b0[j] + b0[j + O] + b1[j] + b1[j + O];
            v *= 0.5f;
            if (do_relu) v = fmaxf(v, 0.f);
            if (outH) outH[(size_t)n * O + j] = __float2half_rn(v);
            else      out[(size_t)n * O + j] = v;
        }
    }
}

// ---------------- host launch ---------------------------------------------------
static float* symf(const void* s) { void* p = nullptr; cudaGetSymbolAddress(&p, s); return (float*)p; }
static int*   symi(const void* s) { void* p = nullptr; cudaGetSymbolAddress(&p, s); return (int*)p; }
static __half* symh(const void* s) { void* p = nullptr; cudaGetSymbolAddress(&p, s); return (__half*)p; }

struct Ctx {
    cudaStream_t s1, s2;
    cudaEvent_t fork1, join1a, join1b, fork2, join2;
    Ctx() {
        cudaStreamCreateWithFlags(&s1, cudaStreamNonBlocking);
        cudaStreamCreateWithFlags(&s2, cudaStreamNonBlocking);
        cudaEventCreateWithFlags(&fork1,  cudaEventDisableTiming);
        cudaEventCreateWithFlags(&join1a, cudaEventDisableTiming);
        cudaEventCreateWithFlags(&join1b, cudaEventDisableTiming);
        cudaEventCreateWithFlags(&fork2,  cudaEventDisableTiming);
        cudaEventCreateWithFlags(&join2,  cudaEventDisableTiming);
    }
};

extern "C" void kernel_launch(void* const* d_in, const int* in_sizes, int n_in,
                              void* d_out, int out_size) {
    static Ctx ctx;
    const float* x     = (const float*)d_in[0];
    const int*   src0  = (const int*)d_in[1];
    const int*   dst0  = (const int*)d_in[2];
    const int*   src1  = (const int*)d_in[3];
    const int*   dst1  = (const int*)d_in[4];
    const float* W1_0  = (const float*)d_in[5];
    const float* al1_0 = (const float*)d_in[6];
    const float* ar1_0 = (const float*)d_in[7];
    const float* b1_0  = (const float*)d_in[8];
    const float* W1_1  = (const float*)d_in[9];
    const float* al1_1 = (const float*)d_in[10];
    const float* ar1_1 = (const float*)d_in[11];
    const float* b1_1  = (const float*)d_in[12];
    const float* W2_0  = (const float*)d_in[13];
    const float* al2_0 = (const float*)d_in[14];
    const float* ar2_0 = (const float*)d_in[15];
    const float* b2_0  = (const float*)d_in[16];
    const float* W2_1  = (const float*)d_in[17];
    const float* al2_1 = (const float*)d_in[18];
    const float* ar2_1 = (const float*)d_in[19];
    const float* b2_1  = (const float*)d_in[20];
    float* out = (float*)d_out;

    __half* feat0 = symh(g_feat0);
    __half* feat1 = symh(g_feat1);
    float* el0 = symf(g_el0); float* er0 = symf(g_er0);
    float* el1 = symf(g_el1); float* er1 = symf(g_er1);
    float* el2 = symf(g_el2); float* er2 = symf(g_er2);
    float* el3 = symf(g_el3); float* er3 = symf(g_er3);
    int* deg0 = symi(g_deg0); int* deg1 = symi(g_deg1);
    int* off0 = symi(g_off0); int* off1 = symi(g_off1);
    int* pos0 = symi(g_pos0); int* pos1 = symi(g_pos1);
    int* csr0 = symi(g_csr0); int* csr1 = symi(g_csr1);
    int* bsum = symi(g_bsum);
    __half* xh = symh(g_xh);
    __half* h1 = symh(g_h1);
    __half* w1_0 = symh(g_w1_0); __half* w1_1 = symh(g_w1_1);
    __half* w2_0 = symh(g_w2_0); __half* w2_1 = symh(g_w2_1);

    cudaStream_t s1 = ctx.s1, s2 = ctx.s2;

    convX_k<<<(NN * DD + 255) / 256, 256>>>(x, xh, NN * DD);
    zeroEl_k<<<(NN * HH + 255) / 256, 256>>>(el0, er0, el1, er1, NN * HH);

    cudaEventRecord(ctx.fork1, 0);
    cudaStreamWaitEvent(s1, ctx.fork1, 0);
    cudaStreamWaitEvent(s2, ctx.fork1, 0);

    // CSR build + layer-2 el/er zero (s1, off critical path)
    zeroEl_k<<<(NN * HH + 255) / 256, 256, 0, s1>>>(el2, er2, el3, er3, NN * HH);
    zero_k<<<(NN + 255) / 256, 256, 0, s1>>>(deg0, deg1, NN);
    hist_k<<<(EE + 255) / 256, 256, 0, s1>>>(dst0, dst1, deg0, deg1);
    { dim3 g(NB, 2); scanA_k<<<g, 1024, 0, s1>>>(deg0, deg1, off0, off1, bsum); }
    scanB_k<<<1, 64, 0, s1>>>(bsum, off0, off1);
    { dim3 g(NB, 2); scanC_k<<<g, 1024, 0, s1>>>(bsum, off0, off1, pos0, pos1); }
    scat_k<<<(EE + 255) / 256, 256, 0, s1>>>(src0, dst0, src1, dst1, pos0, pos1, csr0, csr1);

    convW_k<<<(512 * 128 + 255) / 256, 256>>>(W1_0, w1_0, 128, 512);
    convW_k<<<(256 * 256 + 255) / 256, 256>>>(W2_0, w2_0, 256, 256);
    convW_k<<<(512 * 128 + 255) / 256, 256, 0, s2>>>(W1_1, w1_1, 128, 512);
    convW_k<<<(256 * 256 + 255) / 256, 256, 0, s2>>>(W2_1, w2_1, 256, 256);

    { dim3 g(4, (NN + 127) / 128);
      gemm_mma_k<128, 256><<<g, 256>>>(xh, w1_0, feat0, NN, 512,
                                       al1_0, ar1_0, el0, er0);
      gemm_mma_k<128, 256><<<g, 256, 0, s2>>>(xh, w1_1, feat1, NN, 512,
                                              al1_1, ar1_1, el1, er1); }

    cudaEventRecord(ctx.join1a, s1);
    cudaEventRecord(ctx.join1b, s2);
    cudaStreamWaitEvent(0, ctx.join1a, 0);
    cudaStreamWaitEvent(0, ctx.join1b, 0);

    aggw_k<256><<<(NN * 32 + 255) / 256, 256>>>(off0, csr0, off1, csr1,
                            el0, er0, el1, er1,
                            feat0, feat1, b1_0, b1_1, nullptr, h1, 1);

    // ---- layer 2 ----
    cudaEventRecord(ctx.fork2, 0);
    cudaStreamWaitEvent(s2, ctx.fork2, 0);
    { dim3 g(2, (NN + 127) / 128);
      gemm_mma_k<256, 128><<<g, 256>>>(h1, w2_0, feat0, NN, 256,
                                       al2_0, ar2_0, el2, er2);
      gemm_mma_k<256, 128><<<g, 256, 0, s2>>>(h1, w2_1, feat1, NN, 256,
                                              al2_1, ar2_1, el3, er3); }
    cudaEventRecord(ctx.join2, s2);
    cudaStreamWaitEvent(0, ctx.join2, 0);

    aggw_k<128><<<(NN * 32 + 255) / 256, 256>>>(off0, csr0, off1, csr1,
                            el2, er2, el3, er3,
                            feat0, feat1, b2_0, b2_1, out, nullptr, 0);
}

// round 11
// speedup vs baseline: 3.8153x; 1.0198x over previous
#include <cuda_runtime.h>
#include <cuda_fp16.h>
#include <cstdint>
#include <math.h>

#define NN   20000
#define EE   320000
#define DD   128
#define HH   2
#define NB   ((NN + 1023) / 1024)

// ---------------- scratch (device globals) ------------------------------------
__device__ __align__(16) __half g_feat0[(size_t)NN * 512];
__device__ __align__(16) __half g_feat1[(size_t)NN * 512];
__device__ float g_el0[NN * 2], g_er0[NN * 2];
__device__ float g_el1[NN * 2], g_er1[NN * 2];
__device__ float g_el2[NN * 2], g_er2[NN * 2];
__device__ float g_el3[NN * 2], g_er3[NN * 2];
__device__ int   g_deg0[NN], g_deg1[NN];
__device__ int   g_off0[NN + 1], g_off1[NN + 1];
__device__ int   g_pos0[NN], g_pos1[NN];
__device__ int   g_csr0[EE], g_csr1[EE];
__device__ int   g_bsum[64];
__device__ __align__(16) __half g_xh[(size_t)NN * DD];
__device__ __align__(16) __half g_h1[(size_t)NN * 256];
__device__ __align__(16) __half g_w1_0[512 * 128];
__device__ __align__(16) __half g_w1_1[512 * 128];
__device__ __align__(16) __half g_w2_0[256 * 256];
__device__ __align__(16) __half g_w2_1[256 * 256];

// ---------------- fused init: convX + zero el/er (all layers) + zero deg -------
__global__ void init_k(const float* __restrict__ x, __half* xh,
                       float* el0, float* er0, float* el1, float* er1,
                       float* el2, float* er2, float* el3, float* er3,
                       int* deg0, int* deg1) {
    int i = blockIdx.x * blockDim.x + threadIdx.x;
    if (i < NN * DD) xh[i] = __float2half_rn(x[i]);
    if (i < NN * HH) {
        el0[i] = 0.f; er0[i] = 0.f; el1[i] = 0.f; er1[i] = 0.f;
        el2[i] = 0.f; er2[i] = 0.f; el3[i] = 0.f; er3[i] = 0.f;
    }
    if (i < NN) { deg0[i] = 0; deg1[i] = 0; }
}

// ---------------- CSR build -----------------------------------------------------
__global__ void hist_k(const int* __restrict__ dst0, const int* __restrict__ dst1,
                       int* deg0, int* deg1) {
    int i = blockIdx.x * blockDim.x + threadIdx.x;
    if (i < EE) {
        atomicAdd(&deg0[dst0[i]], 1);
        atomicAdd(&deg1[dst1[i]], 1);
    }
}
__global__ void scanA_k(const int* __restrict__ deg0, const int* __restrict__ deg1,
                        int* off0, int* off1, int* bsum) {
    const int* deg = blockIdx.y ? deg1 : deg0;
    int* off = blockIdx.y ? off1 : off0;
    int i = blockIdx.x * 1024 + threadIdx.x;
    int lane = threadIdx.x & 31, wid = threadIdx.x >> 5;
    int v = (i < NN) ? deg[i] : 0;
    int x = v;
    #pragma unroll
    for (int o = 1; o < 32; o <<= 1) {
        int t = __shfl_up_sync(0xffffffffu, x, o);
        if (lane >= o) x += t;
    }
    __shared__ int wsum[32];
    if (lane == 31) wsum[wid] = x;
    __syncthreads();
    if (wid == 0) {
        int w = wsum[lane];
        #pragma unroll
        for (int o = 1; o < 32; o <<= 1) {
            int t = __shfl_up_sync(0xffffffffu, w, o);
            if (lane >= o) w += t;
        }
        wsum[lane] = w;
    }
    __syncthreads();
    int inc = x + (wid ? wsum[wid - 1] : 0);
    if (i < NN) off[i] = inc - v;
    if (threadIdx.x == 1023) bsum[blockIdx.y * 32 + blockIdx.x] = inc;
}
__global__ void scanB_k(int* bsum, int* off0, int* off1) {
    int y = threadIdx.x >> 5, lane = threadIdx.x & 31;
    int v = (lane < NB) ? bsum[y * 32 + lane] : 0;
    int x = v;
    #pragma unroll
    for (int o = 1; o < 32; o <<= 1) {
        int t = __shfl_up_sync(0xffffffffu, x, o);
        if (lane >= o) x += t;
    }
    if (lane < NB) bsum[y * 32 + lane] = x - v;
    if (lane == NB - 1) { int* off = y ? off1 : off0; off[NN] = x; }
}
__global__ void scanC_k(const int* __restrict__ bsum, int* off0, int* off1,
                        int* pos0, int* pos1) {
    int i = blockIdx.x * 1024 + threadIdx.x;
    if (i >= NN) return;
    int y = blockIdx.y;
    int* off = y ? off1 : off0;
    int* pos = y ? pos1 : pos0;
    int val = off[i] + bsum[y * 32 + blockIdx.x];
    off[i] = val; pos[i] = val;
}
__global__ void scat_k(const int* __restrict__ src0, const int* __restrict__ dst0,
                       const int* __restrict__ src1, const int* __restrict__ dst1,
                       int* pos0, int* pos1, int* csr0, int* csr1) {
    int i = blockIdx.x * blockDim.x + threadIdx.x;
    if (i < EE) {
        csr0[atomicAdd(&pos0[dst0[i]], 1)] = src0[i];
        csr1[atomicAdd(&pos1[dst1[i]], 1)] = src1[i];
    }
}

// ---------------- merged weight transpose (all 4 weights, 65536 elems each) ----
__global__ void convW4_k(const float* __restrict__ Wa, const float* __restrict__ Wb,
                         const float* __restrict__ Wc, const float* __restrict__ Wd,
                         __half* da, __half* db, __half* dc, __half* dd) {
    int which = blockIdx.y;
    const float* W = which == 0 ? Wa : which == 1 ? Wb : which == 2 ? Wc : Wd;
    __half* dst     = which == 0 ? da : which == 1 ? db : which == 2 ? dc : dd;
    int K  = (which < 2) ? 128 : 256;
    int Nd = (which < 2) ? 512 : 256;
    int i = blockIdx.x * blockDim.x + threadIdx.x;   // 65536 total
    int n = i / K, k = i % K;
    dst[i] = __float2half_rn(W[(size_t)k * Nd + n]);
}

// ---------------- mma.sync helpers ---------------------------------------------
__device__ __forceinline__ uint32_t smem_u32(const void* p) {
    uint32_t a;
    asm("{ .reg .u64 t; cvta.to.shared.u64 t, %1; cvt.u32.u64 %0, t; }" : "=r"(a) : "l"(p));
    return a;
}
__device__ __forceinline__ void ldsm_x4(uint32_t* r, uint32_t addr) {
    asm volatile("ldmatrix.sync.aligned.m8n8.x4.shared.b16 {%0,%1,%2,%3}, [%4];"
                 : "=r"(r[0]), "=r"(r[1]), "=r"(r[2]), "=r"(r[3]) : "r"(addr));
}
__device__ __forceinline__ void ldsm_x2(uint32_t* r, uint32_t addr) {
    asm volatile("ldmatrix.sync.aligned.m8n8.x2.shared.b16 {%0,%1}, [%2];"
                 : "=r"(r[0]), "=r"(r[1]) : "r"(addr));
}
__device__ __forceinline__ void mma_fp16(float* d, const uint32_t* a, const uint32_t* b) {
    asm volatile(
        "mma.sync.aligned.m16n8k16.row.col.f32.f16.f16.f32 "
        "{%0,%1,%2,%3}, {%4,%5,%6,%7}, {%8,%9}, {%0,%1,%2,%3};"
        : "+f"(d[0]), "+f"(d[1]), "+f"(d[2]), "+f"(d[3])
        : "r"(a[0]), "r"(a[1]), "r"(a[2]), "r"(a[3]), "r"(b[0]), "r"(b[1]));
}

// ---------------- tensor-core fp16 GEMM, both relations in one launch ----------
// blockIdx.z = relation. C = A * W^T, fp32 accum, fp16 out, fused attn epilogue.
#define SSTR 40
__device__ __forceinline__ void load_chunk(const __half* __restrict__ g,
        int ld, int rbase, int kofs, __half* s, int rlim, int tid) {
    #pragma unroll
    for (int i = 0; i < 2; i++) {
        int id = tid + i * 256;
        int r = id >> 2;
        int c = (id & 3) * 8;
        uint4 v = make_uint4(0u, 0u, 0u, 0u);
        int gr = rbase + r;
        if (gr < rlim)
            v = *(const uint4*)(g + (size_t)gr * ld + kofs + c);
        *(uint4*)(s + r * SSTR + c) = v;
    }
}

template<int KTOT, int O>
__global__ void __launch_bounds__(256) gemm_mma_k(
        const __half* __restrict__ A,
        const __half* __restrict__ W0, const __half* __restrict__ W1,
        __half* __restrict__ C0, __half* __restrict__ C1,
        const float* __restrict__ al0, const float* __restrict__ ar0,
        const float* __restrict__ al1, const float* __restrict__ ar1,
        float* __restrict__ elA, float* __restrict__ erA,
        float* __restrict__ elB, float* __restrict__ erB,
        int M, int Nd) {
    const int rel = blockIdx.z;
    const __half* B = rel ? W1 : W0;
    __half* C = rel ? C1 : C0;
    const float* al = rel ? al1 : al0;
    const float* ar = rel ? ar1 : ar0;
    float* el = rel ? elB : elA;
    float* er = rel ? erB : erA;

    __shared__ __align__(16) __half sA[128 * SSTR];
    __shared__ __align__(16) __half sB[128 * SSTR];
    const int tid = threadIdx.x;
    const int w = tid >> 5;
    const int lane = tid & 31;
    const int rowBase = blockIdx.y * 128;
    const int colBase = blockIdx.x * 128;
    const int wRow = w >> 2;
    const int wCol = w & 3;

    uint32_t aBase = smem_u32(sA);
    uint32_t bBase = smem_u32(sB);

    float d[4][4][4];
    #pragma unroll
    for (int i = 0; i < 4; i++)
        #pragma unroll
        for (int j = 0; j < 4; j++)
            #pragma unroll
            for (int q = 0; q < 4; q++) d[i][j][q] = 0.f;

    constexpr int NKC = KTOT / 32;
    for (int kc = 0; kc < NKC; kc++) {
        load_chunk(A, KTOT, rowBase, kc * 32, sA, M, tid);
        load_chunk(B, KTOT, colBase, kc * 32, sB, 1 << 30, tid);
        __syncthreads();
        #pragma unroll
        for (int ks = 0; ks < 32; ks += 16) {
            uint32_t b[4][2];
            {
                int brow = (lane & 7);
                int bcol = ks + ((lane >> 3) & 1) * 8;
                #pragma unroll
                for (int nt = 0; nt < 4; nt++) {
                    uint32_t off = (uint32_t)(((wCol * 32 + nt * 8 + brow) * SSTR + bcol) * 2);
                    ldsm_x2(b[nt], bBase + off);
                }
            }
            int arow = (lane & 15);
            int acol = ks + (lane >> 4) * 8;
            #pragma unroll
            for (int mt = 0; mt < 4; mt++) {
                uint32_t a[4];
                uint32_t off = (uint32_t)(((wRow * 64 + mt * 16 + arow) * SSTR + acol) * 2);
                ldsm_x4(a, aBase + off);
                #pragma unroll
                for (int nt = 0; nt < 4; nt++)
                    mma_fp16(d[mt][nt], a, b[nt]);
            }
        }
        __syncthreads();
    }

    // ---- epilogue: fp16 C write + fused attn partial dot products ----
    int mlocal = lane >> 2;
    int nlocal = (lane & 3) * 2;
    float alv[4][2], arv[4][2];
    int head;
    {
        int c0 = colBase + wCol * 32 + nlocal;
        head = c0 / O;                              // 32-col warp tile never straddles heads
        #pragma unroll
        for (int nt = 0; nt < 4; nt++) {
            int c = c0 + nt * 8 - head * O;
            alv[nt][0] = al[head * O + c]; alv[nt][1] = al[head * O + c + 1];
            arv[nt][0] = ar[head * O + c]; arv[nt][1] = ar[head * O + c + 1];
        }
    }
    #pragma unroll
    for (int mt = 0; mt < 4; mt++) {
        int row = rowBase + wRow * 64 + mt * 16 + mlocal;
        float pel0 = 0.f, per0 = 0.f, pel8 = 0.f, per8 = 0.f;
        #pragma unroll
        for (int nt = 0; nt < 4; nt++) {
            int col = colBase + wCol * 32 + nt * 8 + nlocal;
            if (row < M)
                *(__half2*)&C[(size_t)row * Nd + col] =
                    __floats2half2_rn(d[mt][nt][0], d[mt][nt][1]);
            if (row + 8 < M)
                *(__half2*)&C[(size_t)(row + 8) * Nd + col] =
                    __floats2half2_rn(d[mt][nt][2], d[mt][nt][3]);
            pel0 += d[mt][nt][0] * alv[nt][0] + d[mt][nt][1] * alv[nt][1];
            per0 += d[mt][nt][0] * arv[nt][0] + d[mt][nt][1] * arv[nt][1];
            pel8 += d[mt][nt][2] * alv[nt][0] + d[mt][nt][3] * alv[nt][1];
            per8 += d[mt][nt][2] * arv[nt][0] + d[mt][nt][3] * arv[nt][1];
        }
        #pragma unroll
        for (int o = 1; o < 4; o <<= 1) {
            pel0 += __shfl_xor_sync(0xffffffffu, pel0, o);
            per0 += __shfl_xor_sync(0xffffffffu, per0, o);
            pel8 += __shfl_xor_sync(0xffffffffu, pel8, o);
            per8 += __shfl_xor_sync(0xffffffffu, per8, o);
        }
        if ((lane & 3) == 0) {
            if (row < M) {
                atomicAdd(&el[row * HH + head], pel0);
                atomicAdd(&er[row * HH + head], per0);
            }
            if (row + 8 < M) {
                atomicAdd(&el[(row + 8) * HH + head], pel8);
                atomicAdd(&er[(row + 8) * HH + head], per8);
            }
        }
    }
}

// ---------------- warp-per-node softmax + aggregation + epilogue ---------------
template<int O>
__global__ void __launch_bounds__(256) aggw_k(
        const int* __restrict__ off0, const int* __restrict__ csr0,
        const int* __restrict__ off1, const int* __restrict__ csr1,
        const float* __restrict__ el0, const float* __restrict__ er0,
        const float* __restrict__ el1, const float* __restrict__ er1,
        const __half* __restrict__ feat0, const __half* __restrict__ feat1,
        const float* __restrict__ b0, const float* __restrict__ b1,
        float* __restrict__ out, __half* __restrict__ outH, int do_relu) {
    constexpr int WIDTH = 2 * O;
    constexpr int NV = WIDTH / 32;          // halves per lane: 16 (O=256) or 8 (O=128)
    int n = (blockIdx.x * blockDim.x + threadIdx.x) >> 5;
    if (n >= NN) return;
    int lane = threadIdx.x & 31;
    int head = lane >> 4;
    float acc[NV];
    #pragma unroll
    for (int j = 0; j < NV; j++) acc[j] = 0.f;

    #pragma unroll
    for (int rel = 0; rel < 2; rel++) {
        const int* off = rel ? off1 : off0;
        const int* csr = rel ? csr1 : csr0;
        const float* el = rel ? el1 : el0;
        const float* er = rel ? er1 : er0;
        const __half* feat = rel ? feat1 : feat0;
        int beg = off[n];
        int deg = off[n + 1] - beg;
        float ern0 = er[n * 2 + 0], ern1 = er[n * 2 + 1];
        float d0 = 0.f, d1 = 0.f;
        for (int i = lane; i < deg; i += 32) {
            int s = csr[beg + i];
            float v0 = el[s * 2 + 0] + ern0;
            float v1 = el[s * 2 + 1] + ern1;
            v0 = v0 > 0.f ? v0 : 0.2f * v0;
            v1 = v1 > 0.f ? v1 : 0.2f * v1;
            d0 += __expf(v0);
            d1 += __expf(v1);
        }
        #pragma unroll
        for (int o = 16; o; o >>= 1) {
            d0 += __shfl_xor_sync(0xffffffffu, d0, o);
            d1 += __shfl_xor_sync(0xffffffffu, d1, o);
        }
        float inv = (head ? 1.f / fmaxf(d1, 1e-9f) : 1.f / fmaxf(d0, 1e-9f));
        float ern = head ? ern1 : ern0;
        #pragma unroll 2
        for (int i = 0; i < deg; i++) {
            int s = csr[beg + i];               // uniform address -> broadcast
            float v = el[s * 2 + head] + ern;
            v = v > 0.f ? v : 0.2f * v;
            float a = __expf(v) * inv;
            const __half* fp = feat + (size_t)s * WIDTH + lane * NV;
            if (NV == 16) {
                uint4 r0 = *(const uint4*)fp;
                uint4 r1 = *(const uint4*)(fp + 8);
                float2 f;
                f = __half22float2(*(__half2*)&r0.x); acc[0] += a * f.x; acc[1] += a * f.y;
                f = __half22float2(*(__half2*)&r0.y); acc[2] += a * f.x; acc[3] += a * f.y;
                f = __half22float2(*(__half2*)&r0.z); acc[4] += a * f.x; acc[5] += a * f.y;
                f = __half22float2(*(__half2*)&r0.w); acc[6] += a * f.x; acc[7] += a * f.y;
                f = __half22float2(*(__half2*)&r1.x); acc[8] += a * f.x; acc[9] += a * f.y;
                f = __half22float2(*(__half2*)&r1.y); acc[10] += a * f.x; acc[11] += a * f.y;
                f = __half22float2(*(__half2*)&r1.z); acc[12] += a * f.x; acc[13] += a * f.y;
                f = __half22float2(*(__half2*)&r1.w); acc[14] += a * f.x; acc[15] += a * f.y;
            } else {
                uint4 r0 = *(const uint4*)fp;
                float2 f;
                f = __half22float2(*(__half2*)&r0.x); acc[0] += a * f.x; acc[1] += a * f.y;
                f = __half22float2(*(__half2*)&r0.y); acc[2] += a * f.x; acc[3] += a * f.y;
                f = __half22float2(*(__half2*)&r0.z); acc[4] += a * f.x; acc[5] += a * f.y;
                f = __half22float2(*(__half2*)&r0.w); acc[6] += a * f.x; acc[7] += a * f.y;
            }
        }
    }
    // epilogue: lane l (<16) combines its cols j=l*NV+k with lane l+16's j+O
    float other[NV];
    #pragma unroll
    for (int j = 0; j < NV; j++)
        other[j] = __shfl_down_sync(0xffffffffu, acc[j], 16);
    if (lane < 16) {
        #pragma unroll
        for (int k = 0; k < NV; k++) {
            int j = lane * NV + k;
            float v = acc[k] + other[k]
                    + b0[j] + b0[j + O] + b1[j] + b1[j + O];
            v *= 0.5f;
            if (do_relu) v = fmaxf(v, 0.f);
            if (outH) outH[(size_t)n * O + j] = __float2half_rn(v);
            else      out[(size_t)n * O + j] = v;
        }
    }
}

// ---------------- host launch ---------------------------------------------------
static float* symf(const void* s) { void* p = nullptr; cudaGetSymbolAddress(&p, s); return (float*)p; }
static int*   symi(const void* s) { void* p = nullptr; cudaGetSymbolAddress(&p, s); return (int*)p; }
static __half* symh(const void* s) { void* p = nullptr; cudaGetSymbolAddress(&p, s); return (__half*)p; }

struct Ctx {
    cudaStream_t s1;
    cudaEvent_t fork1, join1;
    Ctx() {
        cudaStreamCreateWithFlags(&s1, cudaStreamNonBlocking);
        cudaEventCreateWithFlags(&fork1, cudaEventDisableTiming);
        cudaEventCreateWithFlags(&join1, cudaEventDisableTiming);
    }
};

extern "C" void kernel_launch(void* const* d_in, const int* in_sizes, int n_in,
                              void* d_out, int out_size) {
    static Ctx ctx;
    const float* x     = (const float*)d_in[0];
    const int*   src0  = (const int*)d_in[1];
    const int*   dst0  = (const int*)d_in[2];
    const int*   src1  = (const int*)d_in[3];
    const int*   dst1  = (const int*)d_in[4];
    const float* W1_0  = (const float*)d_in[5];
    const float* al1_0 = (const float*)d_in[6];
    const float* ar1_0 = (const float*)d_in[7];
    const float* b1_0  = (const float*)d_in[8];
    const float* W1_1  = (const float*)d_in[9];
    const float* al1_1 = (const float*)d_in[10];
    const float* ar1_1 = (const float*)d_in[11];
    const float* b1_1  = (const float*)d_in[12];
    const float* W2_0  = (const float*)d_in[13];
    const float* al2_0 = (const float*)d_in[14];
    const float* ar2_0 = (const float*)d_in[15];
    const float* b2_0  = (const float*)d_in[16];
    const float* W2_1  = (const float*)d_in[17];
    const float* al2_1 = (const float*)d_in[18];
    const float* ar2_1 = (const float*)d_in[19];
    const float* b2_1  = (const float*)d_in[20];
    float* out = (float*)d_out;

    __half* feat0 = symh(g_feat0);
    __half* feat1 = symh(g_feat1);
    float* el0 = symf(g_el0); float* er0 = symf(g_er0);
    float* el1 = symf(g_el1); float* er1 = symf(g_er1);
    float* el2 = symf(g_el2); float* er2 = symf(g_er2);
    float* el3 = symf(g_el3); float* er3 = symf(g_er3);
    int* deg0 = symi(g_deg0); int* deg1 = symi(g_deg1);
    int* off0 = symi(g_off0); int* off1 = symi(g_off1);
    int* pos0 = symi(g_pos0); int* pos1 = symi(g_pos1);
    int* csr0 = symi(g_csr0); int* csr1 = symi(g_csr1);
    int* bsum = symi(g_bsum);
    __half* xh = symh(g_xh);
    __half* h1 = symh(g_h1);
    __half* w1_0 = symh(g_w1_0); __half* w1_1 = symh(g_w1_1);
    __half* w2_0 = symh(g_w2_0); __half* w2_1 = symh(g_w2_1);

    cudaStream_t s1 = ctx.s1;

    // fused init: convX + zero all el/er + zero deg
    init_k<<<(NN * DD + 255) / 256, 256>>>(x, xh, el0, er0, el1, er1,
                                           el2, er2, el3, er3, deg0, deg1);

    // fork: CSR build on s1, compute chain on default stream
    cudaEventRecord(ctx.fork1, 0);
    cudaStreamWaitEvent(s1, ctx.fork1, 0);

    hist_k<<<(EE + 255) / 256, 256, 0, s1>>>(dst0, dst1, deg0, deg1);
    { dim3 g(NB, 2); scanA_k<<<g, 1024, 0, s1>>>(deg0, deg1, off0, off1, bsum); }
    scanB_k<<<1, 64, 0, s1>>>(bsum, off0, off1);
    { dim3 g(NB, 2); scanC_k<<<g, 1024, 0, s1>>>(bsum, off0, off1, pos0, pos1); }
    scat_k<<<(EE + 255) / 256, 256, 0, s1>>>(src0, dst0, src1, dst1, pos0, pos1, csr0, csr1);
    cudaEventRecord(ctx.join1, s1);

    // all 4 weight transposes in one launch
    { dim3 g(65536 / 256, 4);
      convW4_k<<<g, 256>>>(W1_0, W1_1, W2_0, W2_1, w1_0, w1_1, w2_0, w2_1); }

    // layer-1 GEMM, both relations in one launch (attn fused into epilogue)
    { dim3 g(4, (NN + 127) / 128, 2);
      gemm_mma_k<128, 256><<<g, 256>>>(xh, w1_0, w1_1, feat0, feat1,
                                       al1_0, ar1_0, al1_1, ar1_1,
                                       el0, er0, el1, er1, NN, 512); }

    cudaStreamWaitEvent(0, ctx.join1, 0);   // CSR ready

    aggw_k<256><<<(NN * 32 + 255) / 256, 256>>>(off0, csr0, off1, csr1,
                            el0, er0, el1, er1,
                            feat0, feat1, b1_0, b1_1, nullptr, h1, 1);

    // layer-2 GEMM, both relations in one launch
    { dim3 g(2, (NN + 127) / 128, 2);
      gemm_mma_k<256, 128><<<g, 256>>>(h1, w2_0, w2_1, feat0, feat1,
                                       al2_0, ar2_0, al2_1, ar2_1,
                                       el2, er2, el3, er3, NN, 256); }

    aggw_k<128><<<(NN * 32 + 255) / 256, 256>>>(off0, csr0, off1, csr1,
                            el2, er2, el3, er3,
                            feat0, feat1, b2_0, b2_1, out, nullptr, 0);
}

// round 13
// speedup vs baseline: 3.9815x; 1.0436x over previous
#include <cuda_runtime.h>
#include <cuda_fp16.h>
#include <cstdint>
#include <math.h>

#define NN   20000
#define EE   320000
#define DD   128
#define HH   2
#define NB   ((NN + 1023) / 1024)

// ---------------- scratch (device globals) ------------------------------------
__device__ __align__(16) __half g_feat0[(size_t)NN * 512];
__device__ __align__(16) __half g_feat1[(size_t)NN * 512];
__device__ float g_el0[NN * 2], g_er0[NN * 2];
__device__ float g_el1[NN * 2], g_er1[NN * 2];
__device__ float g_el2[NN * 2], g_er2[NN * 2];
__device__ float g_el3[NN * 2], g_er3[NN * 2];
__device__ int   g_deg0[NN], g_deg1[NN];
__device__ int   g_off0[NN + 1], g_off1[NN + 1];
__device__ int   g_pos0[NN], g_pos1[NN];
__device__ int   g_csr0[EE], g_csr1[EE];
__device__ int   g_bsum[64];
__device__ __align__(16) __half g_xh[(size_t)NN * DD];
__device__ __align__(16) __half g_h1[(size_t)NN * 256];
__device__ __align__(16) __half g_w1_0[512 * 128];
__device__ __align__(16) __half g_w1_1[512 * 128];
__device__ __align__(16) __half g_w2_0[256 * 256];
__device__ __align__(16) __half g_w2_1[256 * 256];

// ---------------- fused init: convX + zero el/er (all layers) + zero deg -------
__global__ void init_k(const float* __restrict__ x, __half* xh,
                       float* el0, float* er0, float* el1, float* er1,
                       float* el2, float* er2, float* el3, float* er3,
                       int* deg0, int* deg1) {
    int i = blockIdx.x * blockDim.x + threadIdx.x;
    if (i < NN * DD) xh[i] = __float2half_rn(x[i]);
    if (i < NN * HH) {
        el0[i] = 0.f; er0[i] = 0.f; el1[i] = 0.f; er1[i] = 0.f;
        el2[i] = 0.f; er2[i] = 0.f; el3[i] = 0.f; er3[i] = 0.f;
    }
    if (i < NN) { deg0[i] = 0; deg1[i] = 0; }
}

// ---------------- CSR build -----------------------------------------------------
__global__ void hist_k(const int* __restrict__ dst0, const int* __restrict__ dst1,
                       int* deg0, int* deg1) {
    int i = blockIdx.x * blockDim.x + threadIdx.x;
    if (i < EE) {
        atomicAdd(&deg0[dst0[i]], 1);
        atomicAdd(&deg1[dst1[i]], 1);
    }
}
__global__ void scanA_k(const int* __restrict__ deg0, const int* __restrict__ deg1,
                        int* off0, int* off1, int* bsum) {
    const int* deg = blockIdx.y ? deg1 : deg0;
    int* off = blockIdx.y ? off1 : off0;
    int i = blockIdx.x * 1024 + threadIdx.x;
    int lane = threadIdx.x & 31, wid = threadIdx.x >> 5;
    int v = (i < NN) ? deg[i] : 0;
    int x = v;
    #pragma unroll
    for (int o = 1; o < 32; o <<= 1) {
        int t = __shfl_up_sync(0xffffffffu, x, o);
        if (lane >= o) x += t;
    }
    __shared__ int wsum[32];
    if (lane == 31) wsum[wid] = x;
    __syncthreads();
    if (wid == 0) {
        int w = wsum[lane];
        #pragma unroll
        for (int o = 1; o < 32; o <<= 1) {
            int t = __shfl_up_sync(0xffffffffu, w, o);
            if (lane >= o) w += t;
        }
        wsum[lane] = w;
    }
    __syncthreads();
    int inc = x + (wid ? wsum[wid - 1] : 0);
    if (i < NN) off[i] = inc - v;
    if (threadIdx.x == 1023) bsum[blockIdx.y * 32 + blockIdx.x] = inc;
}
__global__ void scanB_k(int* bsum, int* off0, int* off1) {
    int y = threadIdx.x >> 5, lane = threadIdx.x & 31;
    int v = (lane < NB) ? bsum[y * 32 + lane] : 0;
    int x = v;
    #pragma unroll
    for (int o = 1; o < 32; o <<= 1) {
        int t = __shfl_up_sync(0xffffffffu, x, o);
        if (lane >= o) x += t;
    }
    if (lane < NB) bsum[y * 32 + lane] = x - v;
    if (lane == NB - 1) { int* off = y ? off1 : off0; off[NN] = x; }
}
__global__ void scanC_k(const int* __restrict__ bsum, int* off0, int* off1,
                        int* pos0, int* pos1) {
    int i = blockIdx.x * 1024 + threadIdx.x;
    if (i >= NN) return;
    int y = blockIdx.y;
    int* off = y ? off1 : off0;
    int* pos = y ? pos1 : pos0;
    int val = off[i] + bsum[y * 32 + blockIdx.x];
    off[i] = val; pos[i] = val;
}
__global__ void scat_k(const int* __restrict__ src0, const int* __restrict__ dst0,
                       const int* __restrict__ src1, const int* __restrict__ dst1,
                       int* pos0, int* pos1, int* csr0, int* csr1) {
    int i = blockIdx.x * blockDim.x + threadIdx.x;
    if (i < EE) {
        csr0[atomicAdd(&pos0[dst0[i]], 1)] = src0[i];
        csr1[atomicAdd(&pos1[dst1[i]], 1)] = src1[i];
    }
}

// ---------------- merged weight transpose (all 4 weights, 65536 elems each) ----
__global__ void convW4_k(const float* __restrict__ Wa, const float* __restrict__ Wb,
                         const float* __restrict__ Wc, const float* __restrict__ Wd,
                         __half* da, __half* db, __half* dc, __half* dd) {
    int which = blockIdx.y;
    const float* W = which == 0 ? Wa : which == 1 ? Wb : which == 2 ? Wc : Wd;
    __half* dst     = which == 0 ? da : which == 1 ? db : which == 2 ? dc : dd;
    int K  = (which < 2) ? 128 : 256;
    int Nd = (which < 2) ? 512 : 256;
    int i = blockIdx.x * blockDim.x + threadIdx.x;   // 65536 total
    int n = i / K, k = i % K;
    dst[i] = __float2half_rn(W[(size_t)k * Nd + n]);
}

// ---------------- mma.sync / cp.async helpers -----------------------------------
__device__ __forceinline__ uint32_t smem_u32(const void* p) {
    uint32_t a;
    asm("{ .reg .u64 t; cvta.to.shared.u64 t, %1; cvt.u32.u64 %0, t; }" : "=r"(a) : "l"(p));
    return a;
}
__device__ __forceinline__ void ldsm_x4(uint32_t* r, uint32_t addr) {
    asm volatile("ldmatrix.sync.aligned.m8n8.x4.shared.b16 {%0,%1,%2,%3}, [%4];"
                 : "=r"(r[0]), "=r"(r[1]), "=r"(r[2]), "=r"(r[3]) : "r"(addr));
}
__device__ __forceinline__ void ldsm_x2(uint32_t* r, uint32_t addr) {
    asm volatile("ldmatrix.sync.aligned.m8n8.x2.shared.b16 {%0,%1}, [%2];"
                 : "=r"(r[0]), "=r"(r[1]) : "r"(addr));
}
__device__ __forceinline__ void mma_fp16(float* d, const uint32_t* a, const uint32_t* b) {
    asm volatile(
        "mma.sync.aligned.m16n8k16.row.col.f32.f16.f16.f32 "
        "{%0,%1,%2,%3}, {%4,%5,%6,%7}, {%8,%9}, {%0,%1,%2,%3};"
        : "+f"(d[0]), "+f"(d[1]), "+f"(d[2]), "+f"(d[3])
        : "r"(a[0]), "r"(a[1]), "r"(a[2]), "r"(a[3]), "r"(b[0]), "r"(b[1]));
}
__device__ __forceinline__ void cp16(uint32_t dst, const void* src, bool valid) {
    int sz = valid ? 16 : 0;
    asm volatile("cp.async.cg.shared.global [%0], [%1], 16, %2;"
                 :: "r"(dst), "l"(src), "r"(sz));
}

// ---------------- tensor-core fp16 GEMM, cp.async double-buffered --------------
// blockIdx.z = relation. C = A * W^T, fp32 accum, fp16 out, fused attn epilogue.
#define SSTR 40
__device__ __forceinline__ void load_chunk_async(const __half* __restrict__ g,
        int ld, int rbase, int kofs, uint32_t sbase, int rlim, int tid) {
    #pragma unroll
    for (int i = 0; i < 2; i++) {
        int id = tid + i * 256;
        int r = id >> 2;
        int c = (id & 3) * 8;
        int gr = rbase + r;
        bool valid = gr < rlim;
        const __half* src = g + (size_t)(valid ? gr : 0) * ld + kofs + c;
        cp16(sbase + (uint32_t)(r * SSTR + c) * 2, src, valid);
    }
}

template<int KTOT, int O>
__global__ void __launch_bounds__(256) gemm_mma_k(
        const __half* __restrict__ A,
        const __half* __restrict__ W0, const __half* __restrict__ W1,
        __half* __restrict__ C0, __half* __restrict__ C1,
        const float* __restrict__ al0, const float* __restrict__ ar0,
        const float* __restrict__ al1, const float* __restrict__ ar1,
        float* __restrict__ elA, float* __restrict__ erA,
        float* __restrict__ elB, float* __restrict__ erB,
        int M, int Nd) {
    const int rel = blockIdx.z;
    const __half* B = rel ? W1 : W0;
    __half* C = rel ? C1 : C0;
    const float* al = rel ? al1 : al0;
    const float* ar = rel ? ar1 : ar0;
    float* el = rel ? elB : elA;
    float* er = rel ? erB : erA;

    __shared__ __align__(16) __half sA[2][128 * SSTR];
    __shared__ __align__(16) __half sB[2][128 * SSTR];
    const int tid = threadIdx.x;
    const int w = tid >> 5;
    const int lane = tid & 31;
    const int rowBase = blockIdx.y * 128;
    const int colBase = blockIdx.x * 128;
    const int wRow = w >> 2;
    const int wCol = w & 3;

    uint32_t aBase[2] = { smem_u32(sA[0]), smem_u32(sA[1]) };
    uint32_t bBase[2] = { smem_u32(sB[0]), smem_u32(sB[1]) };

    float d[4][4][4];
    #pragma unroll
    for (int i = 0; i < 4; i++)
        #pragma unroll
        for (int j = 0; j < 4; j++)
            #pragma unroll
            for (int q = 0; q < 4; q++) d[i][j][q] = 0.f;

    constexpr int NKC = KTOT / 32;
    // prologue: chunk 0 into buffer 0
    load_chunk_async(A, KTOT, rowBase, 0, aBase[0], M, tid);
    load_chunk_async(B, KTOT, colBase, 0, bBase[0], 1 << 30, tid);
    asm volatile("cp.async.commit_group;");
    asm volatile("cp.async.wait_group 0;");
    __syncthreads();

    int buf = 0;
    for (int kc = 0; kc < NKC; kc++) {
        bool more = (kc + 1) < NKC;
        if (more) {
            load_chunk_async(A, KTOT, rowBase, (kc + 1) * 32, aBase[buf ^ 1], M, tid);
            load_chunk_async(B, KTOT, colBase, (kc + 1) * 32, bBase[buf ^ 1], 1 << 30, tid);
            asm volatile("cp.async.commit_group;");
        }
        #pragma unroll
        for (int ks = 0; ks < 32; ks += 16) {
            uint32_t b[4][2];
            {
                int brow = (lane & 7);
                int bcol = ks + ((lane >> 3) & 1) * 8;
                #pragma unroll
                for (int nt = 0; nt < 4; nt++) {
                    uint32_t off = (uint32_t)(((wCol * 32 + nt * 8 + brow) * SSTR + bcol) * 2);
                    ldsm_x2(b[nt], bBase[buf] + off);
                }
            }
            int arow = (lane & 15);
            int acol = ks + (lane >> 4) * 8;
            #pragma unroll
            for (int mt = 0; mt < 4; mt++) {
                uint32_t a[4];
                uint32_t off = (uint32_t)(((wRow * 64 + mt * 16 + arow) * SSTR + acol) * 2);
                ldsm_x4(a, aBase[buf] + off);
                #pragma unroll
                for (int nt = 0; nt < 4; nt++)
                    mma_fp16(d[mt][nt], a, b[nt]);
            }
        }
        if (more) {
            asm volatile("cp.async.wait_group 0;");
            __syncthreads();
            buf ^= 1;
        }
    }

    // ---- epilogue: fp16 C write + fused attn partial dot products ----
    int mlocal = lane >> 2;
    int nlocal = (lane & 3) * 2;
    float alv[4][2], arv[4][2];
    int head;
    {
        int c0 = colBase + wCol * 32 + nlocal;
        head = c0 / O;                              // 32-col warp tile never straddles heads
        #pragma unroll
        for (int nt = 0; nt < 4; nt++) {
            int c = c0 + nt * 8 - head * O;
            alv[nt][0] = al[head * O + c]; alv[nt][1] = al[head * O + c + 1];
            arv[nt][0] = ar[head * O + c]; arv[nt][1] = ar[head * O + c + 1];
        }
    }
    #pragma unroll
    for (int mt = 0; mt < 4; mt++) {
        int row = rowBase + wRow * 64 + mt * 16 + mlocal;
        float pel0 = 0.f, per0 = 0.f, pel8 = 0.f, per8 = 0.f;
        #pragma unroll
        for (int nt = 0; nt < 4; nt++) {
            int col = colBase + wCol * 32 + nt * 8 + nlocal;
            if (row < M)
                *(__half2*)&C[(size_t)row * Nd + col] =
                    __floats2half2_rn(d[mt][nt][0], d[mt][nt][1]);
            if (row + 8 < M)
                *(__half2*)&C[(size_t)(row + 8) * Nd + col] =
                    __floats2half2_rn(d[mt][nt][2], d[mt][nt][3]);
            pel0 += d[mt][nt][0] * alv[nt][0] + d[mt][nt][1] * alv[nt][1];
            per0 += d[mt][nt][0] * arv[nt][0] + d[mt][nt][1] * arv[nt][1];
            pel8 += d[mt][nt][2] * alv[nt][0] + d[mt][nt][3] * alv[nt][1];
            per8 += d[mt][nt][2] * arv[nt][0] + d[mt][nt][3] * arv[nt][1];
        }
        #pragma unroll
        for (int o = 1; o < 4; o <<= 1) {
            pel0 += __shfl_xor_sync(0xffffffffu, pel0, o);
            per0 += __shfl_xor_sync(0xffffffffu, per0, o);
            pel8 += __shfl_xor_sync(0xffffffffu, pel8, o);
            per8 += __shfl_xor_sync(0xffffffffu, per8, o);
        }
        if ((lane & 3) == 0) {
            if (row < M) {
                atomicAdd(&el[row * HH + head], pel0);
                atomicAdd(&er[row * HH + head], per0);
            }
            if (row + 8 < M) {
                atomicAdd(&el[(row + 8) * HH + head], pel8);
                atomicAdd(&er[(row + 8) * HH + head], per8);
            }
        }
    }
}

// ---------------- warp-per-node softmax + aggregation + epilogue ---------------
template<int O>
__global__ void __launch_bounds__(256) aggw_k(
        const int* __restrict__ off0, const int* __restrict__ csr0,
        const int* __restrict__ off1, const int* __restrict__ csr1,
        const float* __restrict__ el0, const float* __restrict__ er0,
        const float* __restrict__ el1, const float* __restrict__ er1,
        const __half* __restrict__ feat0, const __half* __restrict__ feat1,
        const float* __restrict__ b0, const float* __restrict__ b1,
        float* __restrict__ out, __half* __restrict__ outH, int do_relu) {
    constexpr int WIDTH = 2 * O;
    constexpr int NV = WIDTH / 32;          // halves per lane: 16 (O=256) or 8 (O=128)
    int n = (blockIdx.x * blockDim.x + threadIdx.x) >> 5;
    if (n >= NN) return;
    int lane = threadIdx.x & 31;
    int head = lane >> 4;
    float acc[NV];
    #pragma unroll
    for (int j = 0; j < NV; j++) acc[j] = 0.f;

    #pragma unroll
    for (int rel = 0; rel < 2; rel++) {
        const int* off = rel ? off1 : off0;
        const int* csr = rel ? csr1 : csr0;
        const float* el = rel ? el1 : el0;
        const float* er = rel ? er1 : er0;
        const __half* feat = rel ? feat1 : feat0;
        int beg = off[n];
        int deg = off[n + 1] - beg;
        float ern0 = er[n * 2 + 0], ern1 = er[n * 2 + 1];
        float d0 = 0.f, d1 = 0.f;
        for (int i = lane; i < deg; i += 32) {
            int s = csr[beg + i];
            float v0 = el[s * 2 + 0] + ern0;
            float v1 = el[s * 2 + 1] + ern1;
            v0 = v0 > 0.f ? v0 : 0.2f * v0;
            v1 = v1 > 0.f ? v1 : 0.2f * v1;
            d0 += __expf(v0);
            d1 += __expf(v1);
        }
        #pragma unroll
        for (int o = 16; o; o >>= 1) {
            d0 += __shfl_xor_sync(0xffffffffu, d0, o);
            d1 += __shfl_xor_sync(0xffffffffu, d1, o);
        }
        float inv = (head ? 1.f / fmaxf(d1, 1e-9f) : 1.f / fmaxf(d0, 1e-9f));
        float ern = head ? ern1 : ern0;
        #pragma unroll 4
        for (int i = 0; i < deg; i++) {
            int s = csr[beg + i];               // uniform address -> broadcast
            float v = el[s * 2 + head] + ern;
            v = v > 0.f ? v : 0.2f * v;
            float a = __expf(v) * inv;
            const __half* fp = feat + (size_t)s * WIDTH + lane * NV;
            if (NV == 16) {
                uint4 r0 = *(const uint4*)fp;
                uint4 r1 = *(const uint4*)(fp + 8);
                float2 f;
                f = __half22float2(*(__half2*)&r0.x); acc[0] += a * f.x; acc[1] += a * f.y;
                f = __half22float2(*(__half2*)&r0.y); acc[2] += a * f.x; acc[3] += a * f.y;
                f = __half22float2(*(__half2*)&r0.z); acc[4] += a * f.x; acc[5] += a * f.y;
                f = __half22float2(*(__half2*)&r0.w); acc[6] += a * f.x; acc[7] += a * f.y;
                f = __half22float2(*(__half2*)&r1.x); acc[8] += a * f.x; acc[9] += a * f.y;
                f = __half22float2(*(__half2*)&r1.y); acc[10] += a * f.x; acc[11] += a * f.y;
                f = __half22float2(*(__half2*)&r1.z); acc[12] += a * f.x; acc[13] += a * f.y;
                f = __half22float2(*(__half2*)&r1.w); acc[14] += a * f.x; acc[15] += a * f.y;
            } else {
                uint4 r0 = *(const uint4*)fp;
                float2 f;
                f = __half22float2(*(__half2*)&r0.x); acc[0] += a * f.x; acc[1] += a * f.y;
                f = __half22float2(*(__half2*)&r0.y); acc[2] += a * f.x; acc[3] += a * f.y;
                f = __half22float2(*(__half2*)&r0.z); acc[4] += a * f.x; acc[5] += a * f.y;
                f = __half22float2(*(__half2*)&r0.w); acc[6] += a * f.x; acc[7] += a * f.y;
            }
        }
    }
    // epilogue: lane l (<16) combines its cols j=l*NV+k with lane l+16's j+O
    float other[NV];
    #pragma unroll
    for (int j = 0; j < NV; j++)
        other[j] = __shfl_down_sync(0xffffffffu, acc[j], 16);
    if (lane < 16) {
        #pragma unroll
        for (int k = 0; k < NV; k++) {
            int j = lane * NV + k;
            float v = acc[k] + other[k]
                    + b0[j] + b0[j + O] + b1[j] + b1[j + O];
            v *= 0.5f;
            if (do_relu) v = fmaxf(v, 0.f);
            if (outH) outH[(size_t)n * O + j] = __float2half_rn(v);
            else      out[(size_t)n * O + j] = v;
        }
    }
}

// ---------------- host launch ---------------------------------------------------
static float* symf(const void* s) { void* p = nullptr; cudaGetSymbolAddress(&p, s); return (float*)p; }
static int*   symi(const void* s) { void* p = nullptr; cudaGetSymbolAddress(&p, s); return (int*)p; }
static __half* symh(const void* s) { void* p = nullptr; cudaGetSymbolAddress(&p, s); return (__half*)p; }

struct Ctx {
    cudaStream_t s1, s2;
    cudaEvent_t fork1, join1, evW;
    Ctx() {
        cudaStreamCreateWithFlags(&s1, cudaStreamNonBlocking);
        cudaStreamCreateWithFlags(&s2, cudaStreamNonBlocking);
        cudaEventCreateWithFlags(&fork1, cudaEventDisableTiming);
        cudaEventCreateWithFlags(&join1, cudaEventDisableTiming);
        cudaEventCreateWithFlags(&evW,   cudaEventDisableTiming);
    }
};

extern "C" void kernel_launch(void* const* d_in, const int* in_sizes, int n_in,
                              void* d_out, int out_size) {
    static Ctx ctx;
    const float* x     = (const float*)d_in[0];
    const int*   src0  = (const int*)d_in[1];
    const int*   dst0  = (const int*)d_in[2];
    const int*   src1  = (const int*)d_in[3];
    const int*   dst1  = (const int*)d_in[4];
    const float* W1_0  = (const float*)d_in[5];
    const float* al1_0 = (const float*)d_in[6];
    const float* ar1_0 = (const float*)d_in[7];
    const float* b1_0  = (const float*)d_in[8];
    const float* W1_1  = (const float*)d_in[9];
    const float* al1_1 = (const float*)d_in[10];
    const float* ar1_1 = (const float*)d_in[11];
    const float* b1_1  = (const float*)d_in[12];
    const float* W2_0  = (const float*)d_in[13];
    const float* al2_0 = (const float*)d_in[14];
    const float* ar2_0 = (const float*)d_in[15];
    const float* b2_0  = (const float*)d_in[16];
    const float* W2_1  = (const float*)d_in[17];
    const float* al2_1 = (const float*)d_in[18];
    const float* ar2_1 = (const float*)d_in[19];
    const float* b2_1  = (const float*)d_in[20];
    float* out = (float*)d_out;

    __half* feat0 = symh(g_feat0);
    __half* feat1 = symh(g_feat1);
    float* el0 = symf(g_el0); float* er0 = symf(g_er0);
    float* el1 = symf(g_el1); float* er1 = symf(g_er1);
    float* el2 = symf(g_el2); float* er2 = symf(g_er2);
    float* el3 = symf(g_el3); float* er3 = symf(g_er3);
    int* deg0 = symi(g_deg0); int* deg1 = symi(g_deg1);
    int* off0 = symi(g_off0); int* off1 = symi(g_off1);
    int* pos0 = symi(g_pos0); int* pos1 = symi(g_pos1);
    int* csr0 = symi(g_csr0); int* csr1 = symi(g_csr1);
    int* bsum = symi(g_bsum);
    __half* xh = symh(g_xh);
    __half* h1 = symh(g_h1);
    __half* w1_0 = symh(g_w1_0); __half* w1_1 = symh(g_w1_1);
    __half* w2_0 = symh(g_w2_0); __half* w2_1 = symh(g_w2_1);

    cudaStream_t s1 = ctx.s1, s2 = ctx.s2;

    // fork so s1 (CSR) and s2 (convW) run concurrently with init on stream 0
    cudaEventRecord(ctx.fork1, 0);
    cudaStreamWaitEvent(s1, ctx.fork1, 0);
    cudaStreamWaitEvent(s2, ctx.fork1, 0);

    // stream 0: fused init (convX + zero el/er + zero deg handled below on s1 path)
    init_k<<<(NN * DD + 255) / 256, 256>>>(x, xh, el0, er0, el1, er1,
                                           el2, er2, el3, er3, deg0, deg1);

    // s2: all 4 weight transposes, concurrent with init
    { dim3 g(65536 / 256, 4);
      convW4_k<<<g, 256, 0, s2>>>(W1_0, W1_1, W2_0, W2_1, w1_0, w1_1, w2_0, w2_1); }
    cudaEventRecord(ctx.evW, s2);

    // s1: CSR build (hist depends on deg zeroing in init_k -> wait for stream 0)
    cudaEventRecord(ctx.join1, 0);          // reuse: marks init_k done
    cudaStreamWaitEvent(s1, ctx.join1, 0);
    hist_k<<<(EE + 255) / 256, 256, 0, s1>>>(dst0, dst1, deg0, deg1);
    { dim3 g(NB, 2); scanA_k<<<g, 1024, 0, s1>>>(deg0, deg1, off0, off1, bsum); }
    scanB_k<<<1, 64, 0, s1>>>(bsum, off0, off1);
    { dim3 g(NB, 2); scanC_k<<<g, 1024, 0, s1>>>(bsum, off0, off1, pos0, pos1); }
    scat_k<<<(EE + 255) / 256, 256, 0, s1>>>(src0, dst0, src1, dst1, pos0, pos1, csr0, csr1);
    cudaEventRecord(ctx.join1, s1);

    // stream 0: wait for weights, then layer-1 GEMM (both relations)
    cudaStreamWaitEvent(0, ctx.evW, 0);
    { dim3 g(4, (NN + 127) / 128, 2);
      gemm_mma_k<128, 256><<<g, 256>>>(xh, w1_0, w1_1, feat0, feat1,
                                       al1_0, ar1_0, al1_1, ar1_1,
                                       el0, er0, el1, er1, NN, 512); }

    cudaStreamWaitEvent(0, ctx.join1, 0);   // CSR ready

    aggw_k<256><<<(NN * 32 + 255) / 256, 256>>>(off0, csr0, off1, csr1,
                            el0, er0, el1, er1,
                            feat0, feat1, b1_0, b1_1, nullptr, h1, 1);

    // layer-2 GEMM, both relations in one launch
    { dim3 g(2, (NN + 127) / 128, 2);
      gemm_mma_k<256, 128><<<g, 256>>>(h1, w2_0, w2_1, feat0, feat1,
                                       al2_0, ar2_0, al2_1, ar2_1,
                                       el2, er2, el3, er3, NN, 256); }

    aggw_k<128><<<(NN * 32 + 255) / 256, 256>>>(off0, csr0, off1, csr1,
                            el2, er2, el3, er3,
                            feat0, feat1, b2_0, b2_1, out, nullptr, 0);
}

// round 14
// speedup vs baseline: 4.0162x; 1.0087x over previous
#include <cuda_runtime.h>
#include <cuda_fp16.h>
#include <cstdint>
#include <math.h>

#define NN   20000
#define EE   320000
#define DD   128
#define HH   2
#define NB   ((NN + 1023) / 1024)

// ---------------- scratch (device globals) ------------------------------------
__device__ __align__(16) __half g_feat0[(size_t)NN * 512];
__device__ __align__(16) __half g_feat1[(size_t)NN * 512];
__device__ float g_el0[NN * 2], g_er0[NN * 2];
__device__ float g_el1[NN * 2], g_er1[NN * 2];
__device__ float g_el2[NN * 2], g_er2[NN * 2];
__device__ float g_el3[NN * 2], g_er3[NN * 2];
__device__ int   g_deg0[NN], g_deg1[NN];
__device__ int   g_off0[NN + 1], g_off1[NN + 1];
__device__ int   g_pos0[NN], g_pos1[NN];
__device__ int   g_csr0[EE], g_csr1[EE];
__device__ int   g_bsum[64];
__device__ __align__(16) __half g_xh[(size_t)NN * DD];
__device__ __align__(16) __half g_h1[(size_t)NN * 256];
__device__ __align__(16) __half g_w1_0[512 * 128];
__device__ __align__(16) __half g_w1_1[512 * 128];
__device__ __align__(16) __half g_w2_0[256 * 256];
__device__ __align__(16) __half g_w2_1[256 * 256];

// ---------------- fused init ----------------------------------------------------
__global__ void init_k(const float* __restrict__ x, __half* xh,
                       float* el0, float* er0, float* el1, float* er1,
                       float* el2, float* er2, float* el3, float* er3,
                       int* deg0, int* deg1) {
    int i = blockIdx.x * blockDim.x + threadIdx.x;
    if (i < NN * DD) xh[i] = __float2half_rn(x[i]);
    if (i < NN * HH) {
        el0[i] = 0.f; er0[i] = 0.f; el1[i] = 0.f; er1[i] = 0.f;
        el2[i] = 0.f; er2[i] = 0.f; el3[i] = 0.f; er3[i] = 0.f;
    }
    if (i < NN) { deg0[i] = 0; deg1[i] = 0; }
}

// ---------------- CSR build -----------------------------------------------------
__global__ void hist_k(const int* __restrict__ dst0, const int* __restrict__ dst1,
                       int* deg0, int* deg1) {
    int i = blockIdx.x * blockDim.x + threadIdx.x;
    if (i < EE) {
        atomicAdd(&deg0[dst0[i]], 1);
        atomicAdd(&deg1[dst1[i]], 1);
    }
}
__global__ void scanA_k(const int* __restrict__ deg0, const int* __restrict__ deg1,
                        int* off0, int* off1, int* bsum) {
    const int* deg = blockIdx.y ? deg1 : deg0;
    int* off = blockIdx.y ? off1 : off0;
    int i = blockIdx.x * 1024 + threadIdx.x;
    int lane = threadIdx.x & 31, wid = threadIdx.x >> 5;
    int v = (i < NN) ? deg[i] : 0;
    int x = v;
    #pragma unroll
    for (int o = 1; o < 32; o <<= 1) {
        int t = __shfl_up_sync(0xffffffffu, x, o);
        if (lane >= o) x += t;
    }
    __shared__ int wsum[32];
    if (lane == 31) wsum[wid] = x;
    __syncthreads();
    if (wid == 0) {
        int w = wsum[lane];
        #pragma unroll
        for (int o = 1; o < 32; o <<= 1) {
            int t = __shfl_up_sync(0xffffffffu, w, o);
            if (lane >= o) w += t;
        }
        wsum[lane] = w;
    }
    __syncthreads();
    int inc = x + (wid ? wsum[wid - 1] : 0);
    if (i < NN) off[i] = inc - v;
    if (threadIdx.x == 1023) bsum[blockIdx.y * 32 + blockIdx.x] = inc;
}
__global__ void scanB_k(int* bsum, int* off0, int* off1) {
    int y = threadIdx.x >> 5, lane = threadIdx.x & 31;
    int v = (lane < NB) ? bsum[y * 32 + lane] : 0;
    int x = v;
    #pragma unroll
    for (int o = 1; o < 32; o <<= 1) {
        int t = __shfl_up_sync(0xffffffffu, x, o);
        if (lane >= o) x += t;
    }
    if (lane < NB) bsum[y * 32 + lane] = x - v;
    if (lane == NB - 1) { int* off = y ? off1 : off0; off[NN] = x; }
}
__global__ void scanC_k(const int* __restrict__ bsum, int* off0, int* off1,
                        int* pos0, int* pos1) {
    int i = blockIdx.x * 1024 + threadIdx.x;
    if (i >= NN) return;
    int y = blockIdx.y;
    int* off = y ? off1 : off0;
    int* pos = y ? pos1 : pos0;
    int val = off[i] + bsum[y * 32 + blockIdx.x];
    off[i] = val; pos[i] = val;
}
__global__ void scat_k(const int* __restrict__ src0, const int* __restrict__ dst0,
                       const int* __restrict__ src1, const int* __restrict__ dst1,
                       int* pos0, int* pos1, int* csr0, int* csr1) {
    int i = blockIdx.x * blockDim.x + threadIdx.x;
    if (i < EE) {
        csr0[atomicAdd(&pos0[dst0[i]], 1)] = src0[i];
        csr1[atomicAdd(&pos1[dst1[i]], 1)] = src1[i];
    }
}

// ---------------- merged weight transpose ---------------------------------------
__global__ void convW4_k(const float* __restrict__ Wa, const float* __restrict__ Wb,
                         const float* __restrict__ Wc, const float* __restrict__ Wd,
                         __half* da, __half* db, __half* dc, __half* dd) {
    int which = blockIdx.y;
    const float* W = which == 0 ? Wa : which == 1 ? Wb : which == 2 ? Wc : Wd;
    __half* dst     = which == 0 ? da : which == 1 ? db : which == 2 ? dc : dd;
    int K  = (which < 2) ? 128 : 256;
    int Nd = (which < 2) ? 512 : 256;
    int i = blockIdx.x * blockDim.x + threadIdx.x;
    int n = i / K, k = i % K;
    dst[i] = __float2half_rn(W[(size_t)k * Nd + n]);
}

// ---------------- mma.sync / cp.async helpers -----------------------------------
__device__ __forceinline__ uint32_t smem_u32(const void* p) {
    uint32_t a;
    asm("{ .reg .u64 t; cvta.to.shared.u64 t, %1; cvt.u32.u64 %0, t; }" : "=r"(a) : "l"(p));
    return a;
}
__device__ __forceinline__ void ldsm_x4(uint32_t* r, uint32_t addr) {
    asm volatile("ldmatrix.sync.aligned.m8n8.x4.shared.b16 {%0,%1,%2,%3}, [%4];"
                 : "=r"(r[0]), "=r"(r[1]), "=r"(r[2]), "=r"(r[3]) : "r"(addr));
}
__device__ __forceinline__ void ldsm_x2(uint32_t* r, uint32_t addr) {
    asm volatile("ldmatrix.sync.aligned.m8n8.x2.shared.b16 {%0,%1}, [%2];"
                 : "=r"(r[0]), "=r"(r[1]) : "r"(addr));
}
__device__ __forceinline__ void mma_fp16(float* d, const uint32_t* a, const uint32_t* b) {
    asm volatile(
        "mma.sync.aligned.m16n8k16.row.col.f32.f16.f16.f32 "
        "{%0,%1,%2,%3}, {%4,%5,%6,%7}, {%8,%9}, {%0,%1,%2,%3};"
        : "+f"(d[0]), "+f"(d[1]), "+f"(d[2]), "+f"(d[3])
        : "r"(a[0]), "r"(a[1]), "r"(a[2]), "r"(a[3]), "r"(b[0]), "r"(b[1]));
}
__device__ __forceinline__ void cp16(uint32_t dst, const void* src, bool valid) {
    int sz = valid ? 16 : 0;
    asm volatile("cp.async.cg.shared.global [%0], [%1], 16, %2;"
                 :: "r"(dst), "l"(src), "r"(sz));
}

// ---------------- tensor-core fp16 GEMM, cp.async double-buffered --------------
#define SSTR 40
__device__ __forceinline__ void load_chunk_async(const __half* __restrict__ g,
        int ld, int rbase, int kofs, uint32_t sbase, int rlim, int tid) {
    #pragma unroll
    for (int i = 0; i < 2; i++) {
        int id = tid + i * 256;
        int r = id >> 2;
        int c = (id & 3) * 8;
        int gr = rbase + r;
        bool valid = gr < rlim;
        const __half* src = g + (size_t)(valid ? gr : 0) * ld + kofs + c;
        cp16(sbase + (uint32_t)(r * SSTR + c) * 2, src, valid);
    }
}

template<int KTOT, int O>
__global__ void __launch_bounds__(256) gemm_mma_k(
        const __half* __restrict__ A,
        const __half* __restrict__ W0, const __half* __restrict__ W1,
        __half* __restrict__ C0, __half* __restrict__ C1,
        const float* __restrict__ al0, const float* __restrict__ ar0,
        const float* __restrict__ al1, const float* __restrict__ ar1,
        float* __restrict__ elA, float* __restrict__ erA,
        float* __restrict__ elB, float* __restrict__ erB,
        int M, int Nd) {
    const int rel = blockIdx.z;
    const __half* B = rel ? W1 : W0;
    __half* C = rel ? C1 : C0;
    const float* al = rel ? al1 : al0;
    const float* ar = rel ? ar1 : ar0;
    float* el = rel ? elB : elA;
    float* er = rel ? erB : erA;

    __shared__ __align__(16) __half sA[2][128 * SSTR];
    __shared__ __align__(16) __half sB[2][128 * SSTR];
    const int tid = threadIdx.x;
    const int w = tid >> 5;
    const int lane = tid & 31;
    const int rowBase = blockIdx.y * 128;
    const int colBase = blockIdx.x * 128;
    const int wRow = w >> 2;
    const int wCol = w & 3;

    uint32_t aBase[2] = { smem_u32(sA[0]), smem_u32(sA[1]) };
    uint32_t bBase[2] = { smem_u32(sB[0]), smem_u32(sB[1]) };

    float d[4][4][4];
    #pragma unroll
    for (int i = 0; i < 4; i++)
        #pragma unroll
        for (int j = 0; j < 4; j++)
            #pragma unroll
            for (int q = 0; q < 4; q++) d[i][j][q] = 0.f;

    constexpr int NKC = KTOT / 32;
    load_chunk_async(A, KTOT, rowBase, 0, aBase[0], M, tid);
    load_chunk_async(B, KTOT, colBase, 0, bBase[0], 1 << 30, tid);
    asm volatile("cp.async.commit_group;");
    asm volatile("cp.async.wait_group 0;");
    __syncthreads();

    int buf = 0;
    for (int kc = 0; kc < NKC; kc++) {
        bool more = (kc + 1) < NKC;
        if (more) {
            load_chunk_async(A, KTOT, rowBase, (kc + 1) * 32, aBase[buf ^ 1], M, tid);
            load_chunk_async(B, KTOT, colBase, (kc + 1) * 32, bBase[buf ^ 1], 1 << 30, tid);
            asm volatile("cp.async.commit_group;");
        }
        #pragma unroll
        for (int ks = 0; ks < 32; ks += 16) {
            uint32_t b[4][2];
            {
                int brow = (lane & 7);
                int bcol = ks + ((lane >> 3) & 1) * 8;
                #pragma unroll
                for (int nt = 0; nt < 4; nt++) {
                    uint32_t off = (uint32_t)(((wCol * 32 + nt * 8 + brow) * SSTR + bcol) * 2);
                    ldsm_x2(b[nt], bBase[buf] + off);
                }
            }
            int arow = (lane & 15);
            int acol = ks + (lane >> 4) * 8;
            #pragma unroll
            for (int mt = 0; mt < 4; mt++) {
                uint32_t a[4];
                uint32_t off = (uint32_t)(((wRow * 64 + mt * 16 + arow) * SSTR + acol) * 2);
                ldsm_x4(a, aBase[buf] + off);
                #pragma unroll
                for (int nt = 0; nt < 4; nt++)
                    mma_fp16(d[mt][nt], a, b[nt]);
            }
        }
        if (more) {
            asm volatile("cp.async.wait_group 0;");
            __syncthreads();
            buf ^= 1;
        }
    }

    int mlocal = lane >> 2;
    int nlocal = (lane & 3) * 2;
    float alv[4][2], arv[4][2];
    int head;
    {
        int c0 = colBase + wCol * 32 + nlocal;
        head = c0 / O;
        #pragma unroll
        for (int nt = 0; nt < 4; nt++) {
            int c = c0 + nt * 8 - head * O;
            alv[nt][0] = al[head * O + c]; alv[nt][1] = al[head * O + c + 1];
            arv[nt][0] = ar[head * O + c]; arv[nt][1] = ar[head * O + c + 1];
        }
    }
    #pragma unroll
    for (int mt = 0; mt < 4; mt++) {
        int row = rowBase + wRow * 64 + mt * 16 + mlocal;
        float pel0 = 0.f, per0 = 0.f, pel8 = 0.f, per8 = 0.f;
        #pragma unroll
        for (int nt = 0; nt < 4; nt++) {
            int col = colBase + wCol * 32 + nt * 8 + nlocal;
            if (row < M)
                *(__half2*)&C[(size_t)row * Nd + col] =
                    __floats2half2_rn(d[mt][nt][0], d[mt][nt][1]);
            if (row + 8 < M)
                *(__half2*)&C[(size_t)(row + 8) * Nd + col] =
                    __floats2half2_rn(d[mt][nt][2], d[mt][nt][3]);
            pel0 += d[mt][nt][0] * alv[nt][0] + d[mt][nt][1] * alv[nt][1];
            per0 += d[mt][nt][0] * arv[nt][0] + d[mt][nt][1] * arv[nt][1];
            pel8 += d[mt][nt][2] * alv[nt][0] + d[mt][nt][3] * alv[nt][1];
            per8 += d[mt][nt][2] * arv[nt][0] + d[mt][nt][3] * arv[nt][1];
        }
        #pragma unroll
        for (int o = 1; o < 4; o <<= 1) {
            pel0 += __shfl_xor_sync(0xffffffffu, pel0, o);
            per0 += __shfl_xor_sync(0xffffffffu, per0, o);
            pel8 += __shfl_xor_sync(0xffffffffu, pel8, o);
            per8 += __shfl_xor_sync(0xffffffffu, per8, o);
        }
        if ((lane & 3) == 0) {
            if (row < M) {
                atomicAdd(&el[row * HH + head], pel0);
                atomicAdd(&er[row * HH + head], per0);
            }
            if (row + 8 < M) {
                atomicAdd(&el[(row + 8) * HH + head], pel8);
                atomicAdd(&er[(row + 8) * HH + head], per8);
            }
        }
    }
}

// ---------------- 2-warps-per-node softmax + aggregation -----------------------
// Warp (node, head): head = warp&1, owns columns [head*O, (head+1)*O).
// 4 nodes per 256-thread block. Head-1 warp stages partial in smem; head-0
// warp combines (mean over heads) + bias (+relu) and writes.
template<int O>
__global__ void __launch_bounds__(256) aggw_k(
        const int* __restrict__ off0, const int* __restrict__ csr0,
        const int* __restrict__ off1, const int* __restrict__ csr1,
        const float* __restrict__ el0, const float* __restrict__ er0,
        const float* __restrict__ el1, const float* __restrict__ er1,
        const __half* __restrict__ feat0, const __half* __restrict__ feat1,
        const float* __restrict__ b0, const float* __restrict__ b1,
        float* __restrict__ out, __half* __restrict__ outH, int do_relu) {
    constexpr int WIDTH = 2 * O;
    constexpr int NVH = O / 32;             // halves per lane: 8 (O=256) or 4 (O=128)
    __shared__ float s_out[4][O];
    int wid = threadIdx.x >> 5;
    int lane = threadIdx.x & 31;
    int nodeLocal = wid >> 1;
    int head = wid & 1;
    int n = blockIdx.x * 4 + nodeLocal;     // NN % 4 == 0, no OOB

    float acc[NVH];
    #pragma unroll
    for (int j = 0; j < NVH; j++) acc[j] = 0.f;

    #pragma unroll
    for (int rel = 0; rel < 2; rel++) {
        const int* off = rel ? off1 : off0;
        const int* csr = rel ? csr1 : csr0;
        const float* el = rel ? el1 : el0;
        const float* er = rel ? er1 : er0;
        const __half* feat = rel ? feat1 : feat0;
        int beg = off[n];
        int deg = off[n + 1] - beg;
        float ern = er[n * 2 + head];
        // denominator for this head
        float dsum = 0.f;
        for (int i = lane; i < deg; i += 32) {
            int s = csr[beg + i];
            float v = el[s * 2 + head] + ern;
            v = v > 0.f ? v : 0.2f * v;
            dsum += __expf(v);
        }
        #pragma unroll
        for (int o = 16; o; o >>= 1)
            dsum += __shfl_xor_sync(0xffffffffu, dsum, o);
        float inv = 1.f / fmaxf(dsum, 1e-9f);
        // weighted gather
        #pragma unroll 4
        for (int i = 0; i < deg; i++) {
            int s = csr[beg + i];               // uniform address -> broadcast
            float v = el[s * 2 + head] + ern;
            v = v > 0.f ? v : 0.2f * v;
            float a = __expf(v) * inv;
            const __half* fp = feat + (size_t)s * WIDTH + head * O + lane * NVH;
            if (NVH == 8) {
                uint4 r0 = *(const uint4*)fp;
                float2 f;
                f = __half22float2(*(__half2*)&r0.x); acc[0] += a * f.x; acc[1] += a * f.y;
                f = __half22float2(*(__half2*)&r0.y); acc[2] += a * f.x; acc[3] += a * f.y;
                f = __half22float2(*(__half2*)&r0.z); acc[4] += a * f.x; acc[5] += a * f.y;
                f = __half22float2(*(__half2*)&r0.w); acc[6] += a * f.x; acc[7] += a * f.y;
            } else {
                uint2 r0 = *(const uint2*)fp;
                float2 f;
                f = __half22float2(*(__half2*)&r0.x); acc[0] += a * f.x; acc[1] += a * f.y;
                f = __half22float2(*(__half2*)&r0.y); acc[2] += a * f.x; acc[3] += a * f.y;
            }
        }
    }
    // combine heads
    if (head == 1) {
        #pragma unroll
        for (int k = 0; k < NVH; k++)
            s_out[nodeLocal][lane * NVH + k] = acc[k];
    }
    __syncthreads();
    if (head == 0) {
        #pragma unroll
        for (int k = 0; k < NVH; k++) {
            int j = lane * NVH + k;
            float v = acc[k] + s_out[nodeLocal][j]
                    + b0[j] + b0[j + O] + b1[j] + b1[j + O];
            v *= 0.5f;
            if (do_relu) v = fmaxf(v, 0.f);
            if (outH) outH[(size_t)n * O + j] = __float2half_rn(v);
            else      out[(size_t)n * O + j] = v;
        }
    }
}

// ---------------- host launch ---------------------------------------------------
static float* symf(const void* s) { void* p = nullptr; cudaGetSymbolAddress(&p, s); return (float*)p; }
static int*   symi(const void* s) { void* p = nullptr; cudaGetSymbolAddress(&p, s); return (int*)p; }
static __half* symh(const void* s) { void* p = nullptr; cudaGetSymbolAddress(&p, s); return (__half*)p; }

struct Ctx {
    cudaStream_t s1, s2;
    cudaEvent_t fork1, join1, evW;
    Ctx() {
        cudaStreamCreateWithFlags(&s1, cudaStreamNonBlocking);
        cudaStreamCreateWithFlags(&s2, cudaStreamNonBlocking);
        cudaEventCreateWithFlags(&fork1, cudaEventDisableTiming);
        cudaEventCreateWithFlags(&join1, cudaEventDisableTiming);
        cudaEventCreateWithFlags(&evW,   cudaEventDisableTiming);
    }
};

extern "C" void kernel_launch(void* const* d_in, const int* in_sizes, int n_in,
                              void* d_out, int out_size) {
    static Ctx ctx;
    const float* x     = (const float*)d_in[0];
    const int*   src0  = (const int*)d_in[1];
    const int*   dst0  = (const int*)d_in[2];
    const int*   src1  = (const int*)d_in[3];
    const int*   dst1  = (const int*)d_in[4];
    const float* W1_0  = (const float*)d_in[5];
    const float* al1_0 = (const float*)d_in[6];
    const float* ar1_0 = (const float*)d_in[7];
    const float* b1_0  = (const float*)d_in[8];
    const float* W1_1  = (const float*)d_in[9];
    const float* al1_1 = (const float*)d_in[10];
    const float* ar1_1 = (const float*)d_in[11];
    const float* b1_1  = (const float*)d_in[12];
    const float* W2_0  = (const float*)d_in[13];
    const float* al2_0 = (const float*)d_in[14];
    const float* ar2_0 = (const float*)d_in[15];
    const float* b2_0  = (const float*)d_in[16];
    const float* W2_1  = (const float*)d_in[17];
    const float* al2_1 = (const float*)d_in[18];
    const float* ar2_1 = (const float*)d_in[19];
    const float* b2_1  = (const float*)d_in[20];
    float* out = (float*)d_out;

    __half* feat0 = symh(g_feat0);
    __half* feat1 = symh(g_feat1);
    float* el0 = symf(g_el0); float* er0 = symf(g_er0);
    float* el1 = symf(g_el1); float* er1 = symf(g_er1);
    float* el2 = symf(g_el2); float* er2 = symf(g_er2);
    float* el3 = symf(g_el3); float* er3 = symf(g_er3);
    int* deg0 = symi(g_deg0); int* deg1 = symi(g_deg1);
    int* off0 = symi(g_off0); int* off1 = symi(g_off1);
    int* pos0 = symi(g_pos0); int* pos1 = symi(g_pos1);
    int* csr0 = symi(g_csr0); int* csr1 = symi(g_csr1);
    int* bsum = symi(g_bsum);
    __half* xh = symh(g_xh);
    __half* h1 = symh(g_h1);
    __half* w1_0 = symh(g_w1_0); __half* w1_1 = symh(g_w1_1);
    __half* w2_0 = symh(g_w2_0); __half* w2_1 = symh(g_w2_1);

    cudaStream_t s1 = ctx.s1, s2 = ctx.s2;

    cudaEventRecord(ctx.fork1, 0);
    cudaStreamWaitEvent(s1, ctx.fork1, 0);
    cudaStreamWaitEvent(s2, ctx.fork1, 0);

    init_k<<<(NN * DD + 255) / 256, 256>>>(x, xh, el0, er0, el1, er1,
                                           el2, er2, el3, er3, deg0, deg1);

    { dim3 g(65536 / 256, 4);
      convW4_k<<<g, 256, 0, s2>>>(W1_0, W1_1, W2_0, W2_1, w1_0, w1_1, w2_0, w2_1); }
    cudaEventRecord(ctx.evW, s2);

    cudaEventRecord(ctx.join1, 0);          // marks init_k done
    cudaStreamWaitEvent(s1, ctx.join1, 0);
    hist_k<<<(EE + 255) / 256, 256, 0, s1>>>(dst0, dst1, deg0, deg1);
    { dim3 g(NB, 2); scanA_k<<<g, 1024, 0, s1>>>(deg0, deg1, off0, off1, bsum); }
    scanB_k<<<1, 64, 0, s1>>>(bsum, off0, off1);
    { dim3 g(NB, 2); scanC_k<<<g, 1024, 0, s1>>>(bsum, off0, off1, pos0, pos1); }
    scat_k<<<(EE + 255) / 256, 256, 0, s1>>>(src0, dst0, src1, dst1, pos0, pos1, csr0, csr1);
    cudaEventRecord(ctx.join1, s1);

    cudaStreamWaitEvent(0, ctx.evW, 0);
    { dim3 g(4, (NN + 127) / 128, 2);
      gemm_mma_k<128, 256><<<g, 256>>>(xh, w1_0, w1_1, feat0, feat1,
                                       al1_0, ar1_0, al1_1, ar1_1,
                                       el0, er0, el1, er1, NN, 512); }

    cudaStreamWaitEvent(0, ctx.join1, 0);   // CSR ready

    aggw_k<256><<<NN / 4, 256>>>(off0, csr0, off1, csr1,
                            el0, er0, el1, er1,
                            feat0, feat1, b1_0, b1_1, nullptr, h1, 1);

    { dim3 g(2, (NN + 127) / 128, 2);
      gemm_mma_k<256, 128><<<g, 256>>>(h1, w2_0, w2_1, feat0, feat1,
                                       al2_0, ar2_0, al2_1, ar2_1,
                                       el2, er2, el3, er3, NN, 256); }

    aggw_k<128><<<NN / 4, 256>>>(off0, csr0, off1, csr1,
                            el2, er2, el3, er3,
                            feat0, feat1, b2_0, b2_1, out, nullptr, 0);
}